// round 3
// baseline (speedup 1.0000x reference)
#include <cuda_runtime.h>
#include <math.h>

#define EMBED 2048
#define SEQ   2048
#define NHEAD 16
#define DHEAD 128
#define BATCH 2
#define MTOT  (BATCH*SEQ)   // 4096

// ---------------- scratch (static device memory; no allocations) ----------------
__device__ float g_Q[BATCH*NHEAD*SEQ*DHEAD];    // [B,H,S,D]
__device__ float g_K[BATCH*NHEAD*SEQ*DHEAD];
__device__ float g_V[BATCH*NHEAD*SEQ*DHEAD];
__device__ float g_ctx[BATCH*SEQ*EMBED];        // [B,S,E]

// ---------------- GEMM: C = A[M,K] * W[N,K]^T  (both row-major, K contiguous) ---
// mode 0/1/2: A = Ain (x), output -> g_Q/g_K/g_V in [B,H,S,D] layout
// mode 3    : A = g_ctx,   output -> Cout row-major [M,N]
#define BM 128
#define BN 128
#define BK 16

__global__ void __launch_bounds__(256) gemm_nt(const float* __restrict__ Ain,
                                               const float* __restrict__ W,
                                               float* __restrict__ Cout,
                                               int mode)
{
    __shared__ float As[BK][BM+4];
    __shared__ float Ws[BK][BN+4];

    const int tid = threadIdx.x;
    const int tx  = tid & 15;     // 16 col-threads
    const int ty  = tid >> 4;     // 16 row-threads
    const int m0  = blockIdx.y * BM;
    const int n0  = blockIdx.x * BN;

    const float* A = (mode == 3) ? g_ctx : Ain;

    float acc[8][8];
    #pragma unroll
    for (int i = 0; i < 8; i++)
        #pragma unroll
        for (int j = 0; j < 8; j++) acc[i][j] = 0.f;

    const int f0 = tid * 2;   // each thread loads 2 float4 of A and 2 of W per tile

    for (int k0 = 0; k0 < EMBED; k0 += BK) {
        __syncthreads();
        #pragma unroll
        for (int u = 0; u < 2; u++) {
            int f   = f0 + u;          // 0..511
            int row = f >> 2;          // 0..127
            int c4  = (f & 3) * 4;     // 0,4,8,12
            float4 av = *(const float4*)(A + (size_t)(m0 + row) * EMBED + k0 + c4);
            As[c4+0][row] = av.x; As[c4+1][row] = av.y;
            As[c4+2][row] = av.z; As[c4+3][row] = av.w;
            float4 wv = *(const float4*)(W + (size_t)(n0 + row) * EMBED + k0 + c4);
            Ws[c4+0][row] = wv.x; Ws[c4+1][row] = wv.y;
            Ws[c4+2][row] = wv.z; Ws[c4+3][row] = wv.w;
        }
        __syncthreads();

        #pragma unroll
        for (int k = 0; k < BK; k++) {
            float a[8], bv[8];
            *(float4*)&a[0]  = *(const float4*)&As[k][ty*8];
            *(float4*)&a[4]  = *(const float4*)&As[k][ty*8 + 4];
            *(float4*)&bv[0] = *(const float4*)&Ws[k][tx*8];
            *(float4*)&bv[4] = *(const float4*)&Ws[k][tx*8 + 4];
            #pragma unroll
            for (int i = 0; i < 8; i++)
                #pragma unroll
                for (int j = 0; j < 8; j++)
                    acc[i][j] += a[i] * bv[j];
        }
    }

    if (mode <= 2) {
        // BN == DHEAD, so each block covers exactly one head: h = n0/128
        float* base = (mode == 0 ? g_Q : (mode == 1 ? g_K : g_V));
        const int h = n0 >> 7;
        #pragma unroll
        for (int i = 0; i < 8; i++) {
            int m = m0 + ty*8 + i;
            int b = m >> 11;          // / SEQ
            int s = m & (SEQ - 1);
            float* dst = base + ((size_t)((b*NHEAD + h)*SEQ + s))*DHEAD + tx*8;
            *(float4*)(dst)     = make_float4(acc[i][0], acc[i][1], acc[i][2], acc[i][3]);
            *(float4*)(dst + 4) = make_float4(acc[i][4], acc[i][5], acc[i][6], acc[i][7]);
        }
    } else {
        #pragma unroll
        for (int i = 0; i < 8; i++) {
            int m = m0 + ty*8 + i;
            float* dst = Cout + (size_t)m*EMBED + n0 + tx*8;
            *(float4*)(dst)     = make_float4(acc[i][0], acc[i][1], acc[i][2], acc[i][3]);
            *(float4*)(dst + 4) = make_float4(acc[i][4], acc[i][5], acc[i][6], acc[i][7]);
        }
    }
}

// ---------------- RoPE (in-place on g_Q, g_K) ----------------
// One thread per (b,h,s,i<64) pair. Angle formed in fp32 (matching the
// reference's fp32 position*freq product), then double-precision sincos of
// that fp32 angle: immune to fast-math range-reduction error at ~2000 rad.
__global__ void __launch_bounds__(256) rope_kernel()
{
    int idx = blockIdx.x * 256 + threadIdx.x;   // [0, B*H*S*64)
    int i   = idx & 63;
    int s   = (idx >> 6) & (SEQ - 1);
    int bh  = idx >> 17;                        // b*NHEAD + h
    size_t base = ((size_t)bh * SEQ + s) * DHEAD;

    float freq = (float)pow(10000.0, -(double)i / 64.0);  // correctly-rounded fp32 freq
    float ang  = (float)s * freq;                         // fp32 angle (matches reference)
    double sn_d, cs_d;
    sincos((double)ang, &sn_d, &cs_d);
    float sn = (float)sn_d, cs = (float)cs_d;

    float q1 = g_Q[base + i], q2 = g_Q[base + i + 64];
    g_Q[base + i]      = q1*cs - q2*sn;
    g_Q[base + i + 64] = q2*cs + q1*sn;
    float k1 = g_K[base + i], k2 = g_K[base + i + 64];
    g_K[base + i]      = k1*cs - k2*sn;
    g_K[base + i + 64] = k2*cs + k1*sn;
}

// ---------------- Flash-style causal attention (fp32) ----------------
// Br=Bc=64, 128 threads. Thread (tr=tid>>1, th=tid&1) owns query row tr,
// interleaved half of D: dims {(2*i+th)*4 .. +3 | i=0..15}. Full-D dot product
// combined across the pair via shfl_xor(.,1). Scores kept in SMEM (Ss).
// Writes directly to g_ctx (device symbol referenced from DEVICE code only —
// the R1 failure was passing g_ctx as a host-side kernel argument).
#define BR 64
#define BC 64
#define ATTN_SMEM_FLOATS (BC*DHEAD*2 + BR*BC + BC)
#define ATTN_SMEM_BYTES  (ATTN_SMEM_FLOATS * 4)   // 82176

__global__ void __launch_bounds__(128, 2) attn_kernel(const float* __restrict__ mask)
{
    extern __shared__ float sm[];
    float* Ks   = sm;                    // [BC][DHEAD]
    float* Vs   = Ks + BC*DHEAD;         // [BC][DHEAD]
    float* Ss   = Vs + BC*DHEAD;         // [BR][BC]
    float* bias = Ss + BR*BC;            // [BC]

    const int tid = threadIdx.x;
    const int tr  = tid >> 1;
    const int th  = tid & 1;
    const int qt  = blockIdx.x;
    const int h   = blockIdx.y;
    const int b   = blockIdx.z;
    const int q0  = qt * BR;
    const int qrow = q0 + tr;

    const size_t head_base = (size_t)(b*NHEAD + h) * SEQ * DHEAD;
    const float* Qh = g_Q + head_base;
    const float* Kh = g_K + head_base;
    const float* Vh = g_V + head_base;

    // load my query fragment
    float qreg[64];
    #pragma unroll
    for (int i = 0; i < 16; i++) {
        float4 v = *(const float4*)(Qh + (size_t)qrow*DHEAD + (2*i + th)*4);
        qreg[i*4+0] = v.x; qreg[i*4+1] = v.y; qreg[i*4+2] = v.z; qreg[i*4+3] = v.w;
    }

    float m = -1e30f, l = 0.f;
    float o[64];
    #pragma unroll
    for (int i = 0; i < 64; i++) o[i] = 0.f;

    const float scale = 0.08838834764831845f;   // 1/sqrt(128)
    const int nkt = qt + 1;                      // causal: key tiles 0..qt

    for (int kt = 0; kt < nkt; kt++) {
        const int k0 = kt * BC;
        __syncthreads();   // protect Ks/Vs from previous iteration's readers
        {
            const float4* Kg = (const float4*)(Kh + (size_t)k0*DHEAD);
            const float4* Vg = (const float4*)(Vh + (size_t)k0*DHEAD);
            float4* Ks4 = (float4*)Ks;
            float4* Vs4 = (float4*)Vs;
            #pragma unroll
            for (int i = 0; i < 16; i++) {
                int f = tid + i*128;            // 0..2047 float4s
                Ks4[f] = Kg[f];
                Vs4[f] = Vg[f];
            }
            if (tid < BC)
                bias[tid] = (1.0f - mask[b*SEQ + k0 + tid]) * -1e9f;
        }
        __syncthreads();

        // scores for my row
        #pragma unroll 4
        for (int kc = 0; kc < BC; kc++) {
            const float4* Krow = (const float4*)(Ks + kc*DHEAD);
            float acc = 0.f;
            #pragma unroll
            for (int i = 0; i < 16; i++) {
                float4 kv = Krow[2*i + th];
                acc += qreg[i*4+0]*kv.x + qreg[i*4+1]*kv.y
                     + qreg[i*4+2]*kv.z + qreg[i*4+3]*kv.w;
            }
            float s = acc + __shfl_xor_sync(0xffffffffu, acc, 1);
            s = s * scale + bias[kc];
            if (k0 + kc > qrow) s = -1e30f;     // causal (hits only on diagonal tile)
            Ss[tr*BC + kc] = s;                  // both partners write identical value
        }

        // online softmax update (row-private: no barrier needed)
        float tmax = -1e30f;
        #pragma unroll 8
        for (int kc = 0; kc < BC; kc++) tmax = fmaxf(tmax, Ss[tr*BC + kc]);
        float mnew = fmaxf(m, tmax);
        float corr = __expf(m - mnew);
        l *= corr;
        #pragma unroll
        for (int i = 0; i < 64; i++) o[i] *= corr;
        #pragma unroll 8
        for (int kc = 0; kc < BC; kc++) {
            float p = __expf(Ss[tr*BC + kc] - mnew);
            l += p;
            Ss[tr*BC + kc] = p;
        }
        m = mnew;

        // O accumulation
        #pragma unroll 4
        for (int kc = 0; kc < BC; kc++) {
            float p = Ss[tr*BC + kc];
            const float4* Vrow = (const float4*)(Vs + kc*DHEAD);
            #pragma unroll
            for (int i = 0; i < 16; i++) {
                float4 vv = Vrow[2*i + th];
                o[i*4+0] += p*vv.x; o[i*4+1] += p*vv.y;
                o[i*4+2] += p*vv.z; o[i*4+3] += p*vv.w;
            }
        }
    }

    const float inv = 1.0f / l;
    float* outp = g_ctx + ((size_t)(b*SEQ + qrow))*EMBED + h*DHEAD;
    #pragma unroll
    for (int i = 0; i < 16; i++) {
        *(float4*)(outp + (2*i + th)*4) =
            make_float4(o[i*4+0]*inv, o[i*4+1]*inv, o[i*4+2]*inv, o[i*4+3]*inv);
    }
}

// ---------------- launch ----------------
extern "C" void kernel_launch(void* const* d_in, const int* in_sizes, int n_in,
                              void* d_out, int out_size)
{
    (void)in_sizes; (void)n_in; (void)out_size;
    const float* x    = (const float*)d_in[0];
    const float* mask = (const float*)d_in[1];
    const float* Wq   = (const float*)d_in[2];
    const float* Wk   = (const float*)d_in[3];
    const float* Wv   = (const float*)d_in[4];
    const float* Wo   = (const float*)d_in[5];
    float* out        = (float*)d_out;

    cudaFuncSetAttribute(attn_kernel, cudaFuncAttributeMaxDynamicSharedMemorySize,
                         ATTN_SMEM_BYTES);

    dim3 ggrid(EMBED/BN, MTOT/BM, 1);   // (16, 32)
    gemm_nt<<<ggrid, 256>>>(x, Wq, nullptr, 0);
    gemm_nt<<<ggrid, 256>>>(x, Wk, nullptr, 1);
    gemm_nt<<<ggrid, 256>>>(x, Wv, nullptr, 2);

    rope_kernel<<<(BATCH*NHEAD*SEQ*64)/256, 256>>>();   // 16384 blocks

    attn_kernel<<<dim3(SEQ/BR, NHEAD, BATCH), 128, ATTN_SMEM_BYTES>>>(mask);

    gemm_nt<<<ggrid, 256>>>(nullptr, Wo, out, 3);
}

// round 5
// speedup vs baseline: 1.7729x; 1.7729x over previous
#include <cuda_runtime.h>
#include <cuda_bf16.h>
#include <math.h>
#include <stdint.h>

#define EMBED 2048
#define SEQ   2048
#define NHEAD 16
#define DHEAD 128
#define BATCH 2
#define MTOT  (BATCH*SEQ)   // 4096

// ---------------- static device scratch ----------------
__device__ float g_Q[BATCH*NHEAD*SEQ*DHEAD];
__device__ float g_K[BATCH*NHEAD*SEQ*DHEAD];
__device__ float g_V[BATCH*NHEAD*SEQ*DHEAD];
__device__ float g_ctx[BATCH*SEQ*EMBED];
__device__ __nv_bfloat16 g_xh[MTOT*EMBED];
__device__ __nv_bfloat16 g_xl[MTOT*EMBED];
__device__ __nv_bfloat16 g_Wh[4*EMBED*EMBED];
__device__ __nv_bfloat16 g_Wl[4*EMBED*EMBED];
__device__ __nv_bfloat16 g_ch[MTOT*EMBED];
__device__ __nv_bfloat16 g_cl[MTOT*EMBED];
__device__ float g_rsin[SEQ*64];
__device__ float g_rcos[SEQ*64];

// ---------------- baseline-PTX helpers (NO sm_103a-only instructions) ----------
__device__ __forceinline__ uint32_t smem_to_u32(const void* p) {
    uint32_t a;
    asm("{ .reg .u64 t; cvta.to.shared.u64 t, %1; cvt.u32.u64 %0, t; }" : "=r"(a) : "l"(p));
    return a;
}
#define CP_ASYNC16(saddr, gptr) \
    asm volatile("cp.async.cg.shared.global [%0], [%1], 16;" :: "r"(saddr), "l"(gptr) : "memory")
#define CP_COMMIT() asm volatile("cp.async.commit_group;" ::: "memory")
#define CP_WAIT1()  asm volatile("cp.async.wait_group 1;" ::: "memory")

__device__ __forceinline__ void ldsm_x4(uint32_t* r, uint32_t addr) {
    asm volatile("ldmatrix.sync.aligned.m8n8.x4.shared.b16 {%0,%1,%2,%3}, [%4];"
                 : "=r"(r[0]), "=r"(r[1]), "=r"(r[2]), "=r"(r[3]) : "r"(addr));
}
__device__ __forceinline__ void mma_bf16(float* c, const uint32_t* a, const uint32_t* b) {
    asm volatile("mma.sync.aligned.m16n8k16.row.col.f32.bf16.bf16.f32 "
                 "{%0,%1,%2,%3}, {%4,%5,%6,%7}, {%8,%9}, {%0,%1,%2,%3};"
                 : "+f"(c[0]), "+f"(c[1]), "+f"(c[2]), "+f"(c[3])
                 : "r"(a[0]), "r"(a[1]), "r"(a[2]), "r"(a[3]), "r"(b[0]), "r"(b[1]));
}

// ---------------- split: f32 -> bf16 hi + bf16 lo ----------------
// which: 0=x, 1..4=Wq/Wk/Wv/Wo, 5=g_ctx (src arg ignored)
__global__ void __launch_bounds__(256) split_kernel(const float* __restrict__ src,
                                                    int which, int n4)
{
    int idx = blockIdx.x * 256 + threadIdx.x;
    if (idx >= n4) return;
    const float* s = (which == 5) ? g_ctx : src;
    __nv_bfloat16 *hi, *lo;
    if (which == 0)      { hi = g_xh; lo = g_xl; }
    else if (which <= 4) { size_t off = (size_t)(which - 1) * EMBED * EMBED;
                           hi = g_Wh + off; lo = g_Wl + off; }
    else                 { hi = g_ch; lo = g_cl; }

    float4 v = ((const float4*)s)[idx];
    float f[4] = {v.x, v.y, v.z, v.w};
    __nv_bfloat16 h[4], l[4];
    #pragma unroll
    for (int j = 0; j < 4; j++) {
        h[j] = __float2bfloat16(f[j]);
        float r = f[j] - __bfloat162float(h[j]);
        l[j] = __float2bfloat16(r);
    }
    __nv_bfloat162* hp = (__nv_bfloat162*)hi;
    __nv_bfloat162* lp = (__nv_bfloat162*)lo;
    hp[idx*2]   = __nv_bfloat162(h[0], h[1]);
    hp[idx*2+1] = __nv_bfloat162(h[2], h[3]);
    lp[idx*2]   = __nv_bfloat162(l[0], l[1]);
    lp[idx*2+1] = __nv_bfloat162(l[2], l[3]);
}

// ---------------- mma.sync bf16 split GEMM: C = A[M,K] * W[N,K]^T ----------------
// Block 128x128, BK=32, 8 warps in 2(M) x 4(N); warp tile 64x32.
// SMEM tiles: 128 rows x 32 bf16, row pitch 80B (conflict-free ldmatrix).
// mode 0/1/2: A = x split -> g_Q/g_K/g_V [B,H,S,D]; mode 3: A = ctx split -> Cout
#define GT_PITCH 80
#define GT_TILE  (128*GT_PITCH)          // 10240 B
#define GT_STAGE (4*GT_TILE)             // Ah, Al, Wh, Wl = 40960 B
#define GEMM_SMEM (2*GT_STAGE)           // 81920 B

__global__ void __launch_bounds__(256) gemm_mma(float* __restrict__ Cout, int mode)
{
    extern __shared__ char smem[];
    const uint32_t sbase = smem_to_u32(smem);
    const int tid  = threadIdx.x;
    const int lane = tid & 31;
    const int wid  = tid >> 5;
    const int warp_m = wid >> 2;          // 0..1
    const int warp_n = wid & 3;           // 0..3
    const int n0 = blockIdx.x * 128;
    const int m0 = blockIdx.y * 128;

    const __nv_bfloat16* srcs[4];
    srcs[0] = ((mode == 3) ? g_ch : g_xh);
    srcs[1] = ((mode == 3) ? g_cl : g_xl);
    srcs[2] = g_Wh + (size_t)mode * EMBED * EMBED;
    srcs[3] = g_Wl + (size_t)mode * EMBED * EMBED;
    const int base_row[4] = {m0, m0, n0, n0};

    // per-thread gmem/smem load coords: 2 chunks of 16B per tile per stage
    const int l_row0 = tid >> 2;                  // idx = tid
    const int l_seg0 = tid & 3;
    const int l_row1 = (tid + 256) >> 2;          // idx = tid + 256
    const int l_seg1 = tid & 3;                   // (tid+256)&3 == tid&3

    // ldmatrix fragment base offsets (bytes within a tile)
    const uint32_t a_off = (uint32_t)((warp_m*64 + (lane & 15)) * GT_PITCH + (lane >> 4) * 16);
    const uint32_t b_off = (uint32_t)(((lane & 7) + (lane >> 4) * 8 + warp_n*32) * GT_PITCH
                                      + ((lane >> 3) & 1) * 16);

    float acc[4][4][4];
    #pragma unroll
    for (int i = 0; i < 4; i++)
        #pragma unroll
        for (int j = 0; j < 4; j++)
            #pragma unroll
            for (int r = 0; r < 4; r++) acc[i][j][r] = 0.f;

    // ---- software pipeline: prefetch stage 0 ----
    {
        const uint32_t sb = sbase;   // buf 0
        #pragma unroll
        for (int t = 0; t < 4; t++) {
            const __nv_bfloat16* g0 = srcs[t] + (size_t)(base_row[t] + l_row0) * EMBED + l_seg0*8;
            const __nv_bfloat16* g1 = srcs[t] + (size_t)(base_row[t] + l_row1) * EMBED + l_seg1*8;
            CP_ASYNC16(sb + t*GT_TILE + l_row0*GT_PITCH + l_seg0*16, g0);
            CP_ASYNC16(sb + t*GT_TILE + l_row1*GT_PITCH + l_seg1*16, g1);
        }
        CP_COMMIT();
    }

    for (int s = 0; s < EMBED/32; s++) {          // 64 stages
        if (s < EMBED/32 - 1) {
            const uint32_t sb = sbase + ((s+1) & 1) * GT_STAGE;
            const int k0 = (s+1) * 32;
            #pragma unroll
            for (int t = 0; t < 4; t++) {
                const __nv_bfloat16* g0 = srcs[t] + (size_t)(base_row[t] + l_row0) * EMBED + k0 + l_seg0*8;
                const __nv_bfloat16* g1 = srcs[t] + (size_t)(base_row[t] + l_row1) * EMBED + k0 + l_seg1*8;
                CP_ASYNC16(sb + t*GT_TILE + l_row0*GT_PITCH + l_seg0*16, g0);
                CP_ASYNC16(sb + t*GT_TILE + l_row1*GT_PITCH + l_seg1*16, g1);
            }
        }
        CP_COMMIT();
        CP_WAIT1();          // stage s complete (only stage s+1 may still be pending)
        __syncthreads();

        const uint32_t sb = sbase + (s & 1) * GT_STAGE;
        #pragma unroll
        for (int kk = 0; kk < 2; kk++) {          // two k16 steps per stage
            const uint32_t ko = kk * 32;          // 16 bf16 = 32 bytes
            uint32_t Af[4][4], Lf[4][4], Bf[2][4];
            // hi*hi
            #pragma unroll
            for (int ma = 0; ma < 4; ma++)
                ldsm_x4(Af[ma], sb + 0*GT_TILE + a_off + ko + ma*16*GT_PITCH);
            #pragma unroll
            for (int nb = 0; nb < 2; nb++)
                ldsm_x4(Bf[nb], sb + 2*GT_TILE + b_off + ko + nb*16*GT_PITCH);
            #pragma unroll
            for (int ma = 0; ma < 4; ma++)
                #pragma unroll
                for (int na = 0; na < 4; na++)
                    mma_bf16(acc[ma][na], Af[ma], &Bf[na >> 1][(na & 1) * 2]);
            // lo*hi  (Al x Wh)
            #pragma unroll
            for (int ma = 0; ma < 4; ma++)
                ldsm_x4(Lf[ma], sb + 1*GT_TILE + a_off + ko + ma*16*GT_PITCH);
            #pragma unroll
            for (int ma = 0; ma < 4; ma++)
                #pragma unroll
                for (int na = 0; na < 4; na++)
                    mma_bf16(acc[ma][na], Lf[ma], &Bf[na >> 1][(na & 1) * 2]);
            // hi*lo  (Ah x Wl)
            #pragma unroll
            for (int nb = 0; nb < 2; nb++)
                ldsm_x4(Bf[nb], sb + 3*GT_TILE + b_off + ko + nb*16*GT_PITCH);
            #pragma unroll
            for (int ma = 0; ma < 4; ma++)
                #pragma unroll
                for (int na = 0; na < 4; na++)
                    mma_bf16(acc[ma][na], Af[ma], &Bf[na >> 1][(na & 1) * 2]);
        }
        __syncthreads();     // safe to overwrite this buffer next iteration
    }

    // ---- epilogue ----
    const int r0 = lane >> 2;
    const int c0 = (lane & 3) * 2;
    #pragma unroll
    for (int ma = 0; ma < 4; ma++) {
        #pragma unroll
        for (int na = 0; na < 4; na++) {
            const int coln = warp_n*32 + na*8 + c0;     // 0..127 within n-tile
            #pragma unroll
            for (int half = 0; half < 2; half++) {
                const int m = m0 + warp_m*64 + ma*16 + r0 + half*8;
                float2 val = make_float2(acc[ma][na][half*2], acc[ma][na][half*2+1]);
                if (mode <= 2) {
                    float* base = (mode == 0) ? g_Q : (mode == 1) ? g_K : g_V;
                    const int b = m >> 11, ss = m & (SEQ - 1);
                    *(float2*)(base + ((size_t)((b*NHEAD + blockIdx.x)*SEQ + ss))*DHEAD + coln) = val;
                } else {
                    *(float2*)(Cout + (size_t)m * EMBED + n0 + coln) = val;
                }
            }
        }
    }
}

// ---------------- RoPE table + apply ----------------
__global__ void __launch_bounds__(256) rope_table()
{
    int idx = blockIdx.x * 256 + threadIdx.x;   // [0, SEQ*64)
    int i = idx & 63, s = idx >> 6;
    float freq = (float)pow(10000.0, -(double)i / 64.0);
    float ang  = (float)s * freq;
    double sn, cs;
    sincos((double)ang, &sn, &cs);
    g_rsin[idx] = (float)sn;
    g_rcos[idx] = (float)cs;
}

__global__ void __launch_bounds__(256) rope_apply()
{
    int idx = blockIdx.x * 256 + threadIdx.x;   // [0, B*H*S*64)
    int i = idx & 63;
    int s = (idx >> 6) & (SEQ - 1);
    size_t base = ((size_t)(idx >> 6)) * DHEAD;
    float sn = g_rsin[s*64 + i], cs = g_rcos[s*64 + i];

    float q1 = g_Q[base + i], q2 = g_Q[base + i + 64];
    g_Q[base + i]      = q1*cs - q2*sn;
    g_Q[base + i + 64] = q2*cs + q1*sn;
    float k1 = g_K[base + i], k2 = g_K[base + i + 64];
    g_K[base + i]      = k1*cs - k2*sn;
    g_K[base + i + 64] = k2*cs + k1*sn;
}

// ---------------- Flash-style causal attention (fp32, validated in R3) ----------
#define BR 64
#define BC 64
#define ATTN_SMEM_FLOATS (BC*DHEAD*2 + BR*BC + BC)
#define ATTN_SMEM_BYTES  (ATTN_SMEM_FLOATS * 4)   // 82176

__global__ void __launch_bounds__(128, 2) attn_kernel(const float* __restrict__ mask)
{
    extern __shared__ float sm[];
    float* Ks   = sm;
    float* Vs   = Ks + BC*DHEAD;
    float* Ss   = Vs + BC*DHEAD;
    float* bias = Ss + BR*BC;

    const int tid = threadIdx.x;
    const int tr  = tid >> 1;
    const int th  = tid & 1;
    const int qt  = blockIdx.x;
    const int h   = blockIdx.y;
    const int b   = blockIdx.z;
    const int qrow = qt * BR + tr;

    const size_t head_base = (size_t)(b*NHEAD + h) * SEQ * DHEAD;
    const float* Qh = g_Q + head_base;
    const float* Kh = g_K + head_base;
    const float* Vh = g_V + head_base;

    float qreg[64];
    #pragma unroll
    for (int i = 0; i < 16; i++) {
        float4 v = *(const float4*)(Qh + (size_t)qrow*DHEAD + (2*i + th)*4);
        qreg[i*4+0] = v.x; qreg[i*4+1] = v.y; qreg[i*4+2] = v.z; qreg[i*4+3] = v.w;
    }

    float m = -1e30f, l = 0.f;
    float o[64];
    #pragma unroll
    for (int i = 0; i < 64; i++) o[i] = 0.f;

    const float scale = 0.08838834764831845f;
    const int nkt = qt + 1;

    for (int kt = 0; kt < nkt; kt++) {
        const int k0 = kt * BC;
        __syncthreads();
        {
            const float4* Kg = (const float4*)(Kh + (size_t)k0*DHEAD);
            const float4* Vg = (const float4*)(Vh + (size_t)k0*DHEAD);
            float4* Ks4 = (float4*)Ks;
            float4* Vs4 = (float4*)Vs;
            #pragma unroll
            for (int i = 0; i < 16; i++) {
                int f = tid + i*128;
                Ks4[f] = Kg[f];
                Vs4[f] = Vg[f];
            }
            if (tid < BC)
                bias[tid] = (1.0f - mask[b*SEQ + k0 + tid]) * -1e9f;
        }
        __syncthreads();

        #pragma unroll 4
        for (int kc = 0; kc < BC; kc++) {
            const float4* Krow = (const float4*)(Ks + kc*DHEAD);
            float acc = 0.f;
            #pragma unroll
            for (int i = 0; i < 16; i++) {
                float4 kv = Krow[2*i + th];
                acc += qreg[i*4+0]*kv.x + qreg[i*4+1]*kv.y
                     + qreg[i*4+2]*kv.z + qreg[i*4+3]*kv.w;
            }
            float s = acc + __shfl_xor_sync(0xffffffffu, acc, 1);
            s = s * scale + bias[kc];
            if (k0 + kc > qrow) s = -1e30f;
            Ss[tr*BC + kc] = s;
        }

        float tmax = -1e30f;
        #pragma unroll 8
        for (int kc = 0; kc < BC; kc++) tmax = fmaxf(tmax, Ss[tr*BC + kc]);
        float mnew = fmaxf(m, tmax);
        float corr = __expf(m - mnew);
        l *= corr;
        #pragma unroll
        for (int i = 0; i < 64; i++) o[i] *= corr;
        #pragma unroll 8
        for (int kc = 0; kc < BC; kc++) {
            float p = __expf(Ss[tr*BC + kc] - mnew);
            l += p;
            Ss[tr*BC + kc] = p;
        }
        m = mnew;

        #pragma unroll 4
        for (int kc = 0; kc < BC; kc++) {
            float p = Ss[tr*BC + kc];
            const float4* Vrow = (const float4*)(Vs + kc*DHEAD);
            #pragma unroll
            for (int i = 0; i < 16; i++) {
                float4 vv = Vrow[2*i + th];
                o[i*4+0] += p*vv.x; o[i*4+1] += p*vv.y;
                o[i*4+2] += p*vv.z; o[i*4+3] += p*vv.w;
            }
        }
    }

    const float inv = 1.0f / l;
    float* outp = g_ctx + ((size_t)(b*SEQ + qrow))*EMBED + h*DHEAD;
    #pragma unroll
    for (int i = 0; i < 16; i++) {
        *(float4*)(outp + (2*i + th)*4) =
            make_float4(o[i*4+0]*inv, o[i*4+1]*inv, o[i*4+2]*inv, o[i*4+3]*inv);
    }
}

// ---------------- launch ----------------
extern "C" void kernel_launch(void* const* d_in, const int* in_sizes, int n_in,
                              void* d_out, int out_size)
{
    (void)in_sizes; (void)n_in; (void)out_size;
    const float* x    = (const float*)d_in[0];
    const float* mask = (const float*)d_in[1];
    const float* Wq   = (const float*)d_in[2];
    const float* Wk   = (const float*)d_in[3];
    const float* Wv   = (const float*)d_in[4];
    const float* Wo   = (const float*)d_in[5];
    float* out        = (float*)d_out;

    cudaFuncSetAttribute(gemm_mma, cudaFuncAttributeMaxDynamicSharedMemorySize, GEMM_SMEM);
    cudaFuncSetAttribute(attn_kernel, cudaFuncAttributeMaxDynamicSharedMemorySize, ATTN_SMEM_BYTES);

    const int n4x = MTOT*EMBED/4;      // 2097152
    const int n4w = EMBED*EMBED/4;     // 1048576

    split_kernel<<<(n4x+255)/256, 256>>>(x, 0, n4x);
    split_kernel<<<(n4w+255)/256, 256>>>(Wq, 1, n4w);
    split_kernel<<<(n4w+255)/256, 256>>>(Wk, 2, n4w);
    split_kernel<<<(n4w+255)/256, 256>>>(Wv, 3, n4w);
    split_kernel<<<(n4w+255)/256, 256>>>(Wo, 4, n4w);

    rope_table<<<(SEQ*64)/256, 256>>>();

    dim3 ggrid(EMBED/128, MTOT/128);   // (16, 32)
    gemm_mma<<<ggrid, 256, GEMM_SMEM>>>(nullptr, 0);
    gemm_mma<<<ggrid, 256, GEMM_SMEM>>>(nullptr, 1);
    gemm_mma<<<ggrid, 256, GEMM_SMEM>>>(nullptr, 2);

    rope_apply<<<(BATCH*NHEAD*SEQ*64)/256, 256>>>();

    attn_kernel<<<dim3(SEQ/BR, NHEAD, BATCH), 128, ATTN_SMEM_BYTES>>>(mask);

    split_kernel<<<(n4x+255)/256, 256>>>(x /*ignored*/, 5, n4x);
    gemm_mma<<<ggrid, 256, GEMM_SMEM>>>(out, 3);
}

// round 6
// speedup vs baseline: 3.1682x; 1.7871x over previous
#include <cuda_runtime.h>
#include <cuda_bf16.h>
#include <math.h>
#include <stdint.h>

#define EMBED 2048
#define SEQ   2048
#define NHEAD 16
#define DHEAD 128
#define BATCH 2
#define MTOT  (BATCH*SEQ)   // 4096

// ---------------- static device scratch ----------------
__device__ float g_Q[BATCH*NHEAD*SEQ*DHEAD];
__device__ float g_K[BATCH*NHEAD*SEQ*DHEAD];
__device__ float g_V[BATCH*NHEAD*SEQ*DHEAD];
__device__ float g_ctx[BATCH*SEQ*EMBED];
__device__ __nv_bfloat16 g_xh[MTOT*EMBED];
__device__ __nv_bfloat16 g_xl[MTOT*EMBED];
__device__ __nv_bfloat16 g_Wh[4*EMBED*EMBED];
__device__ __nv_bfloat16 g_Wl[4*EMBED*EMBED];
__device__ __nv_bfloat16 g_ch[MTOT*EMBED];
__device__ __nv_bfloat16 g_cl[MTOT*EMBED];
__device__ __nv_bfloat16 g_Qh[BATCH*NHEAD*SEQ*DHEAD];
__device__ __nv_bfloat16 g_Ql[BATCH*NHEAD*SEQ*DHEAD];
__device__ __nv_bfloat16 g_Kh[BATCH*NHEAD*SEQ*DHEAD];
__device__ __nv_bfloat16 g_Kl[BATCH*NHEAD*SEQ*DHEAD];
__device__ __nv_bfloat16 g_Vh[BATCH*NHEAD*SEQ*DHEAD];
__device__ __nv_bfloat16 g_Vl[BATCH*NHEAD*SEQ*DHEAD];
__device__ float g_rsin[SEQ*64];
__device__ float g_rcos[SEQ*64];

// ---------------- baseline-PTX helpers ----------------
__device__ __forceinline__ uint32_t smem_to_u32(const void* p) {
    uint32_t a;
    asm("{ .reg .u64 t; cvta.to.shared.u64 t, %1; cvt.u32.u64 %0, t; }" : "=r"(a) : "l"(p));
    return a;
}
#define CP_ASYNC16(saddr, gptr) \
    asm volatile("cp.async.cg.shared.global [%0], [%1], 16;" :: "r"(saddr), "l"(gptr) : "memory")
#define CP_COMMIT() asm volatile("cp.async.commit_group;" ::: "memory")
#define CP_WAIT1()  asm volatile("cp.async.wait_group 1;" ::: "memory")

__device__ __forceinline__ void ldsm_x4(uint32_t* r, uint32_t addr) {
    asm volatile("ldmatrix.sync.aligned.m8n8.x4.shared.b16 {%0,%1,%2,%3}, [%4];"
                 : "=r"(r[0]), "=r"(r[1]), "=r"(r[2]), "=r"(r[3]) : "r"(addr));
}
__device__ __forceinline__ void ldsm_x4_t(uint32_t* r, uint32_t addr) {
    asm volatile("ldmatrix.sync.aligned.m8n8.x4.trans.shared.b16 {%0,%1,%2,%3}, [%4];"
                 : "=r"(r[0]), "=r"(r[1]), "=r"(r[2]), "=r"(r[3]) : "r"(addr));
}
__device__ __forceinline__ void mma_bf16(float* c, const uint32_t* a, const uint32_t* b) {
    asm volatile("mma.sync.aligned.m16n8k16.row.col.f32.bf16.bf16.f32 "
                 "{%0,%1,%2,%3}, {%4,%5,%6,%7}, {%8,%9}, {%0,%1,%2,%3};"
                 : "+f"(c[0]), "+f"(c[1]), "+f"(c[2]), "+f"(c[3])
                 : "r"(a[0]), "r"(a[1]), "r"(a[2]), "r"(a[3]), "r"(b[0]), "r"(b[1]));
}
// split a float pair into packed bf16 hi + bf16 lo fragments
__device__ __forceinline__ void split_pack(float x, float y, uint32_t& hi, uint32_t& lo) {
    __nv_bfloat16 hx = __float2bfloat16(x), hy = __float2bfloat16(y);
    hi = ((uint32_t)__bfloat16_as_ushort(hy) << 16) | __bfloat16_as_ushort(hx);
    __nv_bfloat16 lx = __float2bfloat16(x - __bfloat162float(hx));
    __nv_bfloat16 ly = __float2bfloat16(y - __bfloat162float(hy));
    lo = ((uint32_t)__bfloat16_as_ushort(ly) << 16) | __bfloat16_as_ushort(lx);
}

// ---------------- split: f32 -> bf16 hi + bf16 lo ----------------
// which: 0=x, 1..4=Wq/Wk/Wv/Wo, 5=g_ctx, 6=g_V (src ignored for 5,6)
__global__ void __launch_bounds__(256) split_kernel(const float* __restrict__ src,
                                                    int which, int n4)
{
    int idx = blockIdx.x * 256 + threadIdx.x;
    if (idx >= n4) return;
    const float* s = (which == 5) ? g_ctx : (which == 6) ? g_V : src;
    __nv_bfloat16 *hi, *lo;
    if (which == 0)      { hi = g_xh; lo = g_xl; }
    else if (which <= 4) { size_t off = (size_t)(which - 1) * EMBED * EMBED;
                           hi = g_Wh + off; lo = g_Wl + off; }
    else if (which == 5) { hi = g_ch; lo = g_cl; }
    else                 { hi = g_Vh; lo = g_Vl; }

    float4 v = ((const float4*)s)[idx];
    float f[4] = {v.x, v.y, v.z, v.w};
    __nv_bfloat16 h[4], l[4];
    #pragma unroll
    for (int j = 0; j < 4; j++) {
        h[j] = __float2bfloat16(f[j]);
        float r = f[j] - __bfloat162float(h[j]);
        l[j] = __float2bfloat16(r);
    }
    __nv_bfloat162* hp = (__nv_bfloat162*)hi;
    __nv_bfloat162* lp = (__nv_bfloat162*)lo;
    hp[idx*2]   = __nv_bfloat162(h[0], h[1]);
    hp[idx*2+1] = __nv_bfloat162(h[2], h[3]);
    lp[idx*2]   = __nv_bfloat162(l[0], l[1]);
    lp[idx*2+1] = __nv_bfloat162(l[2], l[3]);
}

// ---------------- mma.sync bf16 split GEMM (validated R5) ----------------
#define GT_PITCH 80
#define GT_TILE  (128*GT_PITCH)
#define GT_STAGE (4*GT_TILE)
#define GEMM_SMEM (2*GT_STAGE)

__global__ void __launch_bounds__(256) gemm_mma(float* __restrict__ Cout, int mode)
{
    extern __shared__ char smc[];
    const uint32_t sbase = smem_to_u32(smc);
    const int tid  = threadIdx.x;
    const int lane = tid & 31;
    const int wid  = tid >> 5;
    const int warp_m = wid >> 2;
    const int warp_n = wid & 3;
    const int n0 = blockIdx.x * 128;
    const int m0 = blockIdx.y * 128;

    const __nv_bfloat16* srcs[4];
    srcs[0] = ((mode == 3) ? g_ch : g_xh);
    srcs[1] = ((mode == 3) ? g_cl : g_xl);
    srcs[2] = g_Wh + (size_t)mode * EMBED * EMBED;
    srcs[3] = g_Wl + (size_t)mode * EMBED * EMBED;
    const int base_row[4] = {m0, m0, n0, n0};

    const int l_row0 = tid >> 2;
    const int l_seg0 = tid & 3;
    const int l_row1 = (tid + 256) >> 2;
    const int l_seg1 = tid & 3;

    const uint32_t a_off = (uint32_t)((warp_m*64 + (lane & 15)) * GT_PITCH + (lane >> 4) * 16);
    const uint32_t b_off = (uint32_t)(((lane & 7) + (lane >> 4) * 8 + warp_n*32) * GT_PITCH
                                      + ((lane >> 3) & 1) * 16);

    float acc[4][4][4];
    #pragma unroll
    for (int i = 0; i < 4; i++)
        #pragma unroll
        for (int j = 0; j < 4; j++)
            #pragma unroll
            for (int r = 0; r < 4; r++) acc[i][j][r] = 0.f;

    {
        const uint32_t sb = sbase;
        #pragma unroll
        for (int t = 0; t < 4; t++) {
            const __nv_bfloat16* g0 = srcs[t] + (size_t)(base_row[t] + l_row0) * EMBED + l_seg0*8;
            const __nv_bfloat16* g1 = srcs[t] + (size_t)(base_row[t] + l_row1) * EMBED + l_seg1*8;
            CP_ASYNC16(sb + t*GT_TILE + l_row0*GT_PITCH + l_seg0*16, g0);
            CP_ASYNC16(sb + t*GT_TILE + l_row1*GT_PITCH + l_seg1*16, g1);
        }
        CP_COMMIT();
    }

    for (int s = 0; s < EMBED/32; s++) {
        if (s < EMBED/32 - 1) {
            const uint32_t sb = sbase + ((s+1) & 1) * GT_STAGE;
            const int k0 = (s+1) * 32;
            #pragma unroll
            for (int t = 0; t < 4; t++) {
                const __nv_bfloat16* g0 = srcs[t] + (size_t)(base_row[t] + l_row0) * EMBED + k0 + l_seg0*8;
                const __nv_bfloat16* g1 = srcs[t] + (size_t)(base_row[t] + l_row1) * EMBED + k0 + l_seg1*8;
                CP_ASYNC16(sb + t*GT_TILE + l_row0*GT_PITCH + l_seg0*16, g0);
                CP_ASYNC16(sb + t*GT_TILE + l_row1*GT_PITCH + l_seg1*16, g1);
            }
        }
        CP_COMMIT();
        CP_WAIT1();
        __syncthreads();

        const uint32_t sb = sbase + (s & 1) * GT_STAGE;
        #pragma unroll
        for (int kk = 0; kk < 2; kk++) {
            const uint32_t ko = kk * 32;
            uint32_t Af[4][4], Lf[4][4], Bf[2][4];
            #pragma unroll
            for (int ma = 0; ma < 4; ma++)
                ldsm_x4(Af[ma], sb + 0*GT_TILE + a_off + ko + ma*16*GT_PITCH);
            #pragma unroll
            for (int nb = 0; nb < 2; nb++)
                ldsm_x4(Bf[nb], sb + 2*GT_TILE + b_off + ko + nb*16*GT_PITCH);
            #pragma unroll
            for (int ma = 0; ma < 4; ma++)
                #pragma unroll
                for (int na = 0; na < 4; na++)
                    mma_bf16(acc[ma][na], Af[ma], &Bf[na >> 1][(na & 1) * 2]);
            #pragma unroll
            for (int ma = 0; ma < 4; ma++)
                ldsm_x4(Lf[ma], sb + 1*GT_TILE + a_off + ko + ma*16*GT_PITCH);
            #pragma unroll
            for (int ma = 0; ma < 4; ma++)
                #pragma unroll
                for (int na = 0; na < 4; na++)
                    mma_bf16(acc[ma][na], Lf[ma], &Bf[na >> 1][(na & 1) * 2]);
            #pragma unroll
            for (int nb = 0; nb < 2; nb++)
                ldsm_x4(Bf[nb], sb + 3*GT_TILE + b_off + ko + nb*16*GT_PITCH);
            #pragma unroll
            for (int ma = 0; ma < 4; ma++)
                #pragma unroll
                for (int na = 0; na < 4; na++)
                    mma_bf16(acc[ma][na], Af[ma], &Bf[na >> 1][(na & 1) * 2]);
        }
        __syncthreads();
    }

    const int r0 = lane >> 2;
    const int c0 = (lane & 3) * 2;
    #pragma unroll
    for (int ma = 0; ma < 4; ma++) {
        #pragma unroll
        for (int na = 0; na < 4; na++) {
            const int coln = warp_n*32 + na*8 + c0;
            #pragma unroll
            for (int half = 0; half < 2; half++) {
                const int m = m0 + warp_m*64 + ma*16 + r0 + half*8;
                float2 val = make_float2(acc[ma][na][half*2], acc[ma][na][half*2+1]);
                if (mode <= 2) {
                    float* base = (mode == 0) ? g_Q : (mode == 1) ? g_K : g_V;
                    const int b = m >> 11, ss = m & (SEQ - 1);
                    *(float2*)(base + ((size_t)((b*NHEAD + blockIdx.x)*SEQ + ss))*DHEAD + coln) = val;
                } else {
                    *(float2*)(Cout + (size_t)m * EMBED + n0 + coln) = val;
                }
            }
        }
    }
}

// ---------------- RoPE table + apply (apply now emits bf16 hi/lo) ------------
__global__ void __launch_bounds__(256) rope_table()
{
    int idx = blockIdx.x * 256 + threadIdx.x;
    int i = idx & 63, s = idx >> 6;
    float freq = (float)pow(10000.0, -(double)i / 64.0);
    float ang  = (float)s * freq;
    double sn, cs;
    sincos((double)ang, &sn, &cs);
    g_rsin[idx] = (float)sn;
    g_rcos[idx] = (float)cs;
}

__global__ void __launch_bounds__(256) rope_apply()
{
    int idx = blockIdx.x * 256 + threadIdx.x;
    int i = idx & 63;
    int s = (idx >> 6) & (SEQ - 1);
    size_t base = ((size_t)(idx >> 6)) * DHEAD;
    float sn = g_rsin[s*64 + i], cs = g_rcos[s*64 + i];

    float q1 = g_Q[base + i], q2 = g_Q[base + i + 64];
    float k1 = g_K[base + i], k2 = g_K[base + i + 64];
    float qa = q1*cs - q2*sn, qb = q2*cs + q1*sn;
    float ka = k1*cs - k2*sn, kb = k2*cs + k1*sn;

    __nv_bfloat16 h;
    h = __float2bfloat16(qa); g_Qh[base+i]    = h; g_Ql[base+i]    = __float2bfloat16(qa - __bfloat162float(h));
    h = __float2bfloat16(qb); g_Qh[base+i+64] = h; g_Ql[base+i+64] = __float2bfloat16(qb - __bfloat162float(h));
    h = __float2bfloat16(ka); g_Kh[base+i]    = h; g_Kl[base+i]    = __float2bfloat16(ka - __bfloat162float(h));
    h = __float2bfloat16(kb); g_Kh[base+i+64] = h; g_Kl[base+i+64] = __float2bfloat16(kb - __bfloat162float(h));
}

// ---------------- FA2-style bf16 mma attention ----------------
// BR=64 queries/CTA, BC=64 keys/tile, 4 warps, warp owns 16 query rows.
// SMEM pitch 272B => conflict-free ldmatrix. K/V double-buffered via cp.async.
#define AP   272
#define AT   (64*AP)          // 17408 per tile
#define AST  (4*AT)           // stage: Kh,Kl,Vh,Vl
#define AQOFF (2*AST)         // Qh,Ql
#define ABIAS (AQOFF + 2*AT)  // 174080
#define ATTN_SMEM (ABIAS + 512)

__device__ __forceinline__ void attn_pf(uint32_t sb_stage,
    const __nv_bfloat16* Kh, const __nv_bfloat16* Kl,
    const __nv_bfloat16* Vh, const __nv_bfloat16* Vl, int k0, int tid)
{
    #pragma unroll
    for (int i = 0; i < 8; i++) {
        int idx = tid + i*128;
        int r = idx >> 4, c = idx & 15;
        uint32_t so = sb_stage + r*AP + c*16;
        size_t go = (size_t)(k0 + r) * DHEAD;
        CP_ASYNC16(so,        (const char*)(Kh + go) + c*16);
        CP_ASYNC16(so + AT,   (const char*)(Kl + go) + c*16);
        CP_ASYNC16(so + 2*AT, (const char*)(Vh + go) + c*16);
        CP_ASYNC16(so + 3*AT, (const char*)(Vl + go) + c*16);
    }
}

__global__ void __launch_bounds__(128) attn_mma(const float* __restrict__ mask)
{
    extern __shared__ char smc[];
    const uint32_t sb = smem_to_u32(smc);
    const int tid = threadIdx.x, lane = tid & 31, wid = tid >> 5;
    const int qt = blockIdx.x, h = blockIdx.y, b = blockIdx.z;
    const int q0 = qt * 64;
    const size_t hb = (size_t)(b*NHEAD + h) * SEQ * DHEAD;
    const __nv_bfloat16 *Qh = g_Qh + hb, *Ql = g_Ql + hb;
    const __nv_bfloat16 *Kh = g_Kh + hb, *Kl = g_Kl + hb;
    const __nv_bfloat16 *Vh = g_Vh + hb, *Vl = g_Vl + hb;
    float* bias_sm = (float*)(smc + ABIAS);

    // Q tiles + KV tile 0 + bias 0
    #pragma unroll
    for (int i = 0; i < 8; i++) {
        int idx = tid + i*128;
        int r = idx >> 4, c = idx & 15;
        uint32_t so = sb + AQOFF + r*AP + c*16;
        size_t go = (size_t)(q0 + r) * DHEAD;
        CP_ASYNC16(so,      (const char*)(Qh + go) + c*16);
        CP_ASYNC16(so + AT, (const char*)(Ql + go) + c*16);
    }
    attn_pf(sb, Kh, Kl, Vh, Vl, 0, tid);
    if (tid < 64) bias_sm[tid] = (1.0f - mask[b*SEQ + tid]) * -1e9f;
    CP_COMMIT();

    float O[16][4];
    #pragma unroll
    for (int j = 0; j < 16; j++)
        #pragma unroll
        for (int r = 0; r < 4; r++) O[j][r] = 0.f;
    float m_a = -1e30f, m_b = -1e30f, l_a = 0.f, l_b = 0.f;
    const float scale = 0.08838834764831845f;
    const int q_a = q0 + wid*16 + (lane >> 2);
    const int klo = 2*(lane & 3);

    for (int kt = 0; kt <= qt; kt++) {
        const int stage = kt & 1;
        if (kt < qt) {
            attn_pf(sb + (stage^1)*AST, Kh, Kl, Vh, Vl, (kt+1)*64, tid);
            if (tid < 64) bias_sm[(stage^1)*64 + tid] = (1.0f - mask[b*SEQ + (kt+1)*64 + tid]) * -1e9f;
        }
        CP_COMMIT();
        CP_WAIT1();
        __syncthreads();

        const uint32_t ss = sb + stage*AST;
        float s[8][4];
        #pragma unroll
        for (int j = 0; j < 8; j++)
            #pragma unroll
            for (int r = 0; r < 4; r++) s[j][r] = 0.f;

        // ---- scores: (Qh+Ql)(Kh+Kl)^T, drop lo*lo ----
        #pragma unroll
        for (int t = 0; t < 8; t++) {
            uint32_t Aaddr = sb + AQOFF + (wid*16 + (lane & 15))*AP + t*32 + (lane >> 4)*16;
            uint32_t Ah4[4], Al4[4];
            ldsm_x4(Ah4, Aaddr);
            ldsm_x4(Al4, Aaddr + AT);
            uint32_t Kh4[4][4], Kl4[4][4];
            #pragma unroll
            for (int g = 0; g < 4; g++) {
                uint32_t Baddr = ss + (g*16 + (lane & 7) + ((lane >> 4) << 3))*AP
                               + t*32 + ((lane >> 3) & 1)*16;
                ldsm_x4(Kh4[g], Baddr);
                ldsm_x4(Kl4[g], Baddr + AT);
            }
            #pragma unroll
            for (int j = 0; j < 8; j++) mma_bf16(s[j], Ah4, &Kh4[j>>1][(j&1)*2]);
            #pragma unroll
            for (int j = 0; j < 8; j++) mma_bf16(s[j], Al4, &Kh4[j>>1][(j&1)*2]);
            #pragma unroll
            for (int j = 0; j < 8; j++) mma_bf16(s[j], Ah4, &Kl4[j>>1][(j&1)*2]);
        }

        // ---- softmax (online) ----
        const float* bp = bias_sm + stage*64;
        float tmax_a = -1e30f, tmax_b = -1e30f;
        #pragma unroll
        for (int j = 0; j < 8; j++) {
            int kk = 8*j + klo;
            float b0 = bp[kk], b1 = bp[kk+1];
            s[j][0] = s[j][0]*scale + b0;  s[j][1] = s[j][1]*scale + b1;
            s[j][2] = s[j][2]*scale + b0;  s[j][3] = s[j][3]*scale + b1;
            if (kt == qt) {
                int kg = kt*64 + kk;
                if (kg   > q_a)   s[j][0] = -1e30f;
                if (kg+1 > q_a)   s[j][1] = -1e30f;
                if (kg   > q_a+8) s[j][2] = -1e30f;
                if (kg+1 > q_a+8) s[j][3] = -1e30f;
            }
            tmax_a = fmaxf(tmax_a, fmaxf(s[j][0], s[j][1]));
            tmax_b = fmaxf(tmax_b, fmaxf(s[j][2], s[j][3]));
        }
        tmax_a = fmaxf(tmax_a, __shfl_xor_sync(0xffffffffu, tmax_a, 1));
        tmax_a = fmaxf(tmax_a, __shfl_xor_sync(0xffffffffu, tmax_a, 2));
        tmax_b = fmaxf(tmax_b, __shfl_xor_sync(0xffffffffu, tmax_b, 1));
        tmax_b = fmaxf(tmax_b, __shfl_xor_sync(0xffffffffu, tmax_b, 2));
        float mn_a = fmaxf(m_a, tmax_a), mn_b = fmaxf(m_b, tmax_b);
        float ca = __expf(m_a - mn_a), cb = __expf(m_b - mn_b);
        m_a = mn_a; m_b = mn_b;
        float sum_a = 0.f, sum_b = 0.f;
        #pragma unroll
        for (int j = 0; j < 8; j++) {
            s[j][0] = __expf(s[j][0] - mn_a);  s[j][1] = __expf(s[j][1] - mn_a);
            s[j][2] = __expf(s[j][2] - mn_b);  s[j][3] = __expf(s[j][3] - mn_b);
            sum_a += s[j][0] + s[j][1];
            sum_b += s[j][2] + s[j][3];
        }
        sum_a += __shfl_xor_sync(0xffffffffu, sum_a, 1);
        sum_a += __shfl_xor_sync(0xffffffffu, sum_a, 2);
        sum_b += __shfl_xor_sync(0xffffffffu, sum_b, 1);
        sum_b += __shfl_xor_sync(0xffffffffu, sum_b, 2);
        l_a = l_a*ca + sum_a;
        l_b = l_b*cb + sum_b;
        #pragma unroll
        for (int j = 0; j < 16; j++) {
            O[j][0] *= ca; O[j][1] *= ca; O[j][2] *= cb; O[j][3] *= cb;
        }

        // ---- PV: (Ph+Pl)(Vh+Vl), drop lo*lo ----
        #pragma unroll
        for (int t = 0; t < 4; t++) {
            uint32_t aH[4], aL[4];
            split_pack(s[2*t][0],   s[2*t][1],   aH[0], aL[0]);
            split_pack(s[2*t][2],   s[2*t][3],   aH[1], aL[1]);
            split_pack(s[2*t+1][0], s[2*t+1][1], aH[2], aL[2]);
            split_pack(s[2*t+1][2], s[2*t+1][3], aH[3], aL[3]);
            #pragma unroll
            for (int g = 0; g < 8; g++) {
                uint32_t Baddr = ss + 2*AT
                               + (t*16 + (lane & 7) + ((lane >> 3) & 1)*8)*AP
                               + g*32 + (lane >> 4)*16;
                uint32_t Vh4[4], Vl4[4];
                ldsm_x4_t(Vh4, Baddr);
                ldsm_x4_t(Vl4, Baddr + AT);
                mma_bf16(O[2*g],   aH, Vh4);     mma_bf16(O[2*g+1], aH, Vh4+2);
                mma_bf16(O[2*g],   aL, Vh4);     mma_bf16(O[2*g+1], aL, Vh4+2);
                mma_bf16(O[2*g],   aH, Vl4);     mma_bf16(O[2*g+1], aH, Vl4+2);
            }
        }
        __syncthreads();
    }

    const float ia = 1.0f / l_a, ib = 1.0f / l_b;
    float* oa = g_ctx + (size_t)(b*SEQ + q0 + wid*16 + (lane >> 2))*EMBED + h*DHEAD + klo;
    float* ob = oa + 8*EMBED;
    #pragma unroll
    for (int j = 0; j < 16; j++) {
        *(float2*)(oa + 8*j) = make_float2(O[j][0]*ia, O[j][1]*ia);
        *(float2*)(ob + 8*j) = make_float2(O[j][2]*ib, O[j][3]*ib);
    }
}

// ---------------- launch ----------------
extern "C" void kernel_launch(void* const* d_in, const int* in_sizes, int n_in,
                              void* d_out, int out_size)
{
    (void)in_sizes; (void)n_in; (void)out_size;
    const float* x    = (const float*)d_in[0];
    const float* mask = (const float*)d_in[1];
    const float* Wq   = (const float*)d_in[2];
    const float* Wk   = (const float*)d_in[3];
    const float* Wv   = (const float*)d_in[4];
    const float* Wo   = (const float*)d_in[5];
    float* out        = (float*)d_out;

    cudaFuncSetAttribute(gemm_mma, cudaFuncAttributeMaxDynamicSharedMemorySize, GEMM_SMEM);
    cudaFuncSetAttribute(attn_mma, cudaFuncAttributeMaxDynamicSharedMemorySize, ATTN_SMEM);

    const int n4x = MTOT*EMBED/4;
    const int n4w = EMBED*EMBED/4;
    const int n4v = BATCH*NHEAD*SEQ*DHEAD/4;

    split_kernel<<<(n4x+255)/256, 256>>>(x, 0, n4x);
    split_kernel<<<(n4w+255)/256, 256>>>(Wq, 1, n4w);
    split_kernel<<<(n4w+255)/256, 256>>>(Wk, 2, n4w);
    split_kernel<<<(n4w+255)/256, 256>>>(Wv, 3, n4w);
    split_kernel<<<(n4w+255)/256, 256>>>(Wo, 4, n4w);

    rope_table<<<(SEQ*64)/256, 256>>>();

    dim3 ggrid(EMBED/128, MTOT/128);
    gemm_mma<<<ggrid, 256, GEMM_SMEM>>>(nullptr, 0);
    gemm_mma<<<ggrid, 256, GEMM_SMEM>>>(nullptr, 1);
    gemm_mma<<<ggrid, 256, GEMM_SMEM>>>(nullptr, 2);

    rope_apply<<<(BATCH*NHEAD*SEQ*64)/256, 256>>>();
    split_kernel<<<(n4v+255)/256, 256>>>(nullptr, 6, n4v);

    attn_mma<<<dim3(SEQ/64, NHEAD, BATCH), 128, ATTN_SMEM>>>(mask);

    split_kernel<<<(n4x+255)/256, 256>>>(nullptr, 5, n4x);
    gemm_mma<<<ggrid, 256, GEMM_SMEM>>>(out, 3);
}

// round 8
// speedup vs baseline: 3.2005x; 1.0102x over previous
#include <cuda_runtime.h>
#include <cuda_bf16.h>
#include <math.h>
#include <stdint.h>

#define EMBED 2048
#define SEQ   2048
#define NHEAD 16
#define DHEAD 128
#define BATCH 2
#define MTOT  (BATCH*SEQ)   // 4096

// ---------------- static device scratch ----------------
__device__ float g_Q[BATCH*NHEAD*SEQ*DHEAD];
__device__ float g_K[BATCH*NHEAD*SEQ*DHEAD];
__device__ __nv_bfloat16 g_xh[MTOT*EMBED];
__device__ __nv_bfloat16 g_xl[MTOT*EMBED];
__device__ __nv_bfloat16 g_Wh[4*EMBED*EMBED];
__device__ __nv_bfloat16 g_Wl[4*EMBED*EMBED];
__device__ __nv_bfloat16 g_ch[MTOT*EMBED];
__device__ __nv_bfloat16 g_cl[MTOT*EMBED];
__device__ __nv_bfloat16 g_Qh[BATCH*NHEAD*SEQ*DHEAD];
__device__ __nv_bfloat16 g_Ql[BATCH*NHEAD*SEQ*DHEAD];
__device__ __nv_bfloat16 g_Kh[BATCH*NHEAD*SEQ*DHEAD];
__device__ __nv_bfloat16 g_Kl[BATCH*NHEAD*SEQ*DHEAD];
__device__ __nv_bfloat16 g_Vh[BATCH*NHEAD*SEQ*DHEAD];
__device__ __nv_bfloat16 g_Vl[BATCH*NHEAD*SEQ*DHEAD];
__device__ float g_rsin[SEQ*64];
__device__ float g_rcos[SEQ*64];

// ---------------- baseline-PTX helpers ----------------
__device__ __forceinline__ uint32_t smem_to_u32(const void* p) {
    uint32_t a;
    asm("{ .reg .u64 t; cvta.to.shared.u64 t, %1; cvt.u32.u64 %0, t; }" : "=r"(a) : "l"(p));
    return a;
}
#define CP_ASYNC16(saddr, gptr) \
    asm volatile("cp.async.cg.shared.global [%0], [%1], 16;" :: "r"(saddr), "l"(gptr) : "memory")
#define CP_COMMIT() asm volatile("cp.async.commit_group;" ::: "memory")
#define CP_WAIT1()  asm volatile("cp.async.wait_group 1;" ::: "memory")
#define CP_WAIT0()  asm volatile("cp.async.wait_group 0;" ::: "memory")

__device__ __forceinline__ void ldsm_x4(uint32_t* r, uint32_t addr) {
    asm volatile("ldmatrix.sync.aligned.m8n8.x4.shared.b16 {%0,%1,%2,%3}, [%4];"
                 : "=r"(r[0]), "=r"(r[1]), "=r"(r[2]), "=r"(r[3]) : "r"(addr));
}
__device__ __forceinline__ void ldsm_x4_t(uint32_t* r, uint32_t addr) {
    asm volatile("ldmatrix.sync.aligned.m8n8.x4.trans.shared.b16 {%0,%1,%2,%3}, [%4];"
                 : "=r"(r[0]), "=r"(r[1]), "=r"(r[2]), "=r"(r[3]) : "r"(addr));
}
__device__ __forceinline__ void mma_bf16(float* c, const uint32_t* a, const uint32_t* b) {
    asm volatile("mma.sync.aligned.m16n8k16.row.col.f32.bf16.bf16.f32 "
                 "{%0,%1,%2,%3}, {%4,%5,%6,%7}, {%8,%9}, {%0,%1,%2,%3};"
                 : "+f"(c[0]), "+f"(c[1]), "+f"(c[2]), "+f"(c[3])
                 : "r"(a[0]), "r"(a[1]), "r"(a[2]), "r"(a[3]), "r"(b[0]), "r"(b[1]));
}
__device__ __forceinline__ void split_pack(float x, float y, uint32_t& hi, uint32_t& lo) {
    __nv_bfloat16 hx = __float2bfloat16(x), hy = __float2bfloat16(y);
    hi = ((uint32_t)__bfloat16_as_ushort(hy) << 16) | __bfloat16_as_ushort(hx);
    __nv_bfloat16 lx = __float2bfloat16(x - __bfloat162float(hx));
    __nv_bfloat16 ly = __float2bfloat16(y - __bfloat162float(hy));
    lo = ((uint32_t)__bfloat16_as_ushort(ly) << 16) | __bfloat16_as_ushort(lx);
}

// ---------------- split: f32 -> bf16 hi + bf16 lo ----------------
// which: 0=x, 1..4=Wq/Wk/Wv/Wo
__global__ void __launch_bounds__(256) split_kernel(const float* __restrict__ src,
                                                    int which, int n4)
{
    int idx = blockIdx.x * 256 + threadIdx.x;
    if (idx >= n4) return;
    __nv_bfloat16 *hi, *lo;
    if (which == 0) { hi = g_xh; lo = g_xl; }
    else            { size_t off = (size_t)(which - 1) * EMBED * EMBED;
                      hi = g_Wh + off; lo = g_Wl + off; }

    float4 v = ((const float4*)src)[idx];
    float f[4] = {v.x, v.y, v.z, v.w};
    __nv_bfloat16 h[4], l[4];
    #pragma unroll
    for (int j = 0; j < 4; j++) {
        h[j] = __float2bfloat16(f[j]);
        float r = f[j] - __bfloat162float(h[j]);
        l[j] = __float2bfloat16(r);
    }
    __nv_bfloat162* hp = (__nv_bfloat162*)hi;
    __nv_bfloat162* lp = (__nv_bfloat162*)lo;
    hp[idx*2]   = __nv_bfloat162(h[0], h[1]);
    hp[idx*2+1] = __nv_bfloat162(h[2], h[3]);
    lp[idx*2]   = __nv_bfloat162(l[0], l[1]);
    lp[idx*2+1] = __nv_bfloat162(l[2], l[3]);
}

// ---------------- mma.sync bf16 split GEMM (mainloop validated R5/R6) ----------
// mode 0: x->g_Q(f32)  mode 1: x->g_K(f32)  mode 2: x->g_Vh/g_Vl(bf16 split)
// mode 3: ctx(ch/cl)->Cout(f32)
#define GT_PITCH 80
#define GT_TILE  (128*GT_PITCH)
#define GT_STAGE (4*GT_TILE)
#define GEMM_SMEM (2*GT_STAGE)

__global__ void __launch_bounds__(256) gemm_mma(float* __restrict__ Cout, int mode)
{
    extern __shared__ char smc[];
    const uint32_t sbase = smem_to_u32(smc);
    const int tid  = threadIdx.x;
    const int lane = tid & 31;
    const int wid  = tid >> 5;
    const int warp_m = wid >> 2;
    const int warp_n = wid & 3;
    const int n0 = blockIdx.x * 128;
    const int m0 = blockIdx.y * 128;

    const __nv_bfloat16* srcs[4];
    srcs[0] = ((mode == 3) ? g_ch : g_xh);
    srcs[1] = ((mode == 3) ? g_cl : g_xl);
    srcs[2] = g_Wh + (size_t)mode * EMBED * EMBED;
    srcs[3] = g_Wl + (size_t)mode * EMBED * EMBED;
    const int base_row[4] = {m0, m0, n0, n0};

    const int l_row0 = tid >> 2;
    const int l_seg0 = tid & 3;
    const int l_row1 = (tid + 256) >> 2;
    const int l_seg1 = tid & 3;

    const uint32_t a_off = (uint32_t)((warp_m*64 + (lane & 15)) * GT_PITCH + (lane >> 4) * 16);
    const uint32_t b_off = (uint32_t)(((lane & 7) + (lane >> 4) * 8 + warp_n*32) * GT_PITCH
                                      + ((lane >> 3) & 1) * 16);

    float acc[4][4][4];
    #pragma unroll
    for (int i = 0; i < 4; i++)
        #pragma unroll
        for (int j = 0; j < 4; j++)
            #pragma unroll
            for (int r = 0; r < 4; r++) acc[i][j][r] = 0.f;

    {
        const uint32_t sb = sbase;
        #pragma unroll
        for (int t = 0; t < 4; t++) {
            const __nv_bfloat16* g0 = srcs[t] + (size_t)(base_row[t] + l_row0) * EMBED + l_seg0*8;
            const __nv_bfloat16* g1 = srcs[t] + (size_t)(base_row[t] + l_row1) * EMBED + l_seg1*8;
            CP_ASYNC16(sb + t*GT_TILE + l_row0*GT_PITCH + l_seg0*16, g0);
            CP_ASYNC16(sb + t*GT_TILE + l_row1*GT_PITCH + l_seg1*16, g1);
        }
        CP_COMMIT();
    }

    for (int s = 0; s < EMBED/32; s++) {
        if (s < EMBED/32 - 1) {
            const uint32_t sb = sbase + ((s+1) & 1) * GT_STAGE;
            const int k0 = (s+1) * 32;
            #pragma unroll
            for (int t = 0; t < 4; t++) {
                const __nv_bfloat16* g0 = srcs[t] + (size_t)(base_row[t] + l_row0) * EMBED + k0 + l_seg0*8;
                const __nv_bfloat16* g1 = srcs[t] + (size_t)(base_row[t] + l_row1) * EMBED + k0 + l_seg1*8;
                CP_ASYNC16(sb + t*GT_TILE + l_row0*GT_PITCH + l_seg0*16, g0);
                CP_ASYNC16(sb + t*GT_TILE + l_row1*GT_PITCH + l_seg1*16, g1);
            }
        }
        CP_COMMIT();
        CP_WAIT1();
        __syncthreads();

        const uint32_t sb = sbase + (s & 1) * GT_STAGE;
        #pragma unroll
        for (int kk = 0; kk < 2; kk++) {
            const uint32_t ko = kk * 32;
            uint32_t Af[4][4], Lf[4][4], Bf[2][4];
            #pragma unroll
            for (int ma = 0; ma < 4; ma++)
                ldsm_x4(Af[ma], sb + 0*GT_TILE + a_off + ko + ma*16*GT_PITCH);
            #pragma unroll
            for (int nb = 0; nb < 2; nb++)
                ldsm_x4(Bf[nb], sb + 2*GT_TILE + b_off + ko + nb*16*GT_PITCH);
            #pragma unroll
            for (int ma = 0; ma < 4; ma++)
                #pragma unroll
                for (int na = 0; na < 4; na++)
                    mma_bf16(acc[ma][na], Af[ma], &Bf[na >> 1][(na & 1) * 2]);
            #pragma unroll
            for (int ma = 0; ma < 4; ma++)
                ldsm_x4(Lf[ma], sb + 1*GT_TILE + a_off + ko + ma*16*GT_PITCH);
            #pragma unroll
            for (int ma = 0; ma < 4; ma++)
                #pragma unroll
                for (int na = 0; na < 4; na++)
                    mma_bf16(acc[ma][na], Lf[ma], &Bf[na >> 1][(na & 1) * 2]);
            #pragma unroll
            for (int nb = 0; nb < 2; nb++)
                ldsm_x4(Bf[nb], sb + 3*GT_TILE + b_off + ko + nb*16*GT_PITCH);
            #pragma unroll
            for (int ma = 0; ma < 4; ma++)
                #pragma unroll
                for (int na = 0; na < 4; na++)
                    mma_bf16(acc[ma][na], Af[ma], &Bf[na >> 1][(na & 1) * 2]);
        }
        __syncthreads();
    }

    const int r0 = lane >> 2;
    const int c0 = (lane & 3) * 2;
    #pragma unroll
    for (int ma = 0; ma < 4; ma++) {
        #pragma unroll
        for (int na = 0; na < 4; na++) {
            const int coln = warp_n*32 + na*8 + c0;
            #pragma unroll
            for (int half = 0; half < 2; half++) {
                const int m = m0 + warp_m*64 + ma*16 + r0 + half*8;
                float2 val = make_float2(acc[ma][na][half*2], acc[ma][na][half*2+1]);
                if (mode <= 1) {
                    float* base = (mode == 0) ? g_Q : g_K;
                    const int b = m >> 11, ss = m & (SEQ - 1);
                    *(float2*)(base + ((size_t)((b*NHEAD + blockIdx.x)*SEQ + ss))*DHEAD + coln) = val;
                } else if (mode == 2) {
                    const int b = m >> 11, ss = m & (SEQ - 1);
                    size_t off = ((size_t)((b*NHEAD + blockIdx.x)*SEQ + ss))*DHEAD + coln;
                    uint32_t hi, lo;
                    split_pack(val.x, val.y, hi, lo);
                    *(uint32_t*)(g_Vh + off) = hi;
                    *(uint32_t*)(g_Vl + off) = lo;
                } else {
                    *(float2*)(Cout + (size_t)m * EMBED + n0 + coln) = val;
                }
            }
        }
    }
}

// ---------------- RoPE table + apply (emits bf16 hi/lo) ----------------
__global__ void __launch_bounds__(256) rope_table()
{
    int idx = blockIdx.x * 256 + threadIdx.x;
    int i = idx & 63, s = idx >> 6;
    float freq = (float)pow(10000.0, -(double)i / 64.0);
    float ang  = (float)s * freq;
    double sn, cs;
    sincos((double)ang, &sn, &cs);
    g_rsin[idx] = (float)sn;
    g_rcos[idx] = (float)cs;
}

__global__ void __launch_bounds__(256) rope_apply()
{
    int idx = blockIdx.x * 256 + threadIdx.x;
    int i = idx & 63;
    int s = (idx >> 6) & (SEQ - 1);
    size_t base = ((size_t)(idx >> 6)) * DHEAD;
    float sn = g_rsin[s*64 + i], cs = g_rcos[s*64 + i];

    float q1 = g_Q[base + i], q2 = g_Q[base + i + 64];
    float k1 = g_K[base + i], k2 = g_K[base + i + 64];
    float qa = q1*cs - q2*sn, qb = q2*cs + q1*sn;
    float ka = k1*cs - k2*sn, kb = k2*cs + k1*sn;

    __nv_bfloat16 h;
    h = __float2bfloat16(qa); g_Qh[base+i]    = h; g_Ql[base+i]    = __float2bfloat16(qa - __bfloat162float(h));
    h = __float2bfloat16(qb); g_Qh[base+i+64] = h; g_Ql[base+i+64] = __float2bfloat16(qb - __bfloat162float(h));
    h = __float2bfloat16(ka); g_Kh[base+i]    = h; g_Kl[base+i]    = __float2bfloat16(ka - __bfloat162float(h));
    h = __float2bfloat16(kb); g_Kh[base+i+64] = h; g_Kl[base+i+64] = __float2bfloat16(kb - __bfloat162float(h));
}

// ---------------- FA2-style bf16 mma attention v2 ----------------
// BR=128 queries/CTA, BC=64 keys/tile, 256 threads / 8 warps (16 q-rows each).
// Qh fragments in registers (staged through KV stage-0 smem), Ql resident in smem.
// Output written directly as bf16 hi/lo ctx (g_ch/g_cl).
#define AP2    272
#define ATILE  (64*AP2)           // 17408
#define AST2   (4*ATILE)          // 69632 per KV stage (Kh,Kl,Vh,Vl)
#define QLOFF  (2*AST2)           // 139264: Ql tile 128x272 = 34816
#define ABIAS2 (QLOFF + 128*AP2)  // 174080
#define ATTN_SMEM (ABIAS2 + 512)  // 174592

__device__ __forceinline__ void attn_pf(uint32_t sb_stage,
    const __nv_bfloat16* Kh, const __nv_bfloat16* Kl,
    const __nv_bfloat16* Vh, const __nv_bfloat16* Vl, int k0, int tid)
{
    #pragma unroll
    for (int i = 0; i < 4; i++) {
        int idx = tid + i*256;           // 0..1023
        int r = idx >> 4, c = idx & 15;
        uint32_t so = sb_stage + r*AP2 + c*16;
        size_t go = (size_t)(k0 + r) * DHEAD;
        CP_ASYNC16(so,            (const char*)(Kh + go) + c*16);
        CP_ASYNC16(so + ATILE,    (const char*)(Kl + go) + c*16);
        CP_ASYNC16(so + 2*ATILE,  (const char*)(Vh + go) + c*16);
        CP_ASYNC16(so + 3*ATILE,  (const char*)(Vl + go) + c*16);
    }
}

__global__ void __launch_bounds__(256) attn_mma(const float* __restrict__ mask)
{
    extern __shared__ char smc[];
    const uint32_t sb = smem_to_u32(smc);
    const int tid = threadIdx.x, lane = tid & 31, wid = tid >> 5;
    const int qt = blockIdx.x, h = blockIdx.y, b = blockIdx.z;
    const int q0 = qt * 128;
    const size_t hb = (size_t)(b*NHEAD + h) * SEQ * DHEAD;
    const __nv_bfloat16 *Qhp = g_Qh + hb, *Qlp = g_Ql + hb;
    const __nv_bfloat16 *Khp = g_Kh + hb, *Klp = g_Kl + hb;
    const __nv_bfloat16 *Vhp = g_Vh + hb, *Vlp = g_Vl + hb;
    float* bias_sm = (float*)(smc + ABIAS2);

    // ---- stage Q: Qh via stage-0 KV area (reclaimed), Ql persistent ----
    #pragma unroll
    for (int i = 0; i < 8; i++) {
        int idx = tid + i*256;           // 0..2047
        int r = idx >> 4, c = idx & 15;
        size_t go = (size_t)(q0 + r) * DHEAD;
        CP_ASYNC16(sb + r*AP2 + c*16,         (const char*)(Qhp + go) + c*16);
        CP_ASYNC16(sb + QLOFF + r*AP2 + c*16, (const char*)(Qlp + go) + c*16);
    }
    CP_COMMIT();
    CP_WAIT0();
    __syncthreads();

    const uint32_t qa_off = (uint32_t)((wid*16 + (lane & 15))*AP2 + (lane >> 4)*16);
    uint32_t Qf[8][4];
    #pragma unroll
    for (int t = 0; t < 8; t++) ldsm_x4(Qf[t], sb + qa_off + t*32);
    __syncthreads();                     // stage-0 area free for KV now

    attn_pf(sb, Khp, Klp, Vhp, Vlp, 0, tid);
    if (tid < 64) bias_sm[tid] = (1.0f - mask[b*SEQ + tid]) * -1e9f;
    CP_COMMIT();

    float O[16][4];
    #pragma unroll
    for (int j = 0; j < 16; j++)
        #pragma unroll
        for (int r = 0; r < 4; r++) O[j][r] = 0.f;
    float m_a = -1e30f, m_b = -1e30f, l_a = 0.f, l_b = 0.f;
    const float scale = 0.08838834764831845f;
    const int q_a = q0 + wid*16 + (lane >> 2);
    const int klo = 2*(lane & 3);
    const int nkt = 2*qt + 2;

    for (int kt = 0; kt < nkt; kt++) {
        const int stage = kt & 1;
        if (kt + 1 < nkt) {
            attn_pf(sb + (stage^1)*AST2, Khp, Klp, Vhp, Vlp, (kt+1)*64, tid);
            if (tid < 64) bias_sm[(stage^1)*64 + tid] = (1.0f - mask[b*SEQ + (kt+1)*64 + tid]) * -1e9f;
        }
        CP_COMMIT();
        CP_WAIT1();
        __syncthreads();

        const uint32_t ss = sb + stage*AST2;
        float s[8][4];
        #pragma unroll
        for (int j = 0; j < 8; j++)
            #pragma unroll
            for (int r = 0; r < 4; r++) s[j][r] = 0.f;

        // ---- scores: (Qh+Ql)(Kh+Kl)^T, drop lo*lo ----
        #pragma unroll
        for (int t = 0; t < 8; t++) {
            uint32_t Al4[4];
            ldsm_x4(Al4, sb + QLOFF + qa_off + t*32);
            uint32_t Kh4[4][4], Kl4[4][4];
            #pragma unroll
            for (int g = 0; g < 4; g++) {
                uint32_t Baddr = ss + (g*16 + (lane & 7) + ((lane >> 4) << 3))*AP2
                               + t*32 + ((lane >> 3) & 1)*16;
                ldsm_x4(Kh4[g], Baddr);
                ldsm_x4(Kl4[g], Baddr + ATILE);
            }
            #pragma unroll
            for (int j = 0; j < 8; j++) mma_bf16(s[j], Qf[t], &Kh4[j>>1][(j&1)*2]);
            #pragma unroll
            for (int j = 0; j < 8; j++) mma_bf16(s[j], Al4,   &Kh4[j>>1][(j&1)*2]);
            #pragma unroll
            for (int j = 0; j < 8; j++) mma_bf16(s[j], Qf[t], &Kl4[j>>1][(j&1)*2]);
        }

        // ---- online softmax ----
        const float* bp = bias_sm + stage*64;
        const bool diag = (kt >= 2*qt);
        float tmax_a = -1e30f, tmax_b = -1e30f;
        #pragma unroll
        for (int j = 0; j < 8; j++) {
            int kk = 8*j + klo;
            float b0 = bp[kk], b1 = bp[kk+1];
            s[j][0] = s[j][0]*scale + b0;  s[j][1] = s[j][1]*scale + b1;
            s[j][2] = s[j][2]*scale + b0;  s[j][3] = s[j][3]*scale + b1;
            if (diag) {
                int kg = kt*64 + kk;
                if (kg   > q_a)   s[j][0] = -1e30f;
                if (kg+1 > q_a)   s[j][1] = -1e30f;
                if (kg   > q_a+8) s[j][2] = -1e30f;
                if (kg+1 > q_a+8) s[j][3] = -1e30f;
            }
            tmax_a = fmaxf(tmax_a, fmaxf(s[j][0], s[j][1]));
            tmax_b = fmaxf(tmax_b, fmaxf(s[j][2], s[j][3]));
        }
        tmax_a = fmaxf(tmax_a, __shfl_xor_sync(0xffffffffu, tmax_a, 1));
        tmax_a = fmaxf(tmax_a, __shfl_xor_sync(0xffffffffu, tmax_a, 2));
        tmax_b = fmaxf(tmax_b, __shfl_xor_sync(0xffffffffu, tmax_b, 1));
        tmax_b = fmaxf(tmax_b, __shfl_xor_sync(0xffffffffu, tmax_b, 2));
        float mn_a = fmaxf(m_a, tmax_a), mn_b = fmaxf(m_b, tmax_b);
        float ca = __expf(m_a - mn_a), cb = __expf(m_b - mn_b);
        m_a = mn_a; m_b = mn_b;
        float sum_a = 0.f, sum_b = 0.f;
        #pragma unroll
        for (int j = 0; j < 8; j++) {
            s[j][0] = __expf(s[j][0] - mn_a);  s[j][1] = __expf(s[j][1] - mn_a);
            s[j][2] = __expf(s[j][2] - mn_b);  s[j][3] = __expf(s[j][3] - mn_b);
            sum_a += s[j][0] + s[j][1];
            sum_b += s[j][2] + s[j][3];
        }
        sum_a += __shfl_xor_sync(0xffffffffu, sum_a, 1);
        sum_a += __shfl_xor_sync(0xffffffffu, sum_a, 2);
        sum_b += __shfl_xor_sync(0xffffffffu, sum_b, 1);
        sum_b += __shfl_xor_sync(0xffffffffu, sum_b, 2);
        l_a = l_a*ca + sum_a;
        l_b = l_b*cb + sum_b;
        #pragma unroll
        for (int j = 0; j < 16; j++) {
            O[j][0] *= ca; O[j][1] *= ca; O[j][2] *= cb; O[j][3] *= cb;
        }

        // ---- PV: (Ph+Pl)(Vh+Vl), drop lo*lo ----
        #pragma unroll
        for (int t = 0; t < 4; t++) {
            uint32_t aH[4], aL[4];
            split_pack(s[2*t][0],   s[2*t][1],   aH[0], aL[0]);
            split_pack(s[2*t][2],   s[2*t][3],   aH[1], aL[1]);
            split_pack(s[2*t+1][0], s[2*t+1][1], aH[2], aL[2]);
            split_pack(s[2*t+1][2], s[2*t+1][3], aH[3], aL[3]);
            #pragma unroll
            for (int g = 0; g < 8; g++) {
                uint32_t Baddr = ss + 2*ATILE
                               + (t*16 + (lane & 7) + ((lane >> 3) & 1)*8)*AP2
                               + g*32 + (lane >> 4)*16;
                uint32_t Vh4[4], Vl4[4];
                ldsm_x4_t(Vh4, Baddr);
                ldsm_x4_t(Vl4, Baddr + ATILE);
                mma_bf16(O[2*g],   aH, Vh4);     mma_bf16(O[2*g+1], aH, Vh4+2);
                mma_bf16(O[2*g],   aL, Vh4);     mma_bf16(O[2*g+1], aL, Vh4+2);
                mma_bf16(O[2*g],   aH, Vl4);     mma_bf16(O[2*g+1], aH, Vl4+2);
            }
        }
        __syncthreads();
    }

    // ---- epilogue: write bf16 hi/lo ctx directly ----
    const float ia = 1.0f / l_a, ib = 1.0f / l_b;
    const size_t ra = (size_t)(b*SEQ + q0 + wid*16 + (lane >> 2));
    const size_t oa = ra*EMBED + h*DHEAD + klo;
    const size_t ob = oa + 8*(size_t)EMBED;
    #pragma unroll
    for (int j = 0; j < 16; j++) {
        uint32_t hi, lo;
        split_pack(O[j][0]*ia, O[j][1]*ia, hi, lo);
        *(uint32_t*)(g_ch + oa + 8*j) = hi;
        *(uint32_t*)(g_cl + oa + 8*j) = lo;
        split_pack(O[j][2]*ib, O[j][3]*ib, hi, lo);
        *(uint32_t*)(g_ch + ob + 8*j) = hi;
        *(uint32_t*)(g_cl + ob + 8*j) = lo;
    }
}

// ---------------- launch ----------------
extern "C" void kernel_launch(void* const* d_in, const int* in_sizes, int n_in,
                              void* d_out, int out_size)
{
    (void)in_sizes; (void)n_in; (void)out_size;
    const float* x    = (const float*)d_in[0];
    const float* mask = (const float*)d_in[1];
    const float* Wq   = (const float*)d_in[2];
    const float* Wk   = (const float*)d_in[3];
    const float* Wv   = (const float*)d_in[4];
    const float* Wo   = (const float*)d_in[5];
    float* out        = (float*)d_out;

    cudaFuncSetAttribute(gemm_mma, cudaFuncAttributeMaxDynamicSharedMemorySize, GEMM_SMEM);
    cudaFuncSetAttribute(attn_mma, cudaFuncAttributeMaxDynamicSharedMemorySize, ATTN_SMEM);

    const int n4x = MTOT*EMBED/4;
    const int n4w = EMBED*EMBED/4;

    split_kernel<<<(n4x+255)/256, 256>>>(x, 0, n4x);
    split_kernel<<<(n4w+255)/256, 256>>>(Wq, 1, n4w);
    split_kernel<<<(n4w+255)/256, 256>>>(Wk, 2, n4w);
    split_kernel<<<(n4w+255)/256, 256>>>(Wv, 3, n4w);
    split_kernel<<<(n4w+255)/256, 256>>>(Wo, 4, n4w);

    rope_table<<<(SEQ*64)/256, 256>>>();

    dim3 ggrid(EMBED/128, MTOT/128);
    gemm_mma<<<ggrid, 256, GEMM_SMEM>>>(nullptr, 0);
    gemm_mma<<<ggrid, 256, GEMM_SMEM>>>(nullptr, 1);
    gemm_mma<<<ggrid, 256, GEMM_SMEM>>>(nullptr, 2);

    rope_apply<<<(BATCH*NHEAD*SEQ*64)/256, 256>>>();

    attn_mma<<<dim3(SEQ/128, NHEAD, BATCH), 256, ATTN_SMEM>>>(mask);

    gemm_mma<<<ggrid, 256, GEMM_SMEM>>>(out, 3);
}

// round 9
// speedup vs baseline: 3.4370x; 1.0739x over previous
#include <cuda_runtime.h>
#include <cuda_bf16.h>
#include <math.h>
#include <stdint.h>

#define EMBED 2048
#define SEQ   2048
#define NHEAD 16
#define DHEAD 128
#define BATCH 2
#define MTOT  (BATCH*SEQ)   // 4096

// ---------------- static device scratch ----------------
__device__ __nv_bfloat16 g_xh[MTOT*EMBED];
__device__ __nv_bfloat16 g_xl[MTOT*EMBED];
__device__ __nv_bfloat16 g_Wh[4*EMBED*EMBED];
__device__ __nv_bfloat16 g_Wl[4*EMBED*EMBED];
__device__ __nv_bfloat16 g_ch[MTOT*EMBED];
__device__ __nv_bfloat16 g_cl[MTOT*EMBED];
__device__ __nv_bfloat16 g_Qh[BATCH*NHEAD*SEQ*DHEAD];
__device__ __nv_bfloat16 g_Ql[BATCH*NHEAD*SEQ*DHEAD];
__device__ __nv_bfloat16 g_Kh[BATCH*NHEAD*SEQ*DHEAD];
__device__ __nv_bfloat16 g_Kl[BATCH*NHEAD*SEQ*DHEAD];
__device__ __nv_bfloat16 g_Vh[BATCH*NHEAD*SEQ*DHEAD];
__device__ __nv_bfloat16 g_Vl[BATCH*NHEAD*SEQ*DHEAD];
__device__ float g_rsin[SEQ*64];
__device__ float g_rcos[SEQ*64];

// ---------------- baseline-PTX helpers ----------------
__device__ __forceinline__ uint32_t smem_to_u32(const void* p) {
    uint32_t a;
    asm("{ .reg .u64 t; cvta.to.shared.u64 t, %1; cvt.u32.u64 %0, t; }" : "=r"(a) : "l"(p));
    return a;
}
#define CP_ASYNC16(saddr, gptr) \
    asm volatile("cp.async.cg.shared.global [%0], [%1], 16;" :: "r"(saddr), "l"(gptr) : "memory")
#define CP_COMMIT() asm volatile("cp.async.commit_group;" ::: "memory")
#define CP_WAIT1()  asm volatile("cp.async.wait_group 1;" ::: "memory")
#define CP_WAIT0()  asm volatile("cp.async.wait_group 0;" ::: "memory")

__device__ __forceinline__ void ldsm_x4(uint32_t* r, uint32_t addr) {
    asm volatile("ldmatrix.sync.aligned.m8n8.x4.shared.b16 {%0,%1,%2,%3}, [%4];"
                 : "=r"(r[0]), "=r"(r[1]), "=r"(r[2]), "=r"(r[3]) : "r"(addr));
}
__device__ __forceinline__ void ldsm_x4_t(uint32_t* r, uint32_t addr) {
    asm volatile("ldmatrix.sync.aligned.m8n8.x4.trans.shared.b16 {%0,%1,%2,%3}, [%4];"
                 : "=r"(r[0]), "=r"(r[1]), "=r"(r[2]), "=r"(r[3]) : "r"(addr));
}
__device__ __forceinline__ void mma_bf16(float* c, const uint32_t* a, const uint32_t* b) {
    asm volatile("mma.sync.aligned.m16n8k16.row.col.f32.bf16.bf16.f32 "
                 "{%0,%1,%2,%3}, {%4,%5,%6,%7}, {%8,%9}, {%0,%1,%2,%3};"
                 : "+f"(c[0]), "+f"(c[1]), "+f"(c[2]), "+f"(c[3])
                 : "r"(a[0]), "r"(a[1]), "r"(a[2]), "r"(a[3]), "r"(b[0]), "r"(b[1]));
}
__device__ __forceinline__ void split_pack(float x, float y, uint32_t& hi, uint32_t& lo) {
    __nv_bfloat16 hx = __float2bfloat16(x), hy = __float2bfloat16(y);
    hi = ((uint32_t)__bfloat16_as_ushort(hy) << 16) | __bfloat16_as_ushort(hx);
    __nv_bfloat16 lx = __float2bfloat16(x - __bfloat162float(hx));
    __nv_bfloat16 ly = __float2bfloat16(y - __bfloat162float(hy));
    lo = ((uint32_t)__bfloat16_as_ushort(ly) << 16) | __bfloat16_as_ushort(lx);
}

// ---------------- split: f32 -> bf16 hi + bf16 lo ----------------
// which: 0=x, 1..4=Wq/Wk/Wv/Wo
__global__ void __launch_bounds__(256) split_kernel(const float* __restrict__ src,
                                                    int which, int n4)
{
    int idx = blockIdx.x * 256 + threadIdx.x;
    if (idx >= n4) return;
    __nv_bfloat16 *hi, *lo;
    if (which == 0) { hi = g_xh; lo = g_xl; }
    else            { size_t off = (size_t)(which - 1) * EMBED * EMBED;
                      hi = g_Wh + off; lo = g_Wl + off; }

    float4 v = ((const float4*)src)[idx];
    float f[4] = {v.x, v.y, v.z, v.w};
    __nv_bfloat16 h[4], l[4];
    #pragma unroll
    for (int j = 0; j < 4; j++) {
        h[j] = __float2bfloat16(f[j]);
        float r = f[j] - __bfloat162float(h[j]);
        l[j] = __float2bfloat16(r);
    }
    __nv_bfloat162* hp = (__nv_bfloat162*)hi;
    __nv_bfloat162* lp = (__nv_bfloat162*)lo;
    hp[idx*2]   = __nv_bfloat162(h[0], h[1]);
    hp[idx*2+1] = __nv_bfloat162(h[2], h[3]);
    lp[idx*2]   = __nv_bfloat162(l[0], l[1]);
    lp[idx*2+1] = __nv_bfloat162(l[2], l[3]);
}

// ---------------- RoPE table ----------------
__global__ void __launch_bounds__(256) rope_table()
{
    int idx = blockIdx.x * 256 + threadIdx.x;
    int i = idx & 63, s = idx >> 6;
    float freq = (float)pow(10000.0, -(double)i / 64.0);
    float ang  = (float)s * freq;
    double sn, cs;
    sincos((double)ang, &sn, &cs);
    g_rsin[idx] = (float)sn;
    g_rcos[idx] = (float)cs;
}

// ---------------- mma.sync bf16 split GEMM v2: 4 warps, warp tile 64x64 --------
// mode 0: x->g_Qh/g_Ql (RoPE fused)   mode 1: x->g_Kh/g_Kl (RoPE fused)
// mode 2: x->g_Vh/g_Vl                mode 3: ctx(ch/cl)->Cout (f32)
#define GT_PITCH 80
#define GT_TILE  (128*GT_PITCH)      // 10240
#define GT_STAGE (4*GT_TILE)         // 40960
#define GEMM_SMEM (2*GT_STAGE)       // 81920
#define CS_PITCH 134                 // fp32 epilogue tile pitch (floats)

__global__ void __launch_bounds__(128) gemm_mma(float* __restrict__ Cout, int mode)
{
    extern __shared__ char smc[];
    const uint32_t sbase = smem_to_u32(smc);
    const int tid  = threadIdx.x;
    const int lane = tid & 31;
    const int wid  = tid >> 5;
    const int warp_m = wid >> 1;          // 0..1
    const int warp_n = wid & 1;           // 0..1
    const int n0 = blockIdx.x * 128;
    const int m0 = blockIdx.y * 128;

    const __nv_bfloat16* srcs[4];
    srcs[0] = ((mode == 3) ? g_ch : g_xh);
    srcs[1] = ((mode == 3) ? g_cl : g_xl);
    srcs[2] = g_Wh + (size_t)mode * EMBED * EMBED;
    srcs[3] = g_Wl + (size_t)mode * EMBED * EMBED;
    const int base_row[4] = {m0, m0, n0, n0};

    const int seg = tid & 3;              // 16B chunk within 64B row
    const int rb  = tid >> 2;             // base row, +32 per i

    const uint32_t a_off = (uint32_t)((warp_m*64 + (lane & 15)) * GT_PITCH + (lane >> 4) * 16);
    const uint32_t b_off = (uint32_t)(((lane & 7) + (lane >> 4) * 8 + warp_n*64) * GT_PITCH
                                      + ((lane >> 3) & 1) * 16);

    float acc[4][8][4];
    #pragma unroll
    for (int i = 0; i < 4; i++)
        #pragma unroll
        for (int j = 0; j < 8; j++)
            #pragma unroll
            for (int r = 0; r < 4; r++) acc[i][j][r] = 0.f;

    // ---- prefetch stage 0 ----
    #pragma unroll
    for (int t = 0; t < 4; t++)
        #pragma unroll
        for (int i = 0; i < 4; i++) {
            int row = rb + i*32;
            const __nv_bfloat16* g = srcs[t] + (size_t)(base_row[t] + row) * EMBED + seg*8;
            CP_ASYNC16(sbase + t*GT_TILE + row*GT_PITCH + seg*16, g);
        }
    CP_COMMIT();

    for (int s = 0; s < EMBED/32; s++) {
        if (s < EMBED/32 - 1) {
            const uint32_t sb = sbase + ((s+1) & 1) * GT_STAGE;
            const int k0 = (s+1) * 32;
            #pragma unroll
            for (int t = 0; t < 4; t++)
                #pragma unroll
                for (int i = 0; i < 4; i++) {
                    int row = rb + i*32;
                    const __nv_bfloat16* g = srcs[t] + (size_t)(base_row[t] + row) * EMBED + k0 + seg*8;
                    CP_ASYNC16(sb + t*GT_TILE + row*GT_PITCH + seg*16, g);
                }
        }
        CP_COMMIT();
        CP_WAIT1();
        __syncthreads();

        const uint32_t sb = sbase + (s & 1) * GT_STAGE;
        #pragma unroll
        for (int kk = 0; kk < 2; kk++) {
            const uint32_t ko = kk * 32;
            uint32_t Af[4][4], Lf[4][4], Bf[4][4];
            // hi x hi
            #pragma unroll
            for (int ma = 0; ma < 4; ma++)
                ldsm_x4(Af[ma], sb + 0*GT_TILE + a_off + ko + ma*16*GT_PITCH);
            #pragma unroll
            for (int g = 0; g < 4; g++)
                ldsm_x4(Bf[g], sb + 2*GT_TILE + b_off + ko + g*16*GT_PITCH);
            #pragma unroll
            for (int ma = 0; ma < 4; ma++)
                #pragma unroll
                for (int na = 0; na < 8; na++)
                    mma_bf16(acc[ma][na], Af[ma], &Bf[na >> 1][(na & 1) * 2]);
            // lo x hi
            #pragma unroll
            for (int ma = 0; ma < 4; ma++)
                ldsm_x4(Lf[ma], sb + 1*GT_TILE + a_off + ko + ma*16*GT_PITCH);
            #pragma unroll
            for (int ma = 0; ma < 4; ma++)
                #pragma unroll
                for (int na = 0; na < 8; na++)
                    mma_bf16(acc[ma][na], Lf[ma], &Bf[na >> 1][(na & 1) * 2]);
            // hi x lo (overwrite Bf with Wl)
            #pragma unroll
            for (int g = 0; g < 4; g++)
                ldsm_x4(Bf[g], sb + 3*GT_TILE + b_off + ko + g*16*GT_PITCH);
            #pragma unroll
            for (int ma = 0; ma < 4; ma++)
                #pragma unroll
                for (int na = 0; na < 8; na++)
                    mma_bf16(acc[ma][na], Af[ma], &Bf[na >> 1][(na & 1) * 2]);
        }
        __syncthreads();
    }

    const int r0 = lane >> 2;
    const int c0 = (lane & 3) * 2;

    if (mode <= 1) {
        // ---- fused RoPE epilogue: acc -> smem fp32 -> rotate -> bf16 hi/lo ----
        float* Cs = (float*)smc;
        #pragma unroll
        for (int ma = 0; ma < 4; ma++)
            #pragma unroll
            for (int na = 0; na < 8; na++)
                #pragma unroll
                for (int half = 0; half < 2; half++) {
                    int rl = warp_m*64 + ma*16 + r0 + half*8;
                    int cl = warp_n*64 + na*8 + c0;
                    Cs[rl*CS_PITCH + cl]     = acc[ma][na][half*2];
                    Cs[rl*CS_PITCH + cl + 1] = acc[ma][na][half*2+1];
                }
        __syncthreads();

        __nv_bfloat16* Hdst = (mode == 0) ? g_Qh : g_Kh;
        __nv_bfloat16* Ldst = (mode == 0) ? g_Ql : g_Kl;
        #pragma unroll
        for (int pass = 0; pass < 4; pass++) {
            const int r = pass*32 + (tid >> 2);
            const int m = m0 + r;
            const int bb = m >> 11, sq = m & (SEQ - 1);
            const size_t dst = ((size_t)((bb*NHEAD + blockIdx.x)*SEQ + sq))*DHEAD;
            const int g0 = (tid & 3) * 16;
            #pragma unroll
            for (int c = 0; c < 2; c++) {
                const int i0 = g0 + c*8;
                uint32_t hA[4], lA[4], hB[4], lB[4];
                #pragma unroll
                for (int j = 0; j < 4; j++) {
                    int i = i0 + 2*j;
                    float a0 = Cs[r*CS_PITCH + i],      a1 = Cs[r*CS_PITCH + i + 1];
                    float b0 = Cs[r*CS_PITCH + i + 64], b1 = Cs[r*CS_PITCH + i + 65];
                    float sn0 = g_rsin[sq*64 + i], sn1 = g_rsin[sq*64 + i + 1];
                    float cc0 = g_rcos[sq*64 + i], cc1 = g_rcos[sq*64 + i + 1];
                    split_pack(a0*cc0 - b0*sn0, a1*cc1 - b1*sn1, hA[j], lA[j]);
                    split_pack(b0*cc0 + a0*sn0, b1*cc1 + a1*sn1, hB[j], lB[j]);
                }
                *(uint4*)(Hdst + dst + i0)      = make_uint4(hA[0], hA[1], hA[2], hA[3]);
                *(uint4*)(Ldst + dst + i0)      = make_uint4(lA[0], lA[1], lA[2], lA[3]);
                *(uint4*)(Hdst + dst + i0 + 64) = make_uint4(hB[0], hB[1], hB[2], hB[3]);
                *(uint4*)(Ldst + dst + i0 + 64) = make_uint4(lB[0], lB[1], lB[2], lB[3]);
            }
        }
    } else if (mode == 2) {
        #pragma unroll
        for (int ma = 0; ma < 4; ma++)
            #pragma unroll
            for (int na = 0; na < 8; na++) {
                const int coln = warp_n*64 + na*8 + c0;
                #pragma unroll
                for (int half = 0; half < 2; half++) {
                    const int m = m0 + warp_m*64 + ma*16 + r0 + half*8;
                    const int bb = m >> 11, ss = m & (SEQ - 1);
                    size_t off = ((size_t)((bb*NHEAD + blockIdx.x)*SEQ + ss))*DHEAD + coln;
                    uint32_t hi, lo;
                    split_pack(acc[ma][na][half*2], acc[ma][na][half*2+1], hi, lo);
                    *(uint32_t*)(g_Vh + off) = hi;
                    *(uint32_t*)(g_Vl + off) = lo;
                }
            }
    } else {
        #pragma unroll
        for (int ma = 0; ma < 4; ma++)
            #pragma unroll
            for (int na = 0; na < 8; na++) {
                const int coln = warp_n*64 + na*8 + c0;
                #pragma unroll
                for (int half = 0; half < 2; half++) {
                    const int m = m0 + warp_m*64 + ma*16 + r0 + half*8;
                    *(float2*)(Cout + (size_t)m * EMBED + n0 + coln) =
                        make_float2(acc[ma][na][half*2], acc[ma][na][half*2+1]);
                }
            }
    }
}

// ---------------- FA2-style bf16 mma attention (validated R8) ----------------
#define AP2    272
#define ATILE  (64*AP2)
#define AST2   (4*ATILE)
#define QLOFF  (2*AST2)
#define ABIAS2 (QLOFF + 128*AP2)
#define ATTN_SMEM (ABIAS2 + 512)

__device__ __forceinline__ void attn_pf(uint32_t sb_stage,
    const __nv_bfloat16* Kh, const __nv_bfloat16* Kl,
    const __nv_bfloat16* Vh, const __nv_bfloat16* Vl, int k0, int tid)
{
    #pragma unroll
    for (int i = 0; i < 4; i++) {
        int idx = tid + i*256;
        int r = idx >> 4, c = idx & 15;
        uint32_t so = sb_stage + r*AP2 + c*16;
        size_t go = (size_t)(k0 + r) * DHEAD;
        CP_ASYNC16(so,            (const char*)(Kh + go) + c*16);
        CP_ASYNC16(so + ATILE,    (const char*)(Kl + go) + c*16);
        CP_ASYNC16(so + 2*ATILE,  (const char*)(Vh + go) + c*16);
        CP_ASYNC16(so + 3*ATILE,  (const char*)(Vl + go) + c*16);
    }
}

__global__ void __launch_bounds__(256) attn_mma(const float* __restrict__ mask)
{
    extern __shared__ char smc[];
    const uint32_t sb = smem_to_u32(smc);
    const int tid = threadIdx.x, lane = tid & 31, wid = tid >> 5;
    const int qt = blockIdx.x, h = blockIdx.y, b = blockIdx.z;
    const int q0 = qt * 128;
    const size_t hb = (size_t)(b*NHEAD + h) * SEQ * DHEAD;
    const __nv_bfloat16 *Qhp = g_Qh + hb, *Qlp = g_Ql + hb;
    const __nv_bfloat16 *Khp = g_Kh + hb, *Klp = g_Kl + hb;
    const __nv_bfloat16 *Vhp = g_Vh + hb, *Vlp = g_Vl + hb;
    float* bias_sm = (float*)(smc + ABIAS2);

    #pragma unroll
    for (int i = 0; i < 8; i++) {
        int idx = tid + i*256;
        int r = idx >> 4, c = idx & 15;
        size_t go = (size_t)(q0 + r) * DHEAD;
        CP_ASYNC16(sb + r*AP2 + c*16,         (const char*)(Qhp + go) + c*16);
        CP_ASYNC16(sb + QLOFF + r*AP2 + c*16, (const char*)(Qlp + go) + c*16);
    }
    CP_COMMIT();
    CP_WAIT0();
    __syncthreads();

    const uint32_t qa_off = (uint32_t)((wid*16 + (lane & 15))*AP2 + (lane >> 4)*16);
    uint32_t Qf[8][4];
    #pragma unroll
    for (int t = 0; t < 8; t++) ldsm_x4(Qf[t], sb + qa_off + t*32);
    __syncthreads();

    attn_pf(sb, Khp, Klp, Vhp, Vlp, 0, tid);
    if (tid < 64) bias_sm[tid] = (1.0f - mask[b*SEQ + tid]) * -1e9f;
    CP_COMMIT();

    float O[16][4];
    #pragma unroll
    for (int j = 0; j < 16; j++)
        #pragma unroll
        for (int r = 0; r < 4; r++) O[j][r] = 0.f;
    float m_a = -1e30f, m_b = -1e30f, l_a = 0.f, l_b = 0.f;
    const float scale = 0.08838834764831845f;
    const int q_a = q0 + wid*16 + (lane >> 2);
    const int klo = 2*(lane & 3);
    const int nkt = 2*qt + 2;

    for (int kt = 0; kt < nkt; kt++) {
        const int stage = kt & 1;
        if (kt + 1 < nkt) {
            attn_pf(sb + (stage^1)*AST2, Khp, Klp, Vhp, Vlp, (kt+1)*64, tid);
            if (tid < 64) bias_sm[(stage^1)*64 + tid] = (1.0f - mask[b*SEQ + (kt+1)*64 + tid]) * -1e9f;
        }
        CP_COMMIT();
        CP_WAIT1();
        __syncthreads();

        const uint32_t ss = sb + stage*AST2;
        float s[8][4];
        #pragma unroll
        for (int j = 0; j < 8; j++)
            #pragma unroll
            for (int r = 0; r < 4; r++) s[j][r] = 0.f;

        #pragma unroll
        for (int t = 0; t < 8; t++) {
            uint32_t Al4[4];
            ldsm_x4(Al4, sb + QLOFF + qa_off + t*32);
            uint32_t Kh4[4][4], Kl4[4][4];
            #pragma unroll
            for (int g = 0; g < 4; g++) {
                uint32_t Baddr = ss + (g*16 + (lane & 7) + ((lane >> 4) << 3))*AP2
                               + t*32 + ((lane >> 3) & 1)*16;
                ldsm_x4(Kh4[g], Baddr);
                ldsm_x4(Kl4[g], Baddr + ATILE);
            }
            #pragma unroll
            for (int j = 0; j < 8; j++) mma_bf16(s[j], Qf[t], &Kh4[j>>1][(j&1)*2]);
            #pragma unroll
            for (int j = 0; j < 8; j++) mma_bf16(s[j], Al4,   &Kh4[j>>1][(j&1)*2]);
            #pragma unroll
            for (int j = 0; j < 8; j++) mma_bf16(s[j], Qf[t], &Kl4[j>>1][(j&1)*2]);
        }

        const float* bp = bias_sm + stage*64;
        const bool diag = (kt >= 2*qt);
        float tmax_a = -1e30f, tmax_b = -1e30f;
        #pragma unroll
        for (int j = 0; j < 8; j++) {
            int kk = 8*j + klo;
            float b0 = bp[kk], b1 = bp[kk+1];
            s[j][0] = s[j][0]*scale + b0;  s[j][1] = s[j][1]*scale + b1;
            s[j][2] = s[j][2]*scale + b0;  s[j][3] = s[j][3]*scale + b1;
            if (diag) {
                int kg = kt*64 + kk;
                if (kg   > q_a)   s[j][0] = -1e30f;
                if (kg+1 > q_a)   s[j][1] = -1e30f;
                if (kg   > q_a+8) s[j][2] = -1e30f;
                if (kg+1 > q_a+8) s[j][3] = -1e30f;
            }
            tmax_a = fmaxf(tmax_a, fmaxf(s[j][0], s[j][1]));
            tmax_b = fmaxf(tmax_b, fmaxf(s[j][2], s[j][3]));
        }
        tmax_a = fmaxf(tmax_a, __shfl_xor_sync(0xffffffffu, tmax_a, 1));
        tmax_a = fmaxf(tmax_a, __shfl_xor_sync(0xffffffffu, tmax_a, 2));
        tmax_b = fmaxf(tmax_b, __shfl_xor_sync(0xffffffffu, tmax_b, 1));
        tmax_b = fmaxf(tmax_b, __shfl_xor_sync(0xffffffffu, tmax_b, 2));
        float mn_a = fmaxf(m_a, tmax_a), mn_b = fmaxf(m_b, tmax_b);
        float ca = __expf(m_a - mn_a), cb = __expf(m_b - mn_b);
        m_a = mn_a; m_b = mn_b;
        float sum_a = 0.f, sum_b = 0.f;
        #pragma unroll
        for (int j = 0; j < 8; j++) {
            s[j][0] = __expf(s[j][0] - mn_a);  s[j][1] = __expf(s[j][1] - mn_a);
            s[j][2] = __expf(s[j][2] - mn_b);  s[j][3] = __expf(s[j][3] - mn_b);
            sum_a += s[j][0] + s[j][1];
            sum_b += s[j][2] + s[j][3];
        }
        sum_a += __shfl_xor_sync(0xffffffffu, sum_a, 1);
        sum_a += __shfl_xor_sync(0xffffffffu, sum_a, 2);
        sum_b += __shfl_xor_sync(0xffffffffu, sum_b, 1);
        sum_b += __shfl_xor_sync(0xffffffffu, sum_b, 2);
        l_a = l_a*ca + sum_a;
        l_b = l_b*cb + sum_b;
        #pragma unroll
        for (int j = 0; j < 16; j++) {
            O[j][0] *= ca; O[j][1] *= ca; O[j][2] *= cb; O[j][3] *= cb;
        }

        #pragma unroll
        for (int t = 0; t < 4; t++) {
            uint32_t aH[4], aL[4];
            split_pack(s[2*t][0],   s[2*t][1],   aH[0], aL[0]);
            split_pack(s[2*t][2],   s[2*t][3],   aH[1], aL[1]);
            split_pack(s[2*t+1][0], s[2*t+1][1], aH[2], aL[2]);
            split_pack(s[2*t+1][2], s[2*t+1][3], aH[3], aL[3]);
            #pragma unroll
            for (int g = 0; g < 8; g++) {
                uint32_t Baddr = ss + 2*ATILE
                               + (t*16 + (lane & 7) + ((lane >> 3) & 1)*8)*AP2
                               + g*32 + (lane >> 4)*16;
                uint32_t Vh4[4], Vl4[4];
                ldsm_x4_t(Vh4, Baddr);
                ldsm_x4_t(Vl4, Baddr + ATILE);
                mma_bf16(O[2*g],   aH, Vh4);     mma_bf16(O[2*g+1], aH, Vh4+2);
                mma_bf16(O[2*g],   aL, Vh4);     mma_bf16(O[2*g+1], aL, Vh4+2);
                mma_bf16(O[2*g],   aH, Vl4);     mma_bf16(O[2*g+1], aH, Vl4+2);
            }
        }
        __syncthreads();
    }

    const float ia = 1.0f / l_a, ib = 1.0f / l_b;
    const size_t ra = (size_t)(b*SEQ + q0 + wid*16 + (lane >> 2));
    const size_t oa = ra*EMBED + h*DHEAD + klo;
    const size_t ob = oa + 8*(size_t)EMBED;
    #pragma unroll
    for (int j = 0; j < 16; j++) {
        uint32_t hi, lo;
        split_pack(O[j][0]*ia, O[j][1]*ia, hi, lo);
        *(uint32_t*)(g_ch + oa + 8*j) = hi;
        *(uint32_t*)(g_cl + oa + 8*j) = lo;
        split_pack(O[j][2]*ib, O[j][3]*ib, hi, lo);
        *(uint32_t*)(g_ch + ob + 8*j) = hi;
        *(uint32_t*)(g_cl + ob + 8*j) = lo;
    }
}

// ---------------- launch ----------------
extern "C" void kernel_launch(void* const* d_in, const int* in_sizes, int n_in,
                              void* d_out, int out_size)
{
    (void)in_sizes; (void)n_in; (void)out_size;
    const float* x    = (const float*)d_in[0];
    const float* mask = (const float*)d_in[1];
    const float* Wq   = (const float*)d_in[2];
    const float* Wk   = (const float*)d_in[3];
    const float* Wv   = (const float*)d_in[4];
    const float* Wo   = (const float*)d_in[5];
    float* out        = (float*)d_out;

    cudaFuncSetAttribute(gemm_mma, cudaFuncAttributeMaxDynamicSharedMemorySize, GEMM_SMEM);
    cudaFuncSetAttribute(attn_mma, cudaFuncAttributeMaxDynamicSharedMemorySize, ATTN_SMEM);

    const int n4x = MTOT*EMBED/4;
    const int n4w = EMBED*EMBED/4;

    split_kernel<<<(n4x+255)/256, 256>>>(x, 0, n4x);
    split_kernel<<<(n4w+255)/256, 256>>>(Wq, 1, n4w);
    split_kernel<<<(n4w+255)/256, 256>>>(Wk, 2, n4w);
    split_kernel<<<(n4w+255)/256, 256>>>(Wv, 3, n4w);
    split_kernel<<<(n4w+255)/256, 256>>>(Wo, 4, n4w);

    rope_table<<<(SEQ*64)/256, 256>>>();

    dim3 ggrid(EMBED/128, MTOT/128);
    gemm_mma<<<ggrid, 128, GEMM_SMEM>>>(nullptr, 0);
    gemm_mma<<<ggrid, 128, GEMM_SMEM>>>(nullptr, 1);
    gemm_mma<<<ggrid, 128, GEMM_SMEM>>>(nullptr, 2);

    attn_mma<<<dim3(SEQ/128, NHEAD, BATCH), 256, ATTN_SMEM>>>(mask);

    gemm_mma<<<ggrid, 128, GEMM_SMEM>>>(out, 3);
}

// round 10
// speedup vs baseline: 4.5568x; 1.3258x over previous
#include <cuda_runtime.h>
#include <cuda_fp16.h>
#include <math.h>
#include <stdint.h>

#define EMBED 2048
#define SEQ   2048
#define NHEAD 16
#define DHEAD 128
#define BATCH 2
#define MTOT  (BATCH*SEQ)   // 4096

// ---------------- static device scratch (all fp16 now) ----------------
__device__ __half g_xh[MTOT*EMBED];
__device__ __half g_xl[MTOT*EMBED];
__device__ __half g_Wh[4*EMBED*EMBED];
__device__ __half g_ch[MTOT*EMBED];
__device__ __half g_cl[MTOT*EMBED];
__device__ __half g_Qh[BATCH*NHEAD*SEQ*DHEAD];
__device__ __half g_Ql[BATCH*NHEAD*SEQ*DHEAD];
__device__ __half g_Kh[BATCH*NHEAD*SEQ*DHEAD];
__device__ __half g_Kl[BATCH*NHEAD*SEQ*DHEAD];
__device__ __half g_Vh[BATCH*NHEAD*SEQ*DHEAD];
__device__ __half g_Vl[BATCH*NHEAD*SEQ*DHEAD];
__device__ float g_rsin[SEQ*64];
__device__ float g_rcos[SEQ*64];

// ---------------- baseline-PTX helpers ----------------
__device__ __forceinline__ uint32_t smem_to_u32(const void* p) {
    uint32_t a;
    asm("{ .reg .u64 t; cvta.to.shared.u64 t, %1; cvt.u32.u64 %0, t; }" : "=r"(a) : "l"(p));
    return a;
}
#define CP_ASYNC16(saddr, gptr) \
    asm volatile("cp.async.cg.shared.global [%0], [%1], 16;" :: "r"(saddr), "l"(gptr) : "memory")
#define CP_COMMIT() asm volatile("cp.async.commit_group;" ::: "memory")
#define CP_WAIT1()  asm volatile("cp.async.wait_group 1;" ::: "memory")
#define CP_WAIT0()  asm volatile("cp.async.wait_group 0;" ::: "memory")

__device__ __forceinline__ void ldsm_x4(uint32_t* r, uint32_t addr) {
    asm volatile("ldmatrix.sync.aligned.m8n8.x4.shared.b16 {%0,%1,%2,%3}, [%4];"
                 : "=r"(r[0]), "=r"(r[1]), "=r"(r[2]), "=r"(r[3]) : "r"(addr));
}
__device__ __forceinline__ void ldsm_x4_t(uint32_t* r, uint32_t addr) {
    asm volatile("ldmatrix.sync.aligned.m8n8.x4.trans.shared.b16 {%0,%1,%2,%3}, [%4];"
                 : "=r"(r[0]), "=r"(r[1]), "=r"(r[2]), "=r"(r[3]) : "r"(addr));
}
__device__ __forceinline__ void mma_f16(float* c, const uint32_t* a, const uint32_t* b) {
    asm volatile("mma.sync.aligned.m16n8k16.row.col.f32.f16.f16.f32 "
                 "{%0,%1,%2,%3}, {%4,%5,%6,%7}, {%8,%9}, {%0,%1,%2,%3};"
                 : "+f"(c[0]), "+f"(c[1]), "+f"(c[2]), "+f"(c[3])
                 : "r"(a[0]), "r"(a[1]), "r"(a[2]), "r"(a[3]), "r"(b[0]), "r"(b[1]));
}
__device__ __forceinline__ void split_pack(float x, float y, uint32_t& hi, uint32_t& lo) {
    __half hx = __float2half_rn(x), hy = __float2half_rn(y);
    hi = ((uint32_t)__half_as_ushort(hy) << 16) | __half_as_ushort(hx);
    __half lx = __float2half_rn(x - __half2float(hx));
    __half ly = __float2half_rn(y - __half2float(hy));
    lo = ((uint32_t)__half_as_ushort(ly) << 16) | __half_as_ushort(lx);
}

// ---------------- split: f32 -> fp16 hi (+ lo for x only) ----------------
// which: 0=x (hi+lo), 1..4=Wq/Wk/Wv/Wo (hi only)
__global__ void __launch_bounds__(256) split_kernel(const float* __restrict__ src,
                                                    int which, int n4)
{
    int idx = blockIdx.x * 256 + threadIdx.x;
    if (idx >= n4) return;

    float4 v = ((const float4*)src)[idx];
    float f[4] = {v.x, v.y, v.z, v.w};
    uint32_t hp[2], lp[2];
    split_pack(f[0], f[1], hp[0], lp[0]);
    split_pack(f[2], f[3], hp[1], lp[1]);

    if (which == 0) {
        *(uint2*)((uint32_t*)g_xh + idx*2) = make_uint2(hp[0], hp[1]);
        *(uint2*)((uint32_t*)g_xl + idx*2) = make_uint2(lp[0], lp[1]);
    } else {
        __half* hi = g_Wh + (size_t)(which - 1) * EMBED * EMBED;
        *(uint2*)((uint32_t*)hi + idx*2) = make_uint2(hp[0], hp[1]);
    }
}

// ---------------- RoPE table ----------------
__global__ void __launch_bounds__(256) rope_table()
{
    int idx = blockIdx.x * 256 + threadIdx.x;
    int i = idx & 63, s = idx >> 6;
    float freq = (float)pow(10000.0, -(double)i / 64.0);
    float ang  = (float)s * freq;
    double sn, cs;
    sincos((double)ang, &sn, &cs);
    g_rsin[idx] = (float)sn;
    g_rcos[idx] = (float)cs;
}

// ---------------- mma.sync fp16 2-product GEMM: C = (Ah+Al) * Wh^T --------
// 4 warps, warp tile 64x64, block 128x128, BK=32, 3 smem tiles/stage.
// mode 0: x->g_Qh/g_Ql (RoPE fused)   mode 1: x->g_Kh/g_Kl (RoPE fused)
// mode 2: x->g_Vh/g_Vl                mode 3: ctx(ch/cl)->Cout (f32)
#define GT_PITCH 80
#define GT_TILE  (128*GT_PITCH)      // 10240
#define GT_STAGE (3*GT_TILE)         // 30720
#define CS_PITCH 134                 // fp32 epilogue tile pitch (floats)
#define GEMM_SMEM (128*CS_PITCH*4)   // 68608 >= 2*GT_STAGE (61440)

__global__ void __launch_bounds__(128) gemm_mma(float* __restrict__ Cout, int mode)
{
    extern __shared__ char smc[];
    const uint32_t sbase = smem_to_u32(smc);
    const int tid  = threadIdx.x;
    const int lane = tid & 31;
    const int wid  = tid >> 5;
    const int warp_m = wid >> 1;          // 0..1
    const int warp_n = wid & 1;           // 0..1
    const int n0 = blockIdx.x * 128;
    const int m0 = blockIdx.y * 128;

    const __half* srcs[3];
    srcs[0] = ((mode == 3) ? g_ch : g_xh);
    srcs[1] = ((mode == 3) ? g_cl : g_xl);
    srcs[2] = g_Wh + (size_t)mode * EMBED * EMBED;
    const int base_row[3] = {m0, m0, n0};

    const int seg = tid & 3;              // 16B chunk within 64B row
    const int rb  = tid >> 2;             // base row, +32 per i

    const uint32_t a_off = (uint32_t)((warp_m*64 + (lane & 15)) * GT_PITCH + (lane >> 4) * 16);
    const uint32_t b_off = (uint32_t)(((lane & 7) + (lane >> 4) * 8 + warp_n*64) * GT_PITCH
                                      + ((lane >> 3) & 1) * 16);

    float acc[4][8][4];
    #pragma unroll
    for (int i = 0; i < 4; i++)
        #pragma unroll
        for (int j = 0; j < 8; j++)
            #pragma unroll
            for (int r = 0; r < 4; r++) acc[i][j][r] = 0.f;

    // ---- prefetch stage 0 ----
    #pragma unroll
    for (int t = 0; t < 3; t++)
        #pragma unroll
        for (int i = 0; i < 4; i++) {
            int row = rb + i*32;
            const __half* g = srcs[t] + (size_t)(base_row[t] + row) * EMBED + seg*8;
            CP_ASYNC16(sbase + t*GT_TILE + row*GT_PITCH + seg*16, g);
        }
    CP_COMMIT();

    for (int s = 0; s < EMBED/32; s++) {
        if (s < EMBED/32 - 1) {
            const uint32_t sb = sbase + ((s+1) & 1) * GT_STAGE;
            const int k0 = (s+1) * 32;
            #pragma unroll
            for (int t = 0; t < 3; t++)
                #pragma unroll
                for (int i = 0; i < 4; i++) {
                    int row = rb + i*32;
                    const __half* g = srcs[t] + (size_t)(base_row[t] + row) * EMBED + k0 + seg*8;
                    CP_ASYNC16(sb + t*GT_TILE + row*GT_PITCH + seg*16, g);
                }
        }
        CP_COMMIT();
        CP_WAIT1();
        __syncthreads();

        const uint32_t sb = sbase + (s & 1) * GT_STAGE;
        #pragma unroll
        for (int kk = 0; kk < 2; kk++) {
            const uint32_t ko = kk * 32;
            uint32_t Af[4][4], Bf[4][4];
            // Ah x Wh
            #pragma unroll
            for (int ma = 0; ma < 4; ma++)
                ldsm_x4(Af[ma], sb + 0*GT_TILE + a_off + ko + ma*16*GT_PITCH);
            #pragma unroll
            for (int g = 0; g < 4; g++)
                ldsm_x4(Bf[g], sb + 2*GT_TILE + b_off + ko + g*16*GT_PITCH);
            #pragma unroll
            for (int ma = 0; ma < 4; ma++)
                #pragma unroll
                for (int na = 0; na < 8; na++)
                    mma_f16(acc[ma][na], Af[ma], &Bf[na >> 1][(na & 1) * 2]);
            // Al x Wh (reuse Af regs)
            #pragma unroll
            for (int ma = 0; ma < 4; ma++)
                ldsm_x4(Af[ma], sb + 1*GT_TILE + a_off + ko + ma*16*GT_PITCH);
            #pragma unroll
            for (int ma = 0; ma < 4; ma++)
                #pragma unroll
                for (int na = 0; na < 8; na++)
                    mma_f16(acc[ma][na], Af[ma], &Bf[na >> 1][(na & 1) * 2]);
        }
        __syncthreads();
    }

    const int r0 = lane >> 2;
    const int c0 = (lane & 3) * 2;

    if (mode <= 1) {
        // ---- fused RoPE epilogue: acc -> smem fp32 -> rotate -> fp16 hi/lo ----
        float* Cs = (float*)smc;
        #pragma unroll
        for (int ma = 0; ma < 4; ma++)
            #pragma unroll
            for (int na = 0; na < 8; na++)
                #pragma unroll
                for (int half = 0; half < 2; half++) {
                    int rl = warp_m*64 + ma*16 + r0 + half*8;
                    int cl = warp_n*64 + na*8 + c0;
                    Cs[rl*CS_PITCH + cl]     = acc[ma][na][half*2];
                    Cs[rl*CS_PITCH + cl + 1] = acc[ma][na][half*2+1];
                }
        __syncthreads();

        __half* Hdst = (mode == 0) ? g_Qh : g_Kh;
        __half* Ldst = (mode == 0) ? g_Ql : g_Kl;
        #pragma unroll
        for (int pass = 0; pass < 4; pass++) {
            const int r = pass*32 + (tid >> 2);
            const int m = m0 + r;
            const int bb = m >> 11, sq = m & (SEQ - 1);
            const size_t dst = ((size_t)((bb*NHEAD + blockIdx.x)*SEQ + sq))*DHEAD;
            const int g0 = (tid & 3) * 16;
            #pragma unroll
            for (int c = 0; c < 2; c++) {
                const int i0 = g0 + c*8;
                uint32_t hA[4], lA[4], hB[4], lB[4];
                #pragma unroll
                for (int j = 0; j < 4; j++) {
                    int i = i0 + 2*j;
                    float a0 = Cs[r*CS_PITCH + i],      a1 = Cs[r*CS_PITCH + i + 1];
                    float b0 = Cs[r*CS_PITCH + i + 64], b1 = Cs[r*CS_PITCH + i + 65];
                    float sn0 = g_rsin[sq*64 + i], sn1 = g_rsin[sq*64 + i + 1];
                    float cc0 = g_rcos[sq*64 + i], cc1 = g_rcos[sq*64 + i + 1];
                    split_pack(a0*cc0 - b0*sn0, a1*cc1 - b1*sn1, hA[j], lA[j]);
                    split_pack(b0*cc0 + a0*sn0, b1*cc1 + a1*sn1, hB[j], lB[j]);
                }
                *(uint4*)(Hdst + dst + i0)      = make_uint4(hA[0], hA[1], hA[2], hA[3]);
                *(uint4*)(Ldst + dst + i0)      = make_uint4(lA[0], lA[1], lA[2], lA[3]);
                *(uint4*)(Hdst + dst + i0 + 64) = make_uint4(hB[0], hB[1], hB[2], hB[3]);
                *(uint4*)(Ldst + dst + i0 + 64) = make_uint4(lB[0], lB[1], lB[2], lB[3]);
            }
        }
    } else if (mode == 2) {
        #pragma unroll
        for (int ma = 0; ma < 4; ma++)
            #pragma unroll
            for (int na = 0; na < 8; na++) {
                const int coln = warp_n*64 + na*8 + c0;
                #pragma unroll
                for (int half = 0; half < 2; half++) {
                    const int m = m0 + warp_m*64 + ma*16 + r0 + half*8;
                    const int bb = m >> 11, ss = m & (SEQ - 1);
                    size_t off = ((size_t)((bb*NHEAD + blockIdx.x)*SEQ + ss))*DHEAD + coln;
                    uint32_t hi, lo;
                    split_pack(acc[ma][na][half*2], acc[ma][na][half*2+1], hi, lo);
                    *(uint32_t*)(g_Vh + off) = hi;
                    *(uint32_t*)(g_Vl + off) = lo;
                }
            }
    } else {
        #pragma unroll
        for (int ma = 0; ma < 4; ma++)
            #pragma unroll
            for (int na = 0; na < 8; na++) {
                const int coln = warp_n*64 + na*8 + c0;
                #pragma unroll
                for (int half = 0; half < 2; half++) {
                    const int m = m0 + warp_m*64 + ma*16 + r0 + half*8;
                    *(float2*)(Cout + (size_t)m * EMBED + n0 + coln) =
                        make_float2(acc[ma][na][half*2], acc[ma][na][half*2+1]);
                }
            }
    }
}

// ---------------- FA2-style fp16 mma attention (3-product, hedged) ------------
#define AP2    272
#define ATILE  (64*AP2)
#define AST2   (4*ATILE)
#define QLOFF  (2*AST2)
#define ABIAS2 (QLOFF + 128*AP2)
#define ATTN_SMEM (ABIAS2 + 512)

__device__ __forceinline__ void attn_pf(uint32_t sb_stage,
    const __half* Kh, const __half* Kl,
    const __half* Vh, const __half* Vl, int k0, int tid)
{
    #pragma unroll
    for (int i = 0; i < 4; i++) {
        int idx = tid + i*256;
        int r = idx >> 4, c = idx & 15;
        uint32_t so = sb_stage + r*AP2 + c*16;
        size_t go = (size_t)(k0 + r) * DHEAD;
        CP_ASYNC16(so,            (const char*)(Kh + go) + c*16);
        CP_ASYNC16(so + ATILE,    (const char*)(Kl + go) + c*16);
        CP_ASYNC16(so + 2*ATILE,  (const char*)(Vh + go) + c*16);
        CP_ASYNC16(so + 3*ATILE,  (const char*)(Vl + go) + c*16);
    }
}

__global__ void __launch_bounds__(256) attn_mma(const float* __restrict__ mask)
{
    extern __shared__ char smc[];
    const uint32_t sb = smem_to_u32(smc);
    const int tid = threadIdx.x, lane = tid & 31, wid = tid >> 5;
    const int qt = blockIdx.x, h = blockIdx.y, b = blockIdx.z;
    const int q0 = qt * 128;
    const size_t hb = (size_t)(b*NHEAD + h) * SEQ * DHEAD;
    const __half *Qhp = g_Qh + hb, *Qlp = g_Ql + hb;
    const __half *Khp = g_Kh + hb, *Klp = g_Kl + hb;
    const __half *Vhp = g_Vh + hb, *Vlp = g_Vl + hb;
    float* bias_sm = (float*)(smc + ABIAS2);

    #pragma unroll
    for (int i = 0; i < 8; i++) {
        int idx = tid + i*256;
        int r = idx >> 4, c = idx & 15;
        size_t go = (size_t)(q0 + r) * DHEAD;
        CP_ASYNC16(sb + r*AP2 + c*16,         (const char*)(Qhp + go) + c*16);
        CP_ASYNC16(sb + QLOFF + r*AP2 + c*16, (const char*)(Qlp + go) + c*16);
    }
    CP_COMMIT();
    CP_WAIT0();
    __syncthreads();

    const uint32_t qa_off = (uint32_t)((wid*16 + (lane & 15))*AP2 + (lane >> 4)*16);
    uint32_t Qf[8][4];
    #pragma unroll
    for (int t = 0; t < 8; t++) ldsm_x4(Qf[t], sb + qa_off + t*32);
    __syncthreads();

    attn_pf(sb, Khp, Klp, Vhp, Vlp, 0, tid);
    if (tid < 64) bias_sm[tid] = (1.0f - mask[b*SEQ + tid]) * -1e9f;
    CP_COMMIT();

    float O[16][4];
    #pragma unroll
    for (int j = 0; j < 16; j++)
        #pragma unroll
        for (int r = 0; r < 4; r++) O[j][r] = 0.f;
    float m_a = -1e30f, m_b = -1e30f, l_a = 0.f, l_b = 0.f;
    const float scale = 0.08838834764831845f;
    const int q_a = q0 + wid*16 + (lane >> 2);
    const int klo = 2*(lane & 3);
    const int nkt = 2*qt + 2;

    for (int kt = 0; kt < nkt; kt++) {
        const int stage = kt & 1;
        if (kt + 1 < nkt) {
            attn_pf(sb + (stage^1)*AST2, Khp, Klp, Vhp, Vlp, (kt+1)*64, tid);
            if (tid < 64) bias_sm[(stage^1)*64 + tid] = (1.0f - mask[b*SEQ + (kt+1)*64 + tid]) * -1e9f;
        }
        CP_COMMIT();
        CP_WAIT1();
        __syncthreads();

        const uint32_t ss = sb + stage*AST2;
        float s[8][4];
        #pragma unroll
        for (int j = 0; j < 8; j++)
            #pragma unroll
            for (int r = 0; r < 4; r++) s[j][r] = 0.f;

        #pragma unroll
        for (int t = 0; t < 8; t++) {
            uint32_t Al4[4];
            ldsm_x4(Al4, sb + QLOFF + qa_off + t*32);
            uint32_t Kh4[4][4], Kl4[4][4];
            #pragma unroll
            for (int g = 0; g < 4; g++) {
                uint32_t Baddr = ss + (g*16 + (lane & 7) + ((lane >> 4) << 3))*AP2
                               + t*32 + ((lane >> 3) & 1)*16;
                ldsm_x4(Kh4[g], Baddr);
                ldsm_x4(Kl4[g], Baddr + ATILE);
            }
            #pragma unroll
            for (int j = 0; j < 8; j++) mma_f16(s[j], Qf[t], &Kh4[j>>1][(j&1)*2]);
            #pragma unroll
            for (int j = 0; j < 8; j++) mma_f16(s[j], Al4,   &Kh4[j>>1][(j&1)*2]);
            #pragma unroll
            for (int j = 0; j < 8; j++) mma_f16(s[j], Qf[t], &Kl4[j>>1][(j&1)*2]);
        }

        const float* bp = bias_sm + stage*64;
        const bool diag = (kt >= 2*qt);
        float tmax_a = -1e30f, tmax_b = -1e30f;
        #pragma unroll
        for (int j = 0; j < 8; j++) {
            int kk = 8*j + klo;
            float b0 = bp[kk], b1 = bp[kk+1];
            s[j][0] = s[j][0]*scale + b0;  s[j][1] = s[j][1]*scale + b1;
            s[j][2] = s[j][2]*scale + b0;  s[j][3] = s[j][3]*scale + b1;
            if (diag) {
                int kg = kt*64 + kk;
                if (kg   > q_a)   s[j][0] = -1e30f;
                if (kg+1 > q_a)   s[j][1] = -1e30f;
                if (kg   > q_a+8) s[j][2] = -1e30f;
                if (kg+1 > q_a+8) s[j][3] = -1e30f;
            }
            tmax_a = fmaxf(tmax_a, fmaxf(s[j][0], s[j][1]));
            tmax_b = fmaxf(tmax_b, fmaxf(s[j][2], s[j][3]));
        }
        tmax_a = fmaxf(tmax_a, __shfl_xor_sync(0xffffffffu, tmax_a, 1));
        tmax_a = fmaxf(tmax_a, __shfl_xor_sync(0xffffffffu, tmax_a, 2));
        tmax_b = fmaxf(tmax_b, __shfl_xor_sync(0xffffffffu, tmax_b, 1));
        tmax_b = fmaxf(tmax_b, __shfl_xor_sync(0xffffffffu, tmax_b, 2));
        float mn_a = fmaxf(m_a, tmax_a), mn_b = fmaxf(m_b, tmax_b);
        float ca = __expf(m_a - mn_a), cb = __expf(m_b - mn_b);
        m_a = mn_a; m_b = mn_b;
        float sum_a = 0.f, sum_b = 0.f;
        #pragma unroll
        for (int j = 0; j < 8; j++) {
            s[j][0] = __expf(s[j][0] - mn_a);  s[j][1] = __expf(s[j][1] - mn_a);
            s[j][2] = __expf(s[j][2] - mn_b);  s[j][3] = __expf(s[j][3] - mn_b);
            sum_a += s[j][0] + s[j][1];
            sum_b += s[j][2] + s[j][3];
        }
        sum_a += __shfl_xor_sync(0xffffffffu, sum_a, 1);
        sum_a += __shfl_xor_sync(0xffffffffu, sum_a, 2);
        sum_b += __shfl_xor_sync(0xffffffffu, sum_b, 1);
        sum_b += __shfl_xor_sync(0xffffffffu, sum_b, 2);
        l_a = l_a*ca + sum_a;
        l_b = l_b*cb + sum_b;
        #pragma unroll
        for (int j = 0; j < 16; j++) {
            O[j][0] *= ca; O[j][1] *= ca; O[j][2] *= cb; O[j][3] *= cb;
        }

        #pragma unroll
        for (int t = 0; t < 4; t++) {
            uint32_t aH[4], aL[4];
            split_pack(s[2*t][0],   s[2*t][1],   aH[0], aL[0]);
            split_pack(s[2*t][2],   s[2*t][3],   aH[1], aL[1]);
            split_pack(s[2*t+1][0], s[2*t+1][1], aH[2], aL[2]);
            split_pack(s[2*t+1][2], s[2*t+1][3], aH[3], aL[3]);
            #pragma unroll
            for (int g = 0; g < 8; g++) {
                uint32_t Baddr = ss + 2*ATILE
                               + (t*16 + (lane & 7) + ((lane >> 3) & 1)*8)*AP2
                               + g*32 + (lane >> 4)*16;
                uint32_t Vh4[4], Vl4[4];
                ldsm_x4_t(Vh4, Baddr);
                ldsm_x4_t(Vl4, Baddr + ATILE);
                mma_f16(O[2*g],   aH, Vh4);     mma_f16(O[2*g+1], aH, Vh4+2);
                mma_f16(O[2*g],   aL, Vh4);     mma_f16(O[2*g+1], aL, Vh4+2);
                mma_f16(O[2*g],   aH, Vl4);     mma_f16(O[2*g+1], aH, Vl4+2);
            }
        }
        __syncthreads();
    }

    const float ia = 1.0f / l_a, ib = 1.0f / l_b;
    const size_t ra = (size_t)(b*SEQ + q0 + wid*16 + (lane >> 2));
    const size_t oa = ra*EMBED + h*DHEAD + klo;
    const size_t ob = oa + 8*(size_t)EMBED;
    #pragma unroll
    for (int j = 0; j < 16; j++) {
        uint32_t hi, lo;
        split_pack(O[j][0]*ia, O[j][1]*ia, hi, lo);
        *(uint32_t*)(g_ch + oa + 8*j) = hi;
        *(uint32_t*)(g_cl + oa + 8*j) = lo;
        split_pack(O[j][2]*ib, O[j][3]*ib, hi, lo);
        *(uint32_t*)(g_ch + ob + 8*j) = hi;
        *(uint32_t*)(g_cl + ob + 8*j) = lo;
    }
}

// ---------------- launch ----------------
extern "C" void kernel_launch(void* const* d_in, const int* in_sizes, int n_in,
                              void* d_out, int out_size)
{
    (void)in_sizes; (void)n_in; (void)out_size;
    const float* x    = (const float*)d_in[0];
    const float* mask = (const float*)d_in[1];
    const float* Wq   = (const float*)d_in[2];
    const float* Wk   = (const float*)d_in[3];
    const float* Wv   = (const float*)d_in[4];
    const float* Wo   = (const float*)d_in[5];
    float* out        = (float*)d_out;

    cudaFuncSetAttribute(gemm_mma, cudaFuncAttributeMaxDynamicSharedMemorySize, GEMM_SMEM);
    cudaFuncSetAttribute(attn_mma, cudaFuncAttributeMaxDynamicSharedMemorySize, ATTN_SMEM);

    const int n4x = MTOT*EMBED/4;
    const int n4w = EMBED*EMBED/4;

    split_kernel<<<(n4x+255)/256, 256>>>(x, 0, n4x);
    split_kernel<<<(n4w+255)/256, 256>>>(Wq, 1, n4w);
    split_kernel<<<(n4w+255)/256, 256>>>(Wk, 2, n4w);
    split_kernel<<<(n4w+255)/256, 256>>>(Wv, 3, n4w);
    split_kernel<<<(n4w+255)/256, 256>>>(Wo, 4, n4w);

    rope_table<<<(SEQ*64)/256, 256>>>();

    dim3 ggrid(EMBED/128, MTOT/128);
    gemm_mma<<<ggrid, 128, GEMM_SMEM>>>(nullptr, 0);
    gemm_mma<<<ggrid, 128, GEMM_SMEM>>>(nullptr, 1);
    gemm_mma<<<ggrid, 128, GEMM_SMEM>>>(nullptr, 2);

    attn_mma<<<dim3(SEQ/128, NHEAD, BATCH), 256, ATTN_SMEM>>>(mask);

    gemm_mma<<<ggrid, 128, GEMM_SMEM>>>(out, 3);
}

// round 11
// speedup vs baseline: 5.0280x; 1.1034x over previous
#include <cuda_runtime.h>
#include <cuda_fp16.h>
#include <math.h>
#include <stdint.h>

#define EMBED 2048
#define SEQ   2048
#define NHEAD 16
#define DHEAD 128
#define BATCH 2
#define MTOT  (BATCH*SEQ)   // 4096

// ---------------- static device scratch (fp16) ----------------
__device__ __half g_xh[MTOT*EMBED];
__device__ __half g_xl[MTOT*EMBED];
__device__ __half g_Wh[4*EMBED*EMBED];
__device__ __half g_ch[MTOT*EMBED];
__device__ __half g_cl[MTOT*EMBED];
__device__ __half g_Qh[BATCH*NHEAD*SEQ*DHEAD];
__device__ __half g_Ql[BATCH*NHEAD*SEQ*DHEAD];
__device__ __half g_Kh[BATCH*NHEAD*SEQ*DHEAD];
__device__ __half g_Vh[BATCH*NHEAD*SEQ*DHEAD];
__device__ float g_rsin[SEQ*64];
__device__ float g_rcos[SEQ*64];

// ---------------- baseline-PTX helpers ----------------
__device__ __forceinline__ uint32_t smem_to_u32(const void* p) {
    uint32_t a;
    asm("{ .reg .u64 t; cvta.to.shared.u64 t, %1; cvt.u32.u64 %0, t; }" : "=r"(a) : "l"(p));
    return a;
}
#define CP_ASYNC16(saddr, gptr) \
    asm volatile("cp.async.cg.shared.global [%0], [%1], 16;" :: "r"(saddr), "l"(gptr) : "memory")
#define CP_COMMIT() asm volatile("cp.async.commit_group;" ::: "memory")
#define CP_WAIT1()  asm volatile("cp.async.wait_group 1;" ::: "memory")
#define CP_WAIT0()  asm volatile("cp.async.wait_group 0;" ::: "memory")

__device__ __forceinline__ void ldsm_x4(uint32_t* r, uint32_t addr) {
    asm volatile("ldmatrix.sync.aligned.m8n8.x4.shared.b16 {%0,%1,%2,%3}, [%4];"
                 : "=r"(r[0]), "=r"(r[1]), "=r"(r[2]), "=r"(r[3]) : "r"(addr));
}
__device__ __forceinline__ void ldsm_x4_t(uint32_t* r, uint32_t addr) {
    asm volatile("ldmatrix.sync.aligned.m8n8.x4.trans.shared.b16 {%0,%1,%2,%3}, [%4];"
                 : "=r"(r[0]), "=r"(r[1]), "=r"(r[2]), "=r"(r[3]) : "r"(addr));
}
__device__ __forceinline__ void mma_f16(float* c, const uint32_t* a, const uint32_t* b) {
    asm volatile("mma.sync.aligned.m16n8k16.row.col.f32.f16.f16.f32 "
                 "{%0,%1,%2,%3}, {%4,%5,%6,%7}, {%8,%9}, {%0,%1,%2,%3};"
                 : "+f"(c[0]), "+f"(c[1]), "+f"(c[2]), "+f"(c[3])
                 : "r"(a[0]), "r"(a[1]), "r"(a[2]), "r"(a[3]), "r"(b[0]), "r"(b[1]));
}
__device__ __forceinline__ void split_pack(float x, float y, uint32_t& hi, uint32_t& lo) {
    __half hx = __float2half_rn(x), hy = __float2half_rn(y);
    hi = ((uint32_t)__half_as_ushort(hy) << 16) | __half_as_ushort(hx);
    __half lx = __float2half_rn(x - __half2float(hx));
    __half ly = __float2half_rn(y - __half2float(hy));
    lo = ((uint32_t)__half_as_ushort(ly) << 16) | __half_as_ushort(lx);
}
__device__ __forceinline__ uint32_t pack_h(float x, float y) {
    return ((uint32_t)__half_as_ushort(__float2half_rn(y)) << 16)
         | __half_as_ushort(__float2half_rn(x));
}

// ---------------- split: f32 -> fp16 hi (+ lo for x only) ----------------
// which: 0=x (hi+lo), 1..4=Wq/Wk/Wv/Wo (hi only)
__global__ void __launch_bounds__(256) split_kernel(const float* __restrict__ src,
                                                    int which, int n4)
{
    int idx = blockIdx.x * 256 + threadIdx.x;
    if (idx >= n4) return;

    float4 v = ((const float4*)src)[idx];
    uint32_t hp[2], lp[2];
    split_pack(v.x, v.y, hp[0], lp[0]);
    split_pack(v.z, v.w, hp[1], lp[1]);

    if (which == 0) {
        *(uint2*)((uint32_t*)g_xh + idx*2) = make_uint2(hp[0], hp[1]);
        *(uint2*)((uint32_t*)g_xl + idx*2) = make_uint2(lp[0], lp[1]);
    } else {
        __half* hi = g_Wh + (size_t)(which - 1) * EMBED * EMBED;
        *(uint2*)((uint32_t*)hi + idx*2) = make_uint2(hp[0], hp[1]);
    }
}

// ---------------- RoPE table ----------------
__global__ void __launch_bounds__(256) rope_table()
{
    int idx = blockIdx.x * 256 + threadIdx.x;
    int i = idx & 63, s = idx >> 6;
    float freq = (float)pow(10000.0, -(double)i / 64.0);
    float ang  = (float)s * freq;
    double sn, cs;
    sincos((double)ang, &sn, &cs);
    g_rsin[idx] = (float)sn;
    g_rcos[idx] = (float)cs;
}

// ---------------- mma.sync fp16 2-product GEMM: C = (Ah+Al) * Wh^T --------
// mode 0: x->g_Qh/g_Ql (RoPE fused)   mode 1: x->g_Kh (RoPE fused, hi only)
// mode 2: x->g_Vh (hi only)           mode 3: ctx(ch/cl)->Cout (f32)
#define GT_PITCH 80
#define GT_TILE  (128*GT_PITCH)      // 10240
#define GT_STAGE (3*GT_TILE)         // 30720
#define CS_PITCH 134
#define GEMM_SMEM (128*CS_PITCH*4)   // 68608 >= 2*GT_STAGE

__global__ void __launch_bounds__(128) gemm_mma(float* __restrict__ Cout, int mode)
{
    extern __shared__ char smc[];
    const uint32_t sbase = smem_to_u32(smc);
    const int tid  = threadIdx.x;
    const int lane = tid & 31;
    const int wid  = tid >> 5;
    const int warp_m = wid >> 1;
    const int warp_n = wid & 1;
    const int n0 = blockIdx.x * 128;
    const int m0 = blockIdx.y * 128;

    const __half* srcs[3];
    srcs[0] = ((mode == 3) ? g_ch : g_xh);
    srcs[1] = ((mode == 3) ? g_cl : g_xl);
    srcs[2] = g_Wh + (size_t)mode * EMBED * EMBED;
    const int base_row[3] = {m0, m0, n0};

    const int seg = tid & 3;
    const int rb  = tid >> 2;

    const uint32_t a_off = (uint32_t)((warp_m*64 + (lane & 15)) * GT_PITCH + (lane >> 4) * 16);
    const uint32_t b_off = (uint32_t)(((lane & 7) + (lane >> 4) * 8 + warp_n*64) * GT_PITCH
                                      + ((lane >> 3) & 1) * 16);

    float acc[4][8][4];
    #pragma unroll
    for (int i = 0; i < 4; i++)
        #pragma unroll
        for (int j = 0; j < 8; j++)
            #pragma unroll
            for (int r = 0; r < 4; r++) acc[i][j][r] = 0.f;

    #pragma unroll
    for (int t = 0; t < 3; t++)
        #pragma unroll
        for (int i = 0; i < 4; i++) {
            int row = rb + i*32;
            const __half* g = srcs[t] + (size_t)(base_row[t] + row) * EMBED + seg*8;
            CP_ASYNC16(sbase + t*GT_TILE + row*GT_PITCH + seg*16, g);
        }
    CP_COMMIT();

    for (int s = 0; s < EMBED/32; s++) {
        if (s < EMBED/32 - 1) {
            const uint32_t sb = sbase + ((s+1) & 1) * GT_STAGE;
            const int k0 = (s+1) * 32;
            #pragma unroll
            for (int t = 0; t < 3; t++)
                #pragma unroll
                for (int i = 0; i < 4; i++) {
                    int row = rb + i*32;
                    const __half* g = srcs[t] + (size_t)(base_row[t] + row) * EMBED + k0 + seg*8;
                    CP_ASYNC16(sb + t*GT_TILE + row*GT_PITCH + seg*16, g);
                }
        }
        CP_COMMIT();
        CP_WAIT1();
        __syncthreads();

        const uint32_t sb = sbase + (s & 1) * GT_STAGE;
        #pragma unroll
        for (int kk = 0; kk < 2; kk++) {
            const uint32_t ko = kk * 32;
            uint32_t Af[4][4], Bf[4][4];
            #pragma unroll
            for (int ma = 0; ma < 4; ma++)
                ldsm_x4(Af[ma], sb + 0*GT_TILE + a_off + ko + ma*16*GT_PITCH);
            #pragma unroll
            for (int g = 0; g < 4; g++)
                ldsm_x4(Bf[g], sb + 2*GT_TILE + b_off + ko + g*16*GT_PITCH);
            #pragma unroll
            for (int ma = 0; ma < 4; ma++)
                #pragma unroll
                for (int na = 0; na < 8; na++)
                    mma_f16(acc[ma][na], Af[ma], &Bf[na >> 1][(na & 1) * 2]);
            #pragma unroll
            for (int ma = 0; ma < 4; ma++)
                ldsm_x4(Af[ma], sb + 1*GT_TILE + a_off + ko + ma*16*GT_PITCH);
            #pragma unroll
            for (int ma = 0; ma < 4; ma++)
                #pragma unroll
                for (int na = 0; na < 8; na++)
                    mma_f16(acc[ma][na], Af[ma], &Bf[na >> 1][(na & 1) * 2]);
        }
        __syncthreads();
    }

    const int r0 = lane >> 2;
    const int c0 = (lane & 3) * 2;

    if (mode <= 1) {
        // ---- fused RoPE epilogue ----
        float* Cs = (float*)smc;
        #pragma unroll
        for (int ma = 0; ma < 4; ma++)
            #pragma unroll
            for (int na = 0; na < 8; na++)
                #pragma unroll
                for (int half = 0; half < 2; half++) {
                    int rl = warp_m*64 + ma*16 + r0 + half*8;
                    int cl = warp_n*64 + na*8 + c0;
                    Cs[rl*CS_PITCH + cl]     = acc[ma][na][half*2];
                    Cs[rl*CS_PITCH + cl + 1] = acc[ma][na][half*2+1];
                }
        __syncthreads();

        const bool isQ = (mode == 0);
        __half* Hdst = isQ ? g_Qh : g_Kh;
        #pragma unroll
        for (int pass = 0; pass < 4; pass++) {
            const int r = pass*32 + (tid >> 2);
            const int m = m0 + r;
            const int bb = m >> 11, sq = m & (SEQ - 1);
            const size_t dst = ((size_t)((bb*NHEAD + blockIdx.x)*SEQ + sq))*DHEAD;
            const int g0 = (tid & 3) * 16;
            #pragma unroll
            for (int c = 0; c < 2; c++) {
                const int i0 = g0 + c*8;
                uint32_t hA[4], lA[4], hB[4], lB[4];
                #pragma unroll
                for (int j = 0; j < 4; j++) {
                    int i = i0 + 2*j;
                    float a0 = Cs[r*CS_PITCH + i],      a1 = Cs[r*CS_PITCH + i + 1];
                    float b0 = Cs[r*CS_PITCH + i + 64], b1 = Cs[r*CS_PITCH + i + 65];
                    float sn0 = g_rsin[sq*64 + i], sn1 = g_rsin[sq*64 + i + 1];
                    float cc0 = g_rcos[sq*64 + i], cc1 = g_rcos[sq*64 + i + 1];
                    split_pack(a0*cc0 - b0*sn0, a1*cc1 - b1*sn1, hA[j], lA[j]);
                    split_pack(b0*cc0 + a0*sn0, b1*cc1 + a1*sn1, hB[j], lB[j]);
                }
                *(uint4*)(Hdst + dst + i0)      = make_uint4(hA[0], hA[1], hA[2], hA[3]);
                *(uint4*)(Hdst + dst + i0 + 64) = make_uint4(hB[0], hB[1], hB[2], hB[3]);
                if (isQ) {
                    *(uint4*)(g_Ql + dst + i0)      = make_uint4(lA[0], lA[1], lA[2], lA[3]);
                    *(uint4*)(g_Ql + dst + i0 + 64) = make_uint4(lB[0], lB[1], lB[2], lB[3]);
                }
            }
        }
    } else if (mode == 2) {
        #pragma unroll
        for (int ma = 0; ma < 4; ma++)
            #pragma unroll
            for (int na = 0; na < 8; na++) {
                const int coln = warp_n*64 + na*8 + c0;
                #pragma unroll
                for (int half = 0; half < 2; half++) {
                    const int m = m0 + warp_m*64 + ma*16 + r0 + half*8;
                    const int bb = m >> 11, ss = m & (SEQ - 1);
                    size_t off = ((size_t)((bb*NHEAD + blockIdx.x)*SEQ + ss))*DHEAD + coln;
                    *(uint32_t*)(g_Vh + off) = pack_h(acc[ma][na][half*2], acc[ma][na][half*2+1]);
                }
            }
    } else {
        #pragma unroll
        for (int ma = 0; ma < 4; ma++)
            #pragma unroll
            for (int na = 0; na < 8; na++) {
                const int coln = warp_n*64 + na*8 + c0;
                #pragma unroll
                for (int half = 0; half < 2; half++) {
                    const int m = m0 + warp_m*64 + ma*16 + r0 + half*8;
                    *(float2*)(Cout + (size_t)m * EMBED + n0 + coln) =
                        make_float2(acc[ma][na][half*2], acc[ma][na][half*2+1]);
                }
            }
    }
}

// ---------------- FA2-style fp16 attention, 4-product ----------------
// scores = (Qh+Ql)·Kh ; PV = (Ph+Pl)·Vh.  KV stage = Kh,Vh only (2 tiles).
#define AP2    272
#define ATILE  (64*AP2)           // 17408
#define AST2   (2*ATILE)          // 34816 per KV stage
#define QLOFF  (2*AST2)           // 69632 (Ql tile: 128*AP2 = 34816)
#define ABIAS2 (QLOFF + 128*AP2)  // 104448
#define ATTN_SMEM (ABIAS2 + 512)  // 104960

__device__ __forceinline__ void attn_pf(uint32_t sb_stage,
    const __half* Kh, const __half* Vh, int k0, int tid)
{
    #pragma unroll
    for (int i = 0; i < 4; i++) {
        int idx = tid + i*256;
        int r = idx >> 4, c = idx & 15;
        uint32_t so = sb_stage + r*AP2 + c*16;
        size_t go = (size_t)(k0 + r) * DHEAD;
        CP_ASYNC16(so,         (const char*)(Kh + go) + c*16);
        CP_ASYNC16(so + ATILE, (const char*)(Vh + go) + c*16);
    }
}

__global__ void __launch_bounds__(256) attn_mma(const float* __restrict__ mask)
{
    extern __shared__ char smc[];
    const uint32_t sb = smem_to_u32(smc);
    const int tid = threadIdx.x, lane = tid & 31, wid = tid >> 5;
    const int qt = blockIdx.x, h = blockIdx.y, b = blockIdx.z;
    const int q0 = qt * 128;
    const size_t hb = (size_t)(b*NHEAD + h) * SEQ * DHEAD;
    const __half *Qhp = g_Qh + hb, *Qlp = g_Ql + hb;
    const __half *Khp = g_Kh + hb, *Vhp = g_Vh + hb;
    float* bias_sm = (float*)(smc + ABIAS2);

    // stage Qh through KV stage-0 area (exactly 128*AP2 bytes), Ql persistent
    #pragma unroll
    for (int i = 0; i < 8; i++) {
        int idx = tid + i*256;
        int r = idx >> 4, c = idx & 15;
        size_t go = (size_t)(q0 + r) * DHEAD;
        CP_ASYNC16(sb + r*AP2 + c*16,         (const char*)(Qhp + go) + c*16);
        CP_ASYNC16(sb + QLOFF + r*AP2 + c*16, (const char*)(Qlp + go) + c*16);
    }
    CP_COMMIT();
    CP_WAIT0();
    __syncthreads();

    const uint32_t qa_off = (uint32_t)((wid*16 + (lane & 15))*AP2 + (lane >> 4)*16);
    uint32_t Qf[8][4];
    #pragma unroll
    for (int t = 0; t < 8; t++) ldsm_x4(Qf[t], sb + qa_off + t*32);
    __syncthreads();

    attn_pf(sb, Khp, Vhp, 0, tid);
    if (tid < 64) bias_sm[tid] = (1.0f - mask[b*SEQ + tid]) * -1e9f;
    CP_COMMIT();

    float O[16][4];
    #pragma unroll
    for (int j = 0; j < 16; j++)
        #pragma unroll
        for (int r = 0; r < 4; r++) O[j][r] = 0.f;
    float m_a = -1e30f, m_b = -1e30f, l_a = 0.f, l_b = 0.f;
    const float scale = 0.08838834764831845f;
    const int q_a = q0 + wid*16 + (lane >> 2);
    const int klo = 2*(lane & 3);
    const int nkt = 2*qt + 2;

    for (int kt = 0; kt < nkt; kt++) {
        const int stage = kt & 1;
        if (kt + 1 < nkt) {
            attn_pf(sb + (stage^1)*AST2, Khp, Vhp, (kt+1)*64, tid);
            if (tid < 64) bias_sm[(stage^1)*64 + tid] = (1.0f - mask[b*SEQ + (kt+1)*64 + tid]) * -1e9f;
        }
        CP_COMMIT();
        CP_WAIT1();
        __syncthreads();

        const uint32_t ss = sb + stage*AST2;
        float s[8][4];
        #pragma unroll
        for (int j = 0; j < 8; j++)
            #pragma unroll
            for (int r = 0; r < 4; r++) s[j][r] = 0.f;

        // ---- scores: (Qh+Ql)·Kh ----
        #pragma unroll
        for (int t = 0; t < 8; t++) {
            uint32_t Al4[4];
            ldsm_x4(Al4, sb + QLOFF + qa_off + t*32);
            uint32_t Kh4[4][4];
            #pragma unroll
            for (int g = 0; g < 4; g++) {
                uint32_t Baddr = ss + (g*16 + (lane & 7) + ((lane >> 4) << 3))*AP2
                               + t*32 + ((lane >> 3) & 1)*16;
                ldsm_x4(Kh4[g], Baddr);
            }
            #pragma unroll
            for (int j = 0; j < 8; j++) mma_f16(s[j], Qf[t], &Kh4[j>>1][(j&1)*2]);
            #pragma unroll
            for (int j = 0; j < 8; j++) mma_f16(s[j], Al4,   &Kh4[j>>1][(j&1)*2]);
        }

        // ---- online softmax ----
        const float* bp = bias_sm + stage*64;
        const bool diag = (kt >= 2*qt);
        float tmax_a = -1e30f, tmax_b = -1e30f;
        #pragma unroll
        for (int j = 0; j < 8; j++) {
            int kk = 8*j + klo;
            float b0 = bp[kk], b1 = bp[kk+1];
            s[j][0] = s[j][0]*scale + b0;  s[j][1] = s[j][1]*scale + b1;
            s[j][2] = s[j][2]*scale + b0;  s[j][3] = s[j][3]*scale + b1;
            if (diag) {
                int kg = kt*64 + kk;
                if (kg   > q_a)   s[j][0] = -1e30f;
                if (kg+1 > q_a)   s[j][1] = -1e30f;
                if (kg   > q_a+8) s[j][2] = -1e30f;
                if (kg+1 > q_a+8) s[j][3] = -1e30f;
            }
            tmax_a = fmaxf(tmax_a, fmaxf(s[j][0], s[j][1]));
            tmax_b = fmaxf(tmax_b, fmaxf(s[j][2], s[j][3]));
        }
        tmax_a = fmaxf(tmax_a, __shfl_xor_sync(0xffffffffu, tmax_a, 1));
        tmax_a = fmaxf(tmax_a, __shfl_xor_sync(0xffffffffu, tmax_a, 2));
        tmax_b = fmaxf(tmax_b, __shfl_xor_sync(0xffffffffu, tmax_b, 1));
        tmax_b = fmaxf(tmax_b, __shfl_xor_sync(0xffffffffu, tmax_b, 2));
        float mn_a = fmaxf(m_a, tmax_a), mn_b = fmaxf(m_b, tmax_b);
        float ca = __expf(m_a - mn_a), cb = __expf(m_b - mn_b);
        m_a = mn_a; m_b = mn_b;
        float sum_a = 0.f, sum_b = 0.f;
        #pragma unroll
        for (int j = 0; j < 8; j++) {
            s[j][0] = __expf(s[j][0] - mn_a);  s[j][1] = __expf(s[j][1] - mn_a);
            s[j][2] = __expf(s[j][2] - mn_b);  s[j][3] = __expf(s[j][3] - mn_b);
            sum_a += s[j][0] + s[j][1];
            sum_b += s[j][2] + s[j][3];
        }
        sum_a += __shfl_xor_sync(0xffffffffu, sum_a, 1);
        sum_a += __shfl_xor_sync(0xffffffffu, sum_a, 2);
        sum_b += __shfl_xor_sync(0xffffffffu, sum_b, 1);
        sum_b += __shfl_xor_sync(0xffffffffu, sum_b, 2);
        l_a = l_a*ca + sum_a;
        l_b = l_b*cb + sum_b;
        #pragma unroll
        for (int j = 0; j < 16; j++) {
            O[j][0] *= ca; O[j][1] *= ca; O[j][2] *= cb; O[j][3] *= cb;
        }

        // ---- PV: (Ph+Pl)·Vh ----
        #pragma unroll
        for (int t = 0; t < 4; t++) {
            uint32_t aH[4], aL[4];
            split_pack(s[2*t][0],   s[2*t][1],   aH[0], aL[0]);
            split_pack(s[2*t][2],   s[2*t][3],   aH[1], aL[1]);
            split_pack(s[2*t+1][0], s[2*t+1][1], aH[2], aL[2]);
            split_pack(s[2*t+1][2], s[2*t+1][3], aH[3], aL[3]);
            #pragma unroll
            for (int g = 0; g < 8; g++) {
                uint32_t Baddr = ss + ATILE
                               + (t*16 + (lane & 7) + ((lane >> 3) & 1)*8)*AP2
                               + g*32 + (lane >> 4)*16;
                uint32_t Vh4[4];
                ldsm_x4_t(Vh4, Baddr);
                mma_f16(O[2*g],   aH, Vh4);     mma_f16(O[2*g+1], aH, Vh4+2);
                mma_f16(O[2*g],   aL, Vh4);     mma_f16(O[2*g+1], aL, Vh4+2);
            }
        }
        __syncthreads();
    }

    // ---- epilogue: write fp16 hi/lo ctx ----
    const float ia = 1.0f / l_a, ib = 1.0f / l_b;
    const size_t ra = (size_t)(b*SEQ + q0 + wid*16 + (lane >> 2));
    const size_t oa = ra*EMBED + h*DHEAD + klo;
    const size_t ob = oa + 8*(size_t)EMBED;
    #pragma unroll
    for (int j = 0; j < 16; j++) {
        uint32_t hi, lo;
        split_pack(O[j][0]*ia, O[j][1]*ia, hi, lo);
        *(uint32_t*)(g_ch + oa + 8*j) = hi;
        *(uint32_t*)(g_cl + oa + 8*j) = lo;
        split_pack(O[j][2]*ib, O[j][3]*ib, hi, lo);
        *(uint32_t*)(g_ch + ob + 8*j) = hi;
        *(uint32_t*)(g_cl + ob + 8*j) = lo;
    }
}

// ---------------- launch ----------------
extern "C" void kernel_launch(void* const* d_in, const int* in_sizes, int n_in,
                              void* d_out, int out_size)
{
    (void)in_sizes; (void)n_in; (void)out_size;
    const float* x    = (const float*)d_in[0];
    const float* mask = (const float*)d_in[1];
    const float* Wq   = (const float*)d_in[2];
    const float* Wk   = (const float*)d_in[3];
    const float* Wv   = (const float*)d_in[4];
    const float* Wo   = (const float*)d_in[5];
    float* out        = (float*)d_out;

    cudaFuncSetAttribute(gemm_mma, cudaFuncAttributeMaxDynamicSharedMemorySize, GEMM_SMEM);
    cudaFuncSetAttribute(attn_mma, cudaFuncAttributeMaxDynamicSharedMemorySize, ATTN_SMEM);

    const int n4x = MTOT*EMBED/4;
    const int n4w = EMBED*EMBED/4;

    split_kernel<<<(n4x+255)/256, 256>>>(x, 0, n4x);
    split_kernel<<<(n4w+255)/256, 256>>>(Wq, 1, n4w);
    split_kernel<<<(n4w+255)/256, 256>>>(Wk, 2, n4w);
    split_kernel<<<(n4w+255)/256, 256>>>(Wv, 3, n4w);
    split_kernel<<<(n4w+255)/256, 256>>>(Wo, 4, n4w);

    rope_table<<<(SEQ*64)/256, 256>>>();

    dim3 ggrid(EMBED/128, MTOT/128);
    gemm_mma<<<ggrid, 128, GEMM_SMEM>>>(nullptr, 0);
    gemm_mma<<<ggrid, 128, GEMM_SMEM>>>(nullptr, 1);
    gemm_mma<<<ggrid, 128, GEMM_SMEM>>>(nullptr, 2);

    attn_mma<<<dim3(SEQ/128, NHEAD, BATCH), 256, ATTN_SMEM>>>(mask);

    gemm_mma<<<ggrid, 128, GEMM_SMEM>>>(out, 3);
}

// round 12
// speedup vs baseline: 6.9453x; 1.3813x over previous
#include <cuda_runtime.h>
#include <cuda_fp16.h>
#include <math.h>
#include <stdint.h>

#define EMBED 2048
#define SEQ   2048
#define NHEAD 16
#define DHEAD 128
#define BATCH 2
#define MTOT  (BATCH*SEQ)   // 4096

// ---------------- static device scratch (fp16) ----------------
__device__ __half g_xh[MTOT*EMBED];
__device__ __half g_Wh[4*EMBED*EMBED];
__device__ __half g_ch[MTOT*EMBED];
__device__ __half g_Qh[BATCH*NHEAD*SEQ*DHEAD];
__device__ __half g_Ql[BATCH*NHEAD*SEQ*DHEAD];
__device__ __half g_Kh[BATCH*NHEAD*SEQ*DHEAD];
__device__ __half g_Vh[BATCH*NHEAD*SEQ*DHEAD];
__device__ float g_rsin[SEQ*64];
__device__ float g_rcos[SEQ*64];

// ---------------- baseline-PTX helpers ----------------
__device__ __forceinline__ uint32_t smem_to_u32(const void* p) {
    uint32_t a;
    asm("{ .reg .u64 t; cvta.to.shared.u64 t, %1; cvt.u32.u64 %0, t; }" : "=r"(a) : "l"(p));
    return a;
}
#define CP_ASYNC16(saddr, gptr) \
    asm volatile("cp.async.cg.shared.global [%0], [%1], 16;" :: "r"(saddr), "l"(gptr) : "memory")
#define CP_COMMIT() asm volatile("cp.async.commit_group;" ::: "memory")
#define CP_WAIT1()  asm volatile("cp.async.wait_group 1;" ::: "memory")
#define CP_WAIT0()  asm volatile("cp.async.wait_group 0;" ::: "memory")

__device__ __forceinline__ void ldsm_x4(uint32_t* r, uint32_t addr) {
    asm volatile("ldmatrix.sync.aligned.m8n8.x4.shared.b16 {%0,%1,%2,%3}, [%4];"
                 : "=r"(r[0]), "=r"(r[1]), "=r"(r[2]), "=r"(r[3]) : "r"(addr));
}
__device__ __forceinline__ void ldsm_x4_t(uint32_t* r, uint32_t addr) {
    asm volatile("ldmatrix.sync.aligned.m8n8.x4.trans.shared.b16 {%0,%1,%2,%3}, [%4];"
                 : "=r"(r[0]), "=r"(r[1]), "=r"(r[2]), "=r"(r[3]) : "r"(addr));
}
__device__ __forceinline__ void mma_f16(float* c, const uint32_t* a, const uint32_t* b) {
    asm volatile("mma.sync.aligned.m16n8k16.row.col.f32.f16.f16.f32 "
                 "{%0,%1,%2,%3}, {%4,%5,%6,%7}, {%8,%9}, {%0,%1,%2,%3};"
                 : "+f"(c[0]), "+f"(c[1]), "+f"(c[2]), "+f"(c[3])
                 : "r"(a[0]), "r"(a[1]), "r"(a[2]), "r"(a[3]), "r"(b[0]), "r"(b[1]));
}
__device__ __forceinline__ void split_pack(float x, float y, uint32_t& hi, uint32_t& lo) {
    __half hx = __float2half_rn(x), hy = __float2half_rn(y);
    hi = ((uint32_t)__half_as_ushort(hy) << 16) | __half_as_ushort(hx);
    __half lx = __float2half_rn(x - __half2float(hx));
    __half ly = __float2half_rn(y - __half2float(hy));
    lo = ((uint32_t)__half_as_ushort(ly) << 16) | __half_as_ushort(lx);
}
__device__ __forceinline__ uint32_t pack_h(float x, float y) {
    return ((uint32_t)__half_as_ushort(__float2half_rn(y)) << 16)
         | __half_as_ushort(__float2half_rn(x));
}

// ---------------- split: f32 -> fp16 hi only ----------------
// which: 0=x, 1..4=Wq/Wk/Wv/Wo
__global__ void __launch_bounds__(256) split_kernel(const float* __restrict__ src,
                                                    int which, int n4)
{
    int idx = blockIdx.x * 256 + threadIdx.x;
    if (idx >= n4) return;

    float4 v = ((const float4*)src)[idx];
    uint2 hp = make_uint2(pack_h(v.x, v.y), pack_h(v.z, v.w));
    __half* hi = (which == 0) ? g_xh : (g_Wh + (size_t)(which - 1) * EMBED * EMBED);
    *(uint2*)((uint32_t*)hi + idx*2) = hp;
}

// ---------------- RoPE table ----------------
__global__ void __launch_bounds__(256) rope_table()
{
    int idx = blockIdx.x * 256 + threadIdx.x;
    int i = idx & 63, s = idx >> 6;
    float freq = (float)pow(10000.0, -(double)i / 64.0);
    float ang  = (float)s * freq;
    double sn, cs;
    sincos((double)ang, &sn, &cs);
    g_rsin[idx] = (float)sn;
    g_rcos[idx] = (float)cs;
}

// ---------------- mma.sync fp16 1-product GEMM: C = Ah * Wh^T ----------------
// mode 0: x->g_Qh/g_Ql (RoPE fused)   mode 1: x->g_Kh (RoPE fused, hi only)
// mode 2: x->g_Vh (hi only)           mode 3: ctx(ch)->Cout (f32)
#define GT_PITCH 80
#define GT_TILE  (128*GT_PITCH)      // 10240
#define GT_STAGE (2*GT_TILE)         // 20480
#define CS_PITCH 134
#define GEMM_SMEM (128*CS_PITCH*4)   // 68608 >= 2*GT_STAGE (40960)

__global__ void __launch_bounds__(128) gemm_mma(float* __restrict__ Cout, int mode)
{
    extern __shared__ char smc[];
    const uint32_t sbase = smem_to_u32(smc);
    const int tid  = threadIdx.x;
    const int lane = tid & 31;
    const int wid  = tid >> 5;
    const int warp_m = wid >> 1;
    const int warp_n = wid & 1;
    const int n0 = blockIdx.x * 128;
    const int m0 = blockIdx.y * 128;

    const __half* srcs[2];
    srcs[0] = ((mode == 3) ? g_ch : g_xh);
    srcs[1] = g_Wh + (size_t)mode * EMBED * EMBED;
    const int base_row[2] = {m0, n0};

    const int seg = tid & 3;
    const int rb  = tid >> 2;

    const uint32_t a_off = (uint32_t)((warp_m*64 + (lane & 15)) * GT_PITCH + (lane >> 4) * 16);
    const uint32_t b_off = (uint32_t)(((lane & 7) + (lane >> 4) * 8 + warp_n*64) * GT_PITCH
                                      + ((lane >> 3) & 1) * 16);

    float acc[4][8][4];
    #pragma unroll
    for (int i = 0; i < 4; i++)
        #pragma unroll
        for (int j = 0; j < 8; j++)
            #pragma unroll
            for (int r = 0; r < 4; r++) acc[i][j][r] = 0.f;

    #pragma unroll
    for (int t = 0; t < 2; t++)
        #pragma unroll
        for (int i = 0; i < 4; i++) {
            int row = rb + i*32;
            const __half* g = srcs[t] + (size_t)(base_row[t] + row) * EMBED + seg*8;
            CP_ASYNC16(sbase + t*GT_TILE + row*GT_PITCH + seg*16, g);
        }
    CP_COMMIT();

    for (int s = 0; s < EMBED/32; s++) {
        if (s < EMBED/32 - 1) {
            const uint32_t sb = sbase + ((s+1) & 1) * GT_STAGE;
            const int k0 = (s+1) * 32;
            #pragma unroll
            for (int t = 0; t < 2; t++)
                #pragma unroll
                for (int i = 0; i < 4; i++) {
                    int row = rb + i*32;
                    const __half* g = srcs[t] + (size_t)(base_row[t] + row) * EMBED + k0 + seg*8;
                    CP_ASYNC16(sb + t*GT_TILE + row*GT_PITCH + seg*16, g);
                }
        }
        CP_COMMIT();
        CP_WAIT1();
        __syncthreads();

        const uint32_t sb = sbase + (s & 1) * GT_STAGE;
        #pragma unroll
        for (int kk = 0; kk < 2; kk++) {
            const uint32_t ko = kk * 32;
            uint32_t Af[4][4], Bf[4][4];
            #pragma unroll
            for (int ma = 0; ma < 4; ma++)
                ldsm_x4(Af[ma], sb + 0*GT_TILE + a_off + ko + ma*16*GT_PITCH);
            #pragma unroll
            for (int g = 0; g < 4; g++)
                ldsm_x4(Bf[g], sb + 1*GT_TILE + b_off + ko + g*16*GT_PITCH);
            #pragma unroll
            for (int ma = 0; ma < 4; ma++)
                #pragma unroll
                for (int na = 0; na < 8; na++)
                    mma_f16(acc[ma][na], Af[ma], &Bf[na >> 1][(na & 1) * 2]);
        }
        __syncthreads();
    }

    const int r0 = lane >> 2;
    const int c0 = (lane & 3) * 2;

    if (mode <= 1) {
        // ---- fused RoPE epilogue ----
        float* Cs = (float*)smc;
        #pragma unroll
        for (int ma = 0; ma < 4; ma++)
            #pragma unroll
            for (int na = 0; na < 8; na++)
                #pragma unroll
                for (int half = 0; half < 2; half++) {
                    int rl = warp_m*64 + ma*16 + r0 + half*8;
                    int cl = warp_n*64 + na*8 + c0;
                    Cs[rl*CS_PITCH + cl]     = acc[ma][na][half*2];
                    Cs[rl*CS_PITCH + cl + 1] = acc[ma][na][half*2+1];
                }
        __syncthreads();

        const bool isQ = (mode == 0);
        __half* Hdst = isQ ? g_Qh : g_Kh;
        #pragma unroll
        for (int pass = 0; pass < 4; pass++) {
            const int r = pass*32 + (tid >> 2);
            const int m = m0 + r;
            const int bb = m >> 11, sq = m & (SEQ - 1);
            const size_t dst = ((size_t)((bb*NHEAD + blockIdx.x)*SEQ + sq))*DHEAD;
            const int g0 = (tid & 3) * 16;
            #pragma unroll
            for (int c = 0; c < 2; c++) {
                const int i0 = g0 + c*8;
                uint32_t hA[4], lA[4], hB[4], lB[4];
                #pragma unroll
                for (int j = 0; j < 4; j++) {
                    int i = i0 + 2*j;
                    float a0 = Cs[r*CS_PITCH + i],      a1 = Cs[r*CS_PITCH + i + 1];
                    float b0 = Cs[r*CS_PITCH + i + 64], b1 = Cs[r*CS_PITCH + i + 65];
                    float sn0 = g_rsin[sq*64 + i], sn1 = g_rsin[sq*64 + i + 1];
                    float cc0 = g_rcos[sq*64 + i], cc1 = g_rcos[sq*64 + i + 1];
                    split_pack(a0*cc0 - b0*sn0, a1*cc1 - b1*sn1, hA[j], lA[j]);
                    split_pack(b0*cc0 + a0*sn0, b1*cc1 + a1*sn1, hB[j], lB[j]);
                }
                *(uint4*)(Hdst + dst + i0)      = make_uint4(hA[0], hA[1], hA[2], hA[3]);
                *(uint4*)(Hdst + dst + i0 + 64) = make_uint4(hB[0], hB[1], hB[2], hB[3]);
                if (isQ) {
                    *(uint4*)(g_Ql + dst + i0)      = make_uint4(lA[0], lA[1], lA[2], lA[3]);
                    *(uint4*)(g_Ql + dst + i0 + 64) = make_uint4(lB[0], lB[1], lB[2], lB[3]);
                }
            }
        }
    } else if (mode == 2) {
        #pragma unroll
        for (int ma = 0; ma < 4; ma++)
            #pragma unroll
            for (int na = 0; na < 8; na++) {
                const int coln = warp_n*64 + na*8 + c0;
                #pragma unroll
                for (int half = 0; half < 2; half++) {
                    const int m = m0 + warp_m*64 + ma*16 + r0 + half*8;
                    const int bb = m >> 11, ss = m & (SEQ - 1);
                    size_t off = ((size_t)((bb*NHEAD + blockIdx.x)*SEQ + ss))*DHEAD + coln;
                    *(uint32_t*)(g_Vh + off) = pack_h(acc[ma][na][half*2], acc[ma][na][half*2+1]);
                }
            }
    } else {
        #pragma unroll
        for (int ma = 0; ma < 4; ma++)
            #pragma unroll
            for (int na = 0; na < 8; na++) {
                const int coln = warp_n*64 + na*8 + c0;
                #pragma unroll
                for (int half = 0; half < 2; half++) {
                    const int m = m0 + warp_m*64 + ma*16 + r0 + half*8;
                    *(float2*)(Cout + (size_t)m * EMBED + n0 + coln) =
                        make_float2(acc[ma][na][half*2], acc[ma][na][half*2+1]);
                }
            }
    }
}

// ---------------- FA2-style fp16 attention, 4-product (validated R11) ----------
// scores = (Qh+Ql)·Kh ; PV = (Ph+Pl)·Vh.  KV stage = Kh,Vh (2 tiles).
#define AP2    272
#define ATILE  (64*AP2)           // 17408
#define AST2   (2*ATILE)          // 34816 per KV stage
#define QLOFF  (2*AST2)           // 69632
#define ABIAS2 (QLOFF + 128*AP2)  // 104448
#define ATTN_SMEM (ABIAS2 + 512)  // 104960

__device__ __forceinline__ void attn_pf(uint32_t sb_stage,
    const __half* Kh, const __half* Vh, int k0, int tid)
{
    #pragma unroll
    for (int i = 0; i < 4; i++) {
        int idx = tid + i*256;
        int r = idx >> 4, c = idx & 15;
        uint32_t so = sb_stage + r*AP2 + c*16;
        size_t go = (size_t)(k0 + r) * DHEAD;
        CP_ASYNC16(so,         (const char*)(Kh + go) + c*16);
        CP_ASYNC16(so + ATILE, (const char*)(Vh + go) + c*16);
    }
}

__global__ void __launch_bounds__(256) attn_mma(const float* __restrict__ mask)
{
    extern __shared__ char smc[];
    const uint32_t sb = smem_to_u32(smc);
    const int tid = threadIdx.x, lane = tid & 31, wid = tid >> 5;
    const int qt = blockIdx.x, h = blockIdx.y, b = blockIdx.z;
    const int q0 = qt * 128;
    const size_t hb = (size_t)(b*NHEAD + h) * SEQ * DHEAD;
    const __half *Qhp = g_Qh + hb, *Qlp = g_Ql + hb;
    const __half *Khp = g_Kh + hb, *Vhp = g_Vh + hb;
    float* bias_sm = (float*)(smc + ABIAS2);

    #pragma unroll
    for (int i = 0; i < 8; i++) {
        int idx = tid + i*256;
        int r = idx >> 4, c = idx & 15;
        size_t go = (size_t)(q0 + r) * DHEAD;
        CP_ASYNC16(sb + r*AP2 + c*16,         (const char*)(Qhp + go) + c*16);
        CP_ASYNC16(sb + QLOFF + r*AP2 + c*16, (const char*)(Qlp + go) + c*16);
    }
    CP_COMMIT();
    CP_WAIT0();
    __syncthreads();

    const uint32_t qa_off = (uint32_t)((wid*16 + (lane & 15))*AP2 + (lane >> 4)*16);
    uint32_t Qf[8][4];
    #pragma unroll
    for (int t = 0; t < 8; t++) ldsm_x4(Qf[t], sb + qa_off + t*32);
    __syncthreads();

    attn_pf(sb, Khp, Vhp, 0, tid);
    if (tid < 64) bias_sm[tid] = (1.0f - mask[b*SEQ + tid]) * -1e9f;
    CP_COMMIT();

    float O[16][4];
    #pragma unroll
    for (int j = 0; j < 16; j++)
        #pragma unroll
        for (int r = 0; r < 4; r++) O[j][r] = 0.f;
    float m_a = -1e30f, m_b = -1e30f, l_a = 0.f, l_b = 0.f;
    const float scale = 0.08838834764831845f;
    const int q_a = q0 + wid*16 + (lane >> 2);
    const int klo = 2*(lane & 3);
    const int nkt = 2*qt + 2;

    for (int kt = 0; kt < nkt; kt++) {
        const int stage = kt & 1;
        if (kt + 1 < nkt) {
            attn_pf(sb + (stage^1)*AST2, Khp, Vhp, (kt+1)*64, tid);
            if (tid < 64) bias_sm[(stage^1)*64 + tid] = (1.0f - mask[b*SEQ + (kt+1)*64 + tid]) * -1e9f;
        }
        CP_COMMIT();
        CP_WAIT1();
        __syncthreads();

        const uint32_t ss = sb + stage*AST2;
        float s[8][4];
        #pragma unroll
        for (int j = 0; j < 8; j++)
            #pragma unroll
            for (int r = 0; r < 4; r++) s[j][r] = 0.f;

        // ---- scores: (Qh+Ql)·Kh ----
        #pragma unroll
        for (int t = 0; t < 8; t++) {
            uint32_t Al4[4];
            ldsm_x4(Al4, sb + QLOFF + qa_off + t*32);
            uint32_t Kh4[4][4];
            #pragma unroll
            for (int g = 0; g < 4; g++) {
                uint32_t Baddr = ss + (g*16 + (lane & 7) + ((lane >> 4) << 3))*AP2
                               + t*32 + ((lane >> 3) & 1)*16;
                ldsm_x4(Kh4[g], Baddr);
            }
            #pragma unroll
            for (int j = 0; j < 8; j++) mma_f16(s[j], Qf[t], &Kh4[j>>1][(j&1)*2]);
            #pragma unroll
            for (int j = 0; j < 8; j++) mma_f16(s[j], Al4,   &Kh4[j>>1][(j&1)*2]);
        }

        // ---- online softmax ----
        const float* bp = bias_sm + stage*64;
        const bool diag = (kt >= 2*qt);
        float tmax_a = -1e30f, tmax_b = -1e30f;
        #pragma unroll
        for (int j = 0; j < 8; j++) {
            int kk = 8*j + klo;
            float b0 = bp[kk], b1 = bp[kk+1];
            s[j][0] = s[j][0]*scale + b0;  s[j][1] = s[j][1]*scale + b1;
            s[j][2] = s[j][2]*scale + b0;  s[j][3] = s[j][3]*scale + b1;
            if (diag) {
                int kg = kt*64 + kk;
                if (kg   > q_a)   s[j][0] = -1e30f;
                if (kg+1 > q_a)   s[j][1] = -1e30f;
                if (kg   > q_a+8) s[j][2] = -1e30f;
                if (kg+1 > q_a+8) s[j][3] = -1e30f;
            }
            tmax_a = fmaxf(tmax_a, fmaxf(s[j][0], s[j][1]));
            tmax_b = fmaxf(tmax_b, fmaxf(s[j][2], s[j][3]));
        }
        tmax_a = fmaxf(tmax_a, __shfl_xor_sync(0xffffffffu, tmax_a, 1));
        tmax_a = fmaxf(tmax_a, __shfl_xor_sync(0xffffffffu, tmax_a, 2));
        tmax_b = fmaxf(tmax_b, __shfl_xor_sync(0xffffffffu, tmax_b, 1));
        tmax_b = fmaxf(tmax_b, __shfl_xor_sync(0xffffffffu, tmax_b, 2));
        float mn_a = fmaxf(m_a, tmax_a), mn_b = fmaxf(m_b, tmax_b);
        float ca = __expf(m_a - mn_a), cb = __expf(m_b - mn_b);
        m_a = mn_a; m_b = mn_b;
        float sum_a = 0.f, sum_b = 0.f;
        #pragma unroll
        for (int j = 0; j < 8; j++) {
            s[j][0] = __expf(s[j][0] - mn_a);  s[j][1] = __expf(s[j][1] - mn_a);
            s[j][2] = __expf(s[j][2] - mn_b);  s[j][3] = __expf(s[j][3] - mn_b);
            sum_a += s[j][0] + s[j][1];
            sum_b += s[j][2] + s[j][3];
        }
        sum_a += __shfl_xor_sync(0xffffffffu, sum_a, 1);
        sum_a += __shfl_xor_sync(0xffffffffu, sum_a, 2);
        sum_b += __shfl_xor_sync(0xffffffffu, sum_b, 1);
        sum_b += __shfl_xor_sync(0xffffffffu, sum_b, 2);
        l_a = l_a*ca + sum_a;
        l_b = l_b*cb + sum_b;
        #pragma unroll
        for (int j = 0; j < 16; j++) {
            O[j][0] *= ca; O[j][1] *= ca; O[j][2] *= cb; O[j][3] *= cb;
        }

        // ---- PV: (Ph+Pl)·Vh ----
        #pragma unroll
        for (int t = 0; t < 4; t++) {
            uint32_t aH[4], aL[4];
            split_pack(s[2*t][0],   s[2*t][1],   aH[0], aL[0]);
            split_pack(s[2*t][2],   s[2*t][3],   aH[1], aL[1]);
            split_pack(s[2*t+1][0], s[2*t+1][1], aH[2], aL[2]);
            split_pack(s[2*t+1][2], s[2*t+1][3], aH[3], aL[3]);
            #pragma unroll
            for (int g = 0; g < 8; g++) {
                uint32_t Baddr = ss + ATILE
                               + (t*16 + (lane & 7) + ((lane >> 3) & 1)*8)*AP2
                               + g*32 + (lane >> 4)*16;
                uint32_t Vh4[4];
                ldsm_x4_t(Vh4, Baddr);
                mma_f16(O[2*g],   aH, Vh4);     mma_f16(O[2*g+1], aH, Vh4+2);
                mma_f16(O[2*g],   aL, Vh4);     mma_f16(O[2*g+1], aL, Vh4+2);
            }
        }
        __syncthreads();
    }

    // ---- epilogue: write fp16 hi ctx ----
    const float ia = 1.0f / l_a, ib = 1.0f / l_b;
    const size_t ra = (size_t)(b*SEQ + q0 + wid*16 + (lane >> 2));
    const size_t oa = ra*EMBED + h*DHEAD + klo;
    const size_t ob = oa + 8*(size_t)EMBED;
    #pragma unroll
    for (int j = 0; j < 16; j++) {
        *(uint32_t*)(g_ch + oa + 8*j) = pack_h(O[j][0]*ia, O[j][1]*ia);
        *(uint32_t*)(g_ch + ob + 8*j) = pack_h(O[j][2]*ib, O[j][3]*ib);
    }
}

// ---------------- launch ----------------
extern "C" void kernel_launch(void* const* d_in, const int* in_sizes, int n_in,
                              void* d_out, int out_size)
{
    (void)in_sizes; (void)n_in; (void)out_size;
    const float* x    = (const float*)d_in[0];
    const float* mask = (const float*)d_in[1];
    const float* Wq   = (const float*)d_in[2];
    const float* Wk   = (const float*)d_in[3];
    const float* Wv   = (const float*)d_in[4];
    const float* Wo   = (const float*)d_in[5];
    float* out        = (float*)d_out;

    cudaFuncSetAttribute(gemm_mma, cudaFuncAttributeMaxDynamicSharedMemorySize, GEMM_SMEM);
    cudaFuncSetAttribute(attn_mma, cudaFuncAttributeMaxDynamicSharedMemorySize, ATTN_SMEM);

    const int n4x = MTOT*EMBED/4;
    const int n4w = EMBED*EMBED/4;

    split_kernel<<<(n4x+255)/256, 256>>>(x, 0, n4x);
    split_kernel<<<(n4w+255)/256, 256>>>(Wq, 1, n4w);
    split_kernel<<<(n4w+255)/256, 256>>>(Wk, 2, n4w);
    split_kernel<<<(n4w+255)/256, 256>>>(Wv, 3, n4w);
    split_kernel<<<(n4w+255)/256, 256>>>(Wo, 4, n4w);

    rope_table<<<(SEQ*64)/256, 256>>>();

    dim3 ggrid(EMBED/128, MTOT/128);
    gemm_mma<<<ggrid, 128, GEMM_SMEM>>>(nullptr, 0);
    gemm_mma<<<ggrid, 128, GEMM_SMEM>>>(nullptr, 1);
    gemm_mma<<<ggrid, 128, GEMM_SMEM>>>(nullptr, 2);

    attn_mma<<<dim3(SEQ/128, NHEAD, BATCH), 256, ATTN_SMEM>>>(mask);

    gemm_mma<<<ggrid, 128, GEMM_SMEM>>>(out, 3);
}

// round 14
// speedup vs baseline: 7.9216x; 1.1406x over previous
#include <cuda_runtime.h>
#include <cuda_fp16.h>
#include <math.h>
#include <stdint.h>

#define EMBED 2048
#define SEQ   2048
#define NHEAD 16
#define DHEAD 128
#define BATCH 2
#define MTOT  (BATCH*SEQ)   // 4096

// ---------------- static device scratch (fp16) ----------------
__device__ __half g_xh[MTOT*EMBED];
__device__ __half g_Wh[4*EMBED*EMBED];
__device__ __half g_ch[MTOT*EMBED];
__device__ __half g_Qh[BATCH*NHEAD*SEQ*DHEAD];
__device__ __half g_Kh[BATCH*NHEAD*SEQ*DHEAD];
__device__ __half g_Vh[BATCH*NHEAD*SEQ*DHEAD];
__device__ float g_rsin[SEQ*64];
__device__ float g_rcos[SEQ*64];

// ---------------- baseline-PTX helpers ----------------
__device__ __forceinline__ uint32_t smem_to_u32(const void* p) {
    uint32_t a;
    asm("{ .reg .u64 t; cvta.to.shared.u64 t, %1; cvt.u32.u64 %0, t; }" : "=r"(a) : "l"(p));
    return a;
}
#define CP_ASYNC16(saddr, gptr) \
    asm volatile("cp.async.cg.shared.global [%0], [%1], 16;" :: "r"(saddr), "l"(gptr) : "memory")
#define CP_COMMIT() asm volatile("cp.async.commit_group;" ::: "memory")
#define CP_WAIT1()  asm volatile("cp.async.wait_group 1;" ::: "memory")
#define CP_WAIT0()  asm volatile("cp.async.wait_group 0;" ::: "memory")

__device__ __forceinline__ void ldsm_x4(uint32_t* r, uint32_t addr) {
    asm volatile("ldmatrix.sync.aligned.m8n8.x4.shared.b16 {%0,%1,%2,%3}, [%4];"
                 : "=r"(r[0]), "=r"(r[1]), "=r"(r[2]), "=r"(r[3]) : "r"(addr));
}
__device__ __forceinline__ void ldsm_x4_t(uint32_t* r, uint32_t addr) {
    asm volatile("ldmatrix.sync.aligned.m8n8.x4.trans.shared.b16 {%0,%1,%2,%3}, [%4];"
                 : "=r"(r[0]), "=r"(r[1]), "=r"(r[2]), "=r"(r[3]) : "r"(addr));
}
__device__ __forceinline__ void mma_f16(float* c, const uint32_t* a, const uint32_t* b) {
    asm volatile("mma.sync.aligned.m16n8k16.row.col.f32.f16.f16.f32 "
                 "{%0,%1,%2,%3}, {%4,%5,%6,%7}, {%8,%9}, {%0,%1,%2,%3};"
                 : "+f"(c[0]), "+f"(c[1]), "+f"(c[2]), "+f"(c[3])
                 : "r"(a[0]), "r"(a[1]), "r"(a[2]), "r"(a[3]), "r"(b[0]), "r"(b[1]));
}
__device__ __forceinline__ void split_pack(float x, float y, uint32_t& hi, uint32_t& lo) {
    __half hx = __float2half_rn(x), hy = __float2half_rn(y);
    hi = ((uint32_t)__half_as_ushort(hy) << 16) | __half_as_ushort(hx);
    __half lx = __float2half_rn(x - __half2float(hx));
    __half ly = __float2half_rn(y - __half2float(hy));
    lo = ((uint32_t)__half_as_ushort(ly) << 16) | __half_as_ushort(lx);
}
__device__ __forceinline__ uint32_t pack_h(float x, float y) {
    return ((uint32_t)__half_as_ushort(__float2half_rn(y)) << 16)
         | __half_as_ushort(__float2half_rn(x));
}

// ---------------- split: f32 -> fp16 hi only ----------------
// which: 0=x, 1..4=Wq/Wk/Wv/Wo
__global__ void __launch_bounds__(256) split_kernel(const float* __restrict__ src,
                                                    int which, int n4)
{
    int idx = blockIdx.x * 256 + threadIdx.x;
    if (idx >= n4) return;

    float4 v = ((const float4*)src)[idx];
    uint2 hp = make_uint2(pack_h(v.x, v.y), pack_h(v.z, v.w));
    __half* hi = (which == 0) ? g_xh : (g_Wh + (size_t)(which - 1) * EMBED * EMBED);
    *(uint2*)((uint32_t*)hi + idx*2) = hp;
}

// ---------------- RoPE table ----------------
__global__ void __launch_bounds__(256) rope_table()
{
    int idx = blockIdx.x * 256 + threadIdx.x;
    int i = idx & 63, s = idx >> 6;
    float freq = (float)pow(10000.0, -(double)i / 64.0);
    float ang  = (float)s * freq;
    double sn, cs;
    sincos((double)ang, &sn, &cs);
    g_rsin[idx] = (float)sn;
    g_rcos[idx] = (float)cs;
}

// ---------------- mma.sync fp16 1-product GEMM: C = Ah * Wh^T ----------------
// mode = mode_base + blockIdx.z.
// mode 0: x->g_Qh (RoPE)  mode 1: x->g_Kh (RoPE)  mode 2: x->g_Vh  mode 3: ctx->Cout
#define GT_PITCH 80
#define GT_TILE  (128*GT_PITCH)      // 10240
#define GT_STAGE (2*GT_TILE)         // 20480
#define CS_PITCH 134
#define GEMM_SMEM (128*CS_PITCH*4)   // 68608 >= 2*GT_STAGE (40960)

__global__ void __launch_bounds__(128) gemm_mma(float* __restrict__ Cout, int mode_base)
{
    extern __shared__ char smc[];
    const uint32_t sbase = smem_to_u32(smc);
    const int tid  = threadIdx.x;
    const int lane = tid & 31;
    const int wid  = tid >> 5;
    const int warp_m = wid >> 1;
    const int warp_n = wid & 1;
    const int n0 = blockIdx.x * 128;
    const int m0 = blockIdx.y * 128;
    const int mode = mode_base + blockIdx.z;

    const __half* srcs[2];
    srcs[0] = ((mode == 3) ? g_ch : g_xh);
    srcs[1] = g_Wh + (size_t)mode * EMBED * EMBED;
    const int base_row[2] = {m0, n0};

    const int seg = tid & 3;
    const int rb  = tid >> 2;

    const uint32_t a_off = (uint32_t)((warp_m*64 + (lane & 15)) * GT_PITCH + (lane >> 4) * 16);
    const uint32_t b_off = (uint32_t)(((lane & 7) + (lane >> 4) * 8 + warp_n*64) * GT_PITCH
                                      + ((lane >> 3) & 1) * 16);

    float acc[4][8][4];
    #pragma unroll
    for (int i = 0; i < 4; i++)
        #pragma unroll
        for (int j = 0; j < 8; j++)
            #pragma unroll
            for (int r = 0; r < 4; r++) acc[i][j][r] = 0.f;

    #pragma unroll
    for (int t = 0; t < 2; t++)
        #pragma unroll
        for (int i = 0; i < 4; i++) {
            int row = rb + i*32;
            const __half* g = srcs[t] + (size_t)(base_row[t] + row) * EMBED + seg*8;
            CP_ASYNC16(sbase + t*GT_TILE + row*GT_PITCH + seg*16, g);
        }
    CP_COMMIT();

    for (int s = 0; s < EMBED/32; s++) {
        if (s < EMBED/32 - 1) {
            const uint32_t sb = sbase + ((s+1) & 1) * GT_STAGE;
            const int k0 = (s+1) * 32;
            #pragma unroll
            for (int t = 0; t < 2; t++)
                #pragma unroll
                for (int i = 0; i < 4; i++) {
                    int row = rb + i*32;
                    const __half* g = srcs[t] + (size_t)(base_row[t] + row) * EMBED + k0 + seg*8;
                    CP_ASYNC16(sb + t*GT_TILE + row*GT_PITCH + seg*16, g);
                }
        }
        CP_COMMIT();
        CP_WAIT1();
        __syncthreads();

        const uint32_t sb = sbase + (s & 1) * GT_STAGE;
        #pragma unroll
        for (int kk = 0; kk < 2; kk++) {
            const uint32_t ko = kk * 32;
            uint32_t Af[4][4], Bf[4][4];
            #pragma unroll
            for (int ma = 0; ma < 4; ma++)
                ldsm_x4(Af[ma], sb + 0*GT_TILE + a_off + ko + ma*16*GT_PITCH);
            #pragma unroll
            for (int g = 0; g < 4; g++)
                ldsm_x4(Bf[g], sb + 1*GT_TILE + b_off + ko + g*16*GT_PITCH);
            #pragma unroll
            for (int ma = 0; ma < 4; ma++)
                #pragma unroll
                for (int na = 0; na < 8; na++)
                    mma_f16(acc[ma][na], Af[ma], &Bf[na >> 1][(na & 1) * 2]);
        }
        __syncthreads();
    }

    const int r0 = lane >> 2;
    const int c0 = (lane & 3) * 2;

    if (mode <= 1) {
        // ---- fused RoPE epilogue: acc -> smem fp32 -> rotate -> fp16 hi ----
        float* Cs = (float*)smc;
        #pragma unroll
        for (int ma = 0; ma < 4; ma++)
            #pragma unroll
            for (int na = 0; na < 8; na++)
                #pragma unroll
                for (int half = 0; half < 2; half++) {
                    int rl = warp_m*64 + ma*16 + r0 + half*8;
                    int cl = warp_n*64 + na*8 + c0;
                    Cs[rl*CS_PITCH + cl]     = acc[ma][na][half*2];
                    Cs[rl*CS_PITCH + cl + 1] = acc[ma][na][half*2+1];
                }
        __syncthreads();

        __half* Hdst = (mode == 0) ? g_Qh : g_Kh;
        #pragma unroll
        for (int pass = 0; pass < 4; pass++) {
            const int r = pass*32 + (tid >> 2);
            const int m = m0 + r;
            const int bb = m >> 11, sq = m & (SEQ - 1);
            const size_t dst = ((size_t)((bb*NHEAD + blockIdx.x)*SEQ + sq))*DHEAD;
            const int g0 = (tid & 3) * 16;
            #pragma unroll
            for (int c = 0; c < 2; c++) {
                const int i0 = g0 + c*8;
                uint32_t hA[4], hB[4];
                #pragma unroll
                for (int j = 0; j < 4; j++) {
                    int i = i0 + 2*j;
                    float a0 = Cs[r*CS_PITCH + i],      a1 = Cs[r*CS_PITCH + i + 1];
                    float b0 = Cs[r*CS_PITCH + i + 64], b1 = Cs[r*CS_PITCH + i + 65];
                    float sn0 = g_rsin[sq*64 + i], sn1 = g_rsin[sq*64 + i + 1];
                    float cc0 = g_rcos[sq*64 + i], cc1 = g_rcos[sq*64 + i + 1];
                    hA[j] = pack_h(a0*cc0 - b0*sn0, a1*cc1 - b1*sn1);
                    hB[j] = pack_h(b0*cc0 + a0*sn0, b1*cc1 + a1*sn1);
                }
                *(uint4*)(Hdst + dst + i0)      = make_uint4(hA[0], hA[1], hA[2], hA[3]);
                *(uint4*)(Hdst + dst + i0 + 64) = make_uint4(hB[0], hB[1], hB[2], hB[3]);
            }
        }
    } else if (mode == 2) {
        #pragma unroll
        for (int ma = 0; ma < 4; ma++)
            #pragma unroll
            for (int na = 0; na < 8; na++) {
                const int coln = warp_n*64 + na*8 + c0;
                #pragma unroll
                for (int half = 0; half < 2; half++) {
                    const int m = m0 + warp_m*64 + ma*16 + r0 + half*8;
                    const int bb = m >> 11, ss = m & (SEQ - 1);
                    size_t off = ((size_t)((bb*NHEAD + blockIdx.x)*SEQ + ss))*DHEAD + coln;
                    *(uint32_t*)(g_Vh + off) = pack_h(acc[ma][na][half*2], acc[ma][na][half*2+1]);
                }
            }
    } else {
        #pragma unroll
        for (int ma = 0; ma < 4; ma++)
            #pragma unroll
            for (int na = 0; na < 8; na++) {
                const int coln = warp_n*64 + na*8 + c0;
                #pragma unroll
                for (int half = 0; half < 2; half++) {
                    const int m = m0 + warp_m*64 + ma*16 + r0 + half*8;
                    *(float2*)(Cout + (size_t)m * EMBED + n0 + coln) =
                        make_float2(acc[ma][na][half*2], acc[ma][na][half*2+1]);
                }
            }
    }
}

// ---------------- FA2-style fp16 attention ----------------
// scores = Qh·Kh ; PV = (Ph+Pl)·Vh.  KV stage = Kh,Vh (2 tiles).
#define AP2    272
#define ATILE  (64*AP2)           // 17408
#define AST2   (2*ATILE)          // 34816 per KV stage
#define ABIAS2 (2*AST2)           // 69632
#define ATTN_SMEM (ABIAS2 + 512)  // 70144

__device__ __forceinline__ void attn_pf(uint32_t sb_stage,
    const __half* Kh, const __half* Vh, int k0, int tid)
{
    #pragma unroll
    for (int i = 0; i < 4; i++) {
        int idx = tid + i*256;
        int r = idx >> 4, c = idx & 15;
        uint32_t so = sb_stage + r*AP2 + c*16;
        size_t go = (size_t)(k0 + r) * DHEAD;
        CP_ASYNC16(so,         (const char*)(Kh + go) + c*16);
        CP_ASYNC16(so + ATILE, (const char*)(Vh + go) + c*16);
    }
}

__global__ void __launch_bounds__(256) attn_mma(const float* __restrict__ mask)
{
    extern __shared__ char smc[];
    const uint32_t sb = smem_to_u32(smc);
    const int tid = threadIdx.x, lane = tid & 31, wid = tid >> 5;
    const int qt = blockIdx.x, h = blockIdx.y, b = blockIdx.z;
    const int q0 = qt * 128;
    const size_t hb = (size_t)(b*NHEAD + h) * SEQ * DHEAD;
    const __half *Qhp = g_Qh + hb;
    const __half *Khp = g_Kh + hb, *Vhp = g_Vh + hb;
    float* bias_sm = (float*)(smc + ABIAS2);

    // stage Qh through the KV double-buffer area (128*AP2 = 34816 B fits stage 0)
    #pragma unroll
    for (int i = 0; i < 8; i++) {
        int idx = tid + i*256;
        int r = idx >> 4, c = idx & 15;
        size_t go = (size_t)(q0 + r) * DHEAD;
        CP_ASYNC16(sb + r*AP2 + c*16, (const char*)(Qhp + go) + c*16);
    }
    CP_COMMIT();
    CP_WAIT0();
    __syncthreads();

    const uint32_t qa_off = (uint32_t)((wid*16 + (lane & 15))*AP2 + (lane >> 4)*16);
    uint32_t Qf[8][4];
    #pragma unroll
    for (int t = 0; t < 8; t++) ldsm_x4(Qf[t], sb + qa_off + t*32);
    __syncthreads();

    attn_pf(sb, Khp, Vhp, 0, tid);
    if (tid < 64) bias_sm[tid] = (1.0f - mask[b*SEQ + tid]) * -1e9f;
    CP_COMMIT();

    float O[16][4];
    #pragma unroll
    for (int j = 0; j < 16; j++)
        #pragma unroll
        for (int r = 0; r < 4; r++) O[j][r] = 0.f;
    float m_a = -1e30f, m_b = -1e30f, l_a = 0.f, l_b = 0.f;
    const float scale = 0.08838834764831845f;
    const int q_a = q0 + wid*16 + (lane >> 2);
    const int klo = 2*(lane & 3);
    const int nkt = 2*qt + 2;

    for (int kt = 0; kt < nkt; kt++) {
        const int stage = kt & 1;
        if (kt + 1 < nkt) {
            attn_pf(sb + (stage^1)*AST2, Khp, Vhp, (kt+1)*64, tid);
            if (tid < 64) bias_sm[(stage^1)*64 + tid] = (1.0f - mask[b*SEQ + (kt+1)*64 + tid]) * -1e9f;
        }
        CP_COMMIT();
        CP_WAIT1();
        __syncthreads();

        const uint32_t ss = sb + stage*AST2;
        float s[8][4];
        #pragma unroll
        for (int j = 0; j < 8; j++)
            #pragma unroll
            for (int r = 0; r < 4; r++) s[j][r] = 0.f;

        // ---- scores: Qh·Kh ----
        #pragma unroll
        for (int t = 0; t < 8; t++) {
            uint32_t Kh4[4][4];
            #pragma unroll
            for (int g = 0; g < 4; g++) {
                uint32_t Baddr = ss + (g*16 + (lane & 7) + ((lane >> 4) << 3))*AP2
                               + t*32 + ((lane >> 3) & 1)*16;
                ldsm_x4(Kh4[g], Baddr);
            }
            #pragma unroll
            for (int j = 0; j < 8; j++) mma_f16(s[j], Qf[t], &Kh4[j>>1][(j&1)*2]);
        }

        // ---- online softmax ----
        const float* bp = bias_sm + stage*64;
        const bool diag = (kt >= 2*qt);
        float tmax_a = -1e30f, tmax_b = -1e30f;
        #pragma unroll
        for (int j = 0; j < 8; j++) {
            int kk = 8*j + klo;
            float b0 = bp[kk], b1 = bp[kk+1];
            s[j][0] = s[j][0]*scale + b0;  s[j][1] = s[j][1]*scale + b1;
            s[j][2] = s[j][2]*scale + b0;  s[j][3] = s[j][3]*scale + b1;
            if (diag) {
                int kg = kt*64 + kk;
                if (kg   > q_a)   s[j][0] = -1e30f;
                if (kg+1 > q_a)   s[j][1] = -1e30f;
                if (kg   > q_a+8) s[j][2] = -1e30f;
                if (kg+1 > q_a+8) s[j][3] = -1e30f;
            }
            tmax_a = fmaxf(tmax_a, fmaxf(s[j][0], s[j][1]));
            tmax_b = fmaxf(tmax_b, fmaxf(s[j][2], s[j][3]));
        }
        tmax_a = fmaxf(tmax_a, __shfl_xor_sync(0xffffffffu, tmax_a, 1));
        tmax_a = fmaxf(tmax_a, __shfl_xor_sync(0xffffffffu, tmax_a, 2));
        tmax_b = fmaxf(tmax_b, __shfl_xor_sync(0xffffffffu, tmax_b, 1));
        tmax_b = fmaxf(tmax_b, __shfl_xor_sync(0xffffffffu, tmax_b, 2));
        float mn_a = fmaxf(m_a, tmax_a), mn_b = fmaxf(m_b, tmax_b);
        float ca = __expf(m_a - mn_a), cb = __expf(m_b - mn_b);
        m_a = mn_a; m_b = mn_b;
        float sum_a = 0.f, sum_b = 0.f;
        #pragma unroll
        for (int j = 0; j < 8; j++) {
            s[j][0] = __expf(s[j][0] - mn_a);  s[j][1] = __expf(s[j][1] - mn_a);
            s[j][2] = __expf(s[j][2] - mn_b);  s[j][3] = __expf(s[j][3] - mn_b);
            sum_a += s[j][0] + s[j][1];
            sum_b += s[j][2] + s[j][3];
        }
        sum_a += __shfl_xor_sync(0xffffffffu, sum_a, 1);
        sum_a += __shfl_xor_sync(0xffffffffu, sum_a, 2);
        sum_b += __shfl_xor_sync(0xffffffffu, sum_b, 1);
        sum_b += __shfl_xor_sync(0xffffffffu, sum_b, 2);
        l_a = l_a*ca + sum_a;
        l_b = l_b*cb + sum_b;
        #pragma unroll
        for (int j = 0; j < 16; j++) {
            O[j][0] *= ca; O[j][1] *= ca; O[j][2] *= cb; O[j][3] *= cb;
        }

        // ---- PV: (Ph+Pl)·Vh ----
        #pragma unroll
        for (int t = 0; t < 4; t++) {
            uint32_t aH[4], aL[4];
            split_pack(s[2*t][0],   s[2*t][1],   aH[0], aL[0]);
            split_pack(s[2*t][2],   s[2*t][3],   aH[1], aL[1]);
            split_pack(s[2*t+1][0], s[2*t+1][1], aH[2], aL[2]);
            split_pack(s[2*t+1][2], s[2*t+1][3], aH[3], aL[3]);
            #pragma unroll
            for (int g = 0; g < 8; g++) {
                uint32_t Baddr = ss + ATILE
                               + (t*16 + (lane & 7) + ((lane >> 3) & 1)*8)*AP2
                               + g*32 + (lane >> 4)*16;
                uint32_t Vh4[4];
                ldsm_x4_t(Vh4, Baddr);
                mma_f16(O[2*g],   aH, Vh4);     mma_f16(O[2*g+1], aH, Vh4+2);
                mma_f16(O[2*g],   aL, Vh4);     mma_f16(O[2*g+1], aL, Vh4+2);
            }
        }
        __syncthreads();
    }

    // ---- epilogue: write fp16 hi ctx ----
    const float ia = 1.0f / l_a, ib = 1.0f / l_b;
    const size_t ra = (size_t)(b*SEQ + q0 + wid*16 + (lane >> 2));
    const size_t oa = ra*EMBED + h*DHEAD + klo;
    const size_t ob = oa + 8*(size_t)EMBED;
    #pragma unroll
    for (int j = 0; j < 16; j++) {
        *(uint32_t*)(g_ch + oa + 8*j) = pack_h(O[j][0]*ia, O[j][1]*ia);
        *(uint32_t*)(g_ch + ob + 8*j) = pack_h(O[j][2]*ib, O[j][3]*ib);
    }
}

// ---------------- launch ----------------
extern "C" void kernel_launch(void* const* d_in, const int* in_sizes, int n_in,
                              void* d_out, int out_size)
{
    (void)in_sizes; (void)n_in; (void)out_size;
    const float* x    = (const float*)d_in[0];
    const float* mask = (const float*)d_in[1];
    const float* Wq   = (const float*)d_in[2];
    const float* Wk   = (const float*)d_in[3];
    const float* Wv   = (const float*)d_in[4];
    const float* Wo   = (const float*)d_in[5];
    float* out        = (float*)d_out;

    cudaFuncSetAttribute(gemm_mma, cudaFuncAttributeMaxDynamicSharedMemorySize, GEMM_SMEM);
    cudaFuncSetAttribute(attn_mma, cudaFuncAttributeMaxDynamicSharedMemorySize, ATTN_SMEM);

    const int n4x = MTOT*EMBED/4;
    const int n4w = EMBED*EMBED/4;

    split_kernel<<<(n4x+255)/256, 256>>>(x, 0, n4x);
    split_kernel<<<(n4w+255)/256, 256>>>(Wq, 1, n4w);
    split_kernel<<<(n4w+255)/256, 256>>>(Wk, 2, n4w);
    split_kernel<<<(n4w+255)/256, 256>>>(Wv, 3, n4w);
    split_kernel<<<(n4w+255)/256, 256>>>(Wo, 4, n4w);

    rope_table<<<(SEQ*64)/256, 256>>>();

    // fused Q/K/V projection: one launch, mode = blockIdx.z
    gemm_mma<<<dim3(EMBED/128, MTOT/128, 3), 128, GEMM_SMEM>>>(nullptr, 0);

    attn_mma<<<dim3(SEQ/128, NHEAD, BATCH), 256, ATTN_SMEM>>>(mask);

    gemm_mma<<<dim3(EMBED/128, MTOT/128, 1), 128, GEMM_SMEM>>>(out, 3);
}

// round 15
// speedup vs baseline: 8.5443x; 1.0786x over previous
#include <cuda_runtime.h>
#include <cuda_fp16.h>
#include <math.h>
#include <stdint.h>

#define EMBED 2048
#define SEQ   2048
#define NHEAD 16
#define DHEAD 128
#define BATCH 2
#define MTOT  (BATCH*SEQ)   // 4096

// ---------------- static device scratch (fp16) ----------------
__device__ __half g_xh[MTOT*EMBED];
__device__ __half g_Wh[4*EMBED*EMBED];
__device__ __half g_ch[MTOT*EMBED];
__device__ __half g_Qh[BATCH*NHEAD*SEQ*DHEAD];
__device__ __half g_Kh[BATCH*NHEAD*SEQ*DHEAD];
__device__ __half g_Vh[BATCH*NHEAD*SEQ*DHEAD];
__device__ float g_rsin[SEQ*64];
__device__ float g_rcos[SEQ*64];

// ---------------- baseline-PTX helpers ----------------
__device__ __forceinline__ uint32_t smem_to_u32(const void* p) {
    uint32_t a;
    asm("{ .reg .u64 t; cvta.to.shared.u64 t, %1; cvt.u32.u64 %0, t; }" : "=r"(a) : "l"(p));
    return a;
}
#define CP_ASYNC16(saddr, gptr) \
    asm volatile("cp.async.cg.shared.global [%0], [%1], 16;" :: "r"(saddr), "l"(gptr) : "memory")
#define CP_COMMIT() asm volatile("cp.async.commit_group;" ::: "memory")
#define CP_WAIT1()  asm volatile("cp.async.wait_group 1;" ::: "memory")
#define CP_WAIT0()  asm volatile("cp.async.wait_group 0;" ::: "memory")

__device__ __forceinline__ void ldsm_x4(uint32_t* r, uint32_t addr) {
    asm volatile("ldmatrix.sync.aligned.m8n8.x4.shared.b16 {%0,%1,%2,%3}, [%4];"
                 : "=r"(r[0]), "=r"(r[1]), "=r"(r[2]), "=r"(r[3]) : "r"(addr));
}
__device__ __forceinline__ void ldsm_x4_t(uint32_t* r, uint32_t addr) {
    asm volatile("ldmatrix.sync.aligned.m8n8.x4.trans.shared.b16 {%0,%1,%2,%3}, [%4];"
                 : "=r"(r[0]), "=r"(r[1]), "=r"(r[2]), "=r"(r[3]) : "r"(addr));
}
__device__ __forceinline__ void mma_f16(float* c, const uint32_t* a, const uint32_t* b) {
    asm volatile("mma.sync.aligned.m16n8k16.row.col.f32.f16.f16.f32 "
                 "{%0,%1,%2,%3}, {%4,%5,%6,%7}, {%8,%9}, {%0,%1,%2,%3};"
                 : "+f"(c[0]), "+f"(c[1]), "+f"(c[2]), "+f"(c[3])
                 : "r"(a[0]), "r"(a[1]), "r"(a[2]), "r"(a[3]), "r"(b[0]), "r"(b[1]));
}
__device__ __forceinline__ uint32_t pack_h(float x, float y) {
    return ((uint32_t)__half_as_ushort(__float2half_rn(y)) << 16)
         | __half_as_ushort(__float2half_rn(x));
}

// ---------------- splits: f32 -> fp16 ----------------
__global__ void __launch_bounds__(256) split_x(const float* __restrict__ src, int n4)
{
    int idx = blockIdx.x * 256 + threadIdx.x;
    if (idx >= n4) return;
    float4 v = ((const float4*)src)[idx];
    *(uint2*)((uint32_t*)g_xh + idx*2) = make_uint2(pack_h(v.x, v.y), pack_h(v.z, v.w));
}

// all four weight matrices in one launch; blockIdx.y selects the matrix
__global__ void __launch_bounds__(256) split_w(const float* __restrict__ w0,
                                               const float* __restrict__ w1,
                                               const float* __restrict__ w2,
                                               const float* __restrict__ w3, int n4)
{
    int idx = blockIdx.x * 256 + threadIdx.x;
    if (idx >= n4) return;
    const float* srcs[4] = {w0, w1, w2, w3};
    const float* src = srcs[blockIdx.y];
    float4 v = ((const float4*)src)[idx];
    __half* hi = g_Wh + (size_t)blockIdx.y * EMBED * EMBED;
    *(uint2*)((uint32_t*)hi + idx*2) = make_uint2(pack_h(v.x, v.y), pack_h(v.z, v.w));
}

// ---------------- RoPE table ----------------
__global__ void __launch_bounds__(256) rope_table()
{
    int idx = blockIdx.x * 256 + threadIdx.x;
    int i = idx & 63, s = idx >> 6;
    float freq = (float)pow(10000.0, -(double)i / 64.0);
    float ang  = (float)s * freq;
    double sn, cs;
    sincos((double)ang, &sn, &cs);
    g_rsin[idx] = (float)sn;
    g_rcos[idx] = (float)cs;
}

// ---------------- mma.sync fp16 1-product GEMM: C = Ah * Wh^T ----------------
// mode = mode_base + blockIdx.z.
// mode 0: x->g_Qh (RoPE)  mode 1: x->g_Kh (RoPE)  mode 2: x->g_Vh  mode 3: ctx->Cout
#define GT_PITCH 80
#define GT_TILE  (128*GT_PITCH)      // 10240
#define GT_STAGE (2*GT_TILE)         // 20480
#define CS_PITCH 134
#define GEMM_SMEM (128*CS_PITCH*4)   // 68608 >= 2*GT_STAGE (40960)

__global__ void __launch_bounds__(128) gemm_mma(float* __restrict__ Cout, int mode_base)
{
    extern __shared__ char smc[];
    const uint32_t sbase = smem_to_u32(smc);
    const int tid  = threadIdx.x;
    const int lane = tid & 31;
    const int wid  = tid >> 5;
    const int warp_m = wid >> 1;
    const int warp_n = wid & 1;
    const int n0 = blockIdx.x * 128;
    const int m0 = blockIdx.y * 128;
    const int mode = mode_base + blockIdx.z;

    const __half* srcs[2];
    srcs[0] = ((mode == 3) ? g_ch : g_xh);
    srcs[1] = g_Wh + (size_t)mode * EMBED * EMBED;
    const int base_row[2] = {m0, n0};

    const int seg = tid & 3;
    const int rb  = tid >> 2;

    const uint32_t a_off = (uint32_t)((warp_m*64 + (lane & 15)) * GT_PITCH + (lane >> 4) * 16);
    const uint32_t b_off = (uint32_t)(((lane & 7) + (lane >> 4) * 8 + warp_n*64) * GT_PITCH
                                      + ((lane >> 3) & 1) * 16);

    float acc[4][8][4];
    #pragma unroll
    for (int i = 0; i < 4; i++)
        #pragma unroll
        for (int j = 0; j < 8; j++)
            #pragma unroll
            for (int r = 0; r < 4; r++) acc[i][j][r] = 0.f;

    #pragma unroll
    for (int t = 0; t < 2; t++)
        #pragma unroll
        for (int i = 0; i < 4; i++) {
            int row = rb + i*32;
            const __half* g = srcs[t] + (size_t)(base_row[t] + row) * EMBED + seg*8;
            CP_ASYNC16(sbase + t*GT_TILE + row*GT_PITCH + seg*16, g);
        }
    CP_COMMIT();

    for (int s = 0; s < EMBED/32; s++) {
        if (s < EMBED/32 - 1) {
            const uint32_t sb = sbase + ((s+1) & 1) * GT_STAGE;
            const int k0 = (s+1) * 32;
            #pragma unroll
            for (int t = 0; t < 2; t++)
                #pragma unroll
                for (int i = 0; i < 4; i++) {
                    int row = rb + i*32;
                    const __half* g = srcs[t] + (size_t)(base_row[t] + row) * EMBED + k0 + seg*8;
                    CP_ASYNC16(sb + t*GT_TILE + row*GT_PITCH + seg*16, g);
                }
        }
        CP_COMMIT();
        CP_WAIT1();
        __syncthreads();

        const uint32_t sb = sbase + (s & 1) * GT_STAGE;
        #pragma unroll
        for (int kk = 0; kk < 2; kk++) {
            const uint32_t ko = kk * 32;
            uint32_t Af[4][4], Bf[4][4];
            #pragma unroll
            for (int ma = 0; ma < 4; ma++)
                ldsm_x4(Af[ma], sb + 0*GT_TILE + a_off + ko + ma*16*GT_PITCH);
            #pragma unroll
            for (int g = 0; g < 4; g++)
                ldsm_x4(Bf[g], sb + 1*GT_TILE + b_off + ko + g*16*GT_PITCH);
            #pragma unroll
            for (int ma = 0; ma < 4; ma++)
                #pragma unroll
                for (int na = 0; na < 8; na++)
                    mma_f16(acc[ma][na], Af[ma], &Bf[na >> 1][(na & 1) * 2]);
        }
        __syncthreads();
    }

    const int r0 = lane >> 2;
    const int c0 = (lane & 3) * 2;

    if (mode <= 1) {
        // ---- fused RoPE epilogue: acc -> smem fp32 -> rotate -> fp16 hi ----
        float* Cs = (float*)smc;
        #pragma unroll
        for (int ma = 0; ma < 4; ma++)
            #pragma unroll
            for (int na = 0; na < 8; na++)
                #pragma unroll
                for (int half = 0; half < 2; half++) {
                    int rl = warp_m*64 + ma*16 + r0 + half*8;
                    int cl = warp_n*64 + na*8 + c0;
                    Cs[rl*CS_PITCH + cl]     = acc[ma][na][half*2];
                    Cs[rl*CS_PITCH + cl + 1] = acc[ma][na][half*2+1];
                }
        __syncthreads();

        __half* Hdst = (mode == 0) ? g_Qh : g_Kh;
        #pragma unroll
        for (int pass = 0; pass < 4; pass++) {
            const int r = pass*32 + (tid >> 2);
            const int m = m0 + r;
            const int bb = m >> 11, sq = m & (SEQ - 1);
            const size_t dst = ((size_t)((bb*NHEAD + blockIdx.x)*SEQ + sq))*DHEAD;
            const int g0 = (tid & 3) * 16;
            #pragma unroll
            for (int c = 0; c < 2; c++) {
                const int i0 = g0 + c*8;
                uint32_t hA[4], hB[4];
                #pragma unroll
                for (int j = 0; j < 4; j++) {
                    int i = i0 + 2*j;
                    float a0 = Cs[r*CS_PITCH + i],      a1 = Cs[r*CS_PITCH + i + 1];
                    float b0 = Cs[r*CS_PITCH + i + 64], b1 = Cs[r*CS_PITCH + i + 65];
                    float sn0 = g_rsin[sq*64 + i], sn1 = g_rsin[sq*64 + i + 1];
                    float cc0 = g_rcos[sq*64 + i], cc1 = g_rcos[sq*64 + i + 1];
                    hA[j] = pack_h(a0*cc0 - b0*sn0, a1*cc1 - b1*sn1);
                    hB[j] = pack_h(b0*cc0 + a0*sn0, b1*cc1 + a1*sn1);
                }
                *(uint4*)(Hdst + dst + i0)      = make_uint4(hA[0], hA[1], hA[2], hA[3]);
                *(uint4*)(Hdst + dst + i0 + 64) = make_uint4(hB[0], hB[1], hB[2], hB[3]);
            }
        }
    } else if (mode == 2) {
        #pragma unroll
        for (int ma = 0; ma < 4; ma++)
            #pragma unroll
            for (int na = 0; na < 8; na++) {
                const int coln = warp_n*64 + na*8 + c0;
                #pragma unroll
                for (int half = 0; half < 2; half++) {
                    const int m = m0 + warp_m*64 + ma*16 + r0 + half*8;
                    const int bb = m >> 11, ss = m & (SEQ - 1);
                    size_t off = ((size_t)((bb*NHEAD + blockIdx.x)*SEQ + ss))*DHEAD + coln;
                    *(uint32_t*)(g_Vh + off) = pack_h(acc[ma][na][half*2], acc[ma][na][half*2+1]);
                }
            }
    } else {
        #pragma unroll
        for (int ma = 0; ma < 4; ma++)
            #pragma unroll
            for (int na = 0; na < 8; na++) {
                const int coln = warp_n*64 + na*8 + c0;
                #pragma unroll
                for (int half = 0; half < 2; half++) {
                    const int m = m0 + warp_m*64 + ma*16 + r0 + half*8;
                    *(float2*)(Cout + (size_t)m * EMBED + n0 + coln) =
                        make_float2(acc[ma][na][half*2], acc[ma][na][half*2+1]);
                }
            }
    }
}

// ---------------- FA2-style fp16 attention ----------------
// scores = Qh·Kh ; PV = Ph·Vh (single product).  KV stage = Kh,Vh (2 tiles).
// Heavy q-tiles scheduled first (qt reversed) to shrink causal makespan tail.
#define AP2    272
#define ATILE  (64*AP2)           // 17408
#define AST2   (2*ATILE)          // 34816 per KV stage
#define ABIAS2 (2*AST2)           // 69632
#define ATTN_SMEM (ABIAS2 + 512)  // 70144

__device__ __forceinline__ void attn_pf(uint32_t sb_stage,
    const __half* Kh, const __half* Vh, int k0, int tid)
{
    #pragma unroll
    for (int i = 0; i < 4; i++) {
        int idx = tid + i*256;
        int r = idx >> 4, c = idx & 15;
        uint32_t so = sb_stage + r*AP2 + c*16;
        size_t go = (size_t)(k0 + r) * DHEAD;
        CP_ASYNC16(so,         (const char*)(Kh + go) + c*16);
        CP_ASYNC16(so + ATILE, (const char*)(Vh + go) + c*16);
    }
}

__global__ void __launch_bounds__(256) attn_mma(const float* __restrict__ mask)
{
    extern __shared__ char smc[];
    const uint32_t sb = smem_to_u32(smc);
    const int tid = threadIdx.x, lane = tid & 31, wid = tid >> 5;
    const int qt = gridDim.x - 1 - blockIdx.x;     // heavy tiles first
    const int h = blockIdx.y, b = blockIdx.z;
    const int q0 = qt * 128;
    const size_t hb = (size_t)(b*NHEAD + h) * SEQ * DHEAD;
    const __half *Qhp = g_Qh + hb;
    const __half *Khp = g_Kh + hb, *Vhp = g_Vh + hb;
    float* bias_sm = (float*)(smc + ABIAS2);

    // stage Qh through the KV double-buffer area (128*AP2 = 34816 B = stage 0)
    #pragma unroll
    for (int i = 0; i < 8; i++) {
        int idx = tid + i*256;
        int r = idx >> 4, c = idx & 15;
        size_t go = (size_t)(q0 + r) * DHEAD;
        CP_ASYNC16(sb + r*AP2 + c*16, (const char*)(Qhp + go) + c*16);
    }
    CP_COMMIT();
    CP_WAIT0();
    __syncthreads();

    const uint32_t qa_off = (uint32_t)((wid*16 + (lane & 15))*AP2 + (lane >> 4)*16);
    uint32_t Qf[8][4];
    #pragma unroll
    for (int t = 0; t < 8; t++) ldsm_x4(Qf[t], sb + qa_off + t*32);
    __syncthreads();

    attn_pf(sb, Khp, Vhp, 0, tid);
    if (tid < 64) bias_sm[tid] = (1.0f - mask[b*SEQ + tid]) * -1e9f;
    CP_COMMIT();

    float O[16][4];
    #pragma unroll
    for (int j = 0; j < 16; j++)
        #pragma unroll
        for (int r = 0; r < 4; r++) O[j][r] = 0.f;
    float m_a = -1e30f, m_b = -1e30f, l_a = 0.f, l_b = 0.f;
    const float scale = 0.08838834764831845f;
    const int q_a = q0 + wid*16 + (lane >> 2);
    const int klo = 2*(lane & 3);
    const int nkt = 2*qt + 2;

    for (int kt = 0; kt < nkt; kt++) {
        const int stage = kt & 1;
        if (kt + 1 < nkt) {
            attn_pf(sb + (stage^1)*AST2, Khp, Vhp, (kt+1)*64, tid);
            if (tid < 64) bias_sm[(stage^1)*64 + tid] = (1.0f - mask[b*SEQ + (kt+1)*64 + tid]) * -1e9f;
        }
        CP_COMMIT();
        CP_WAIT1();
        __syncthreads();

        const uint32_t ss = sb + stage*AST2;
        float s[8][4];
        #pragma unroll
        for (int j = 0; j < 8; j++)
            #pragma unroll
            for (int r = 0; r < 4; r++) s[j][r] = 0.f;

        // ---- scores: Qh·Kh ----
        #pragma unroll
        for (int t = 0; t < 8; t++) {
            uint32_t Kh4[4][4];
            #pragma unroll
            for (int g = 0; g < 4; g++) {
                uint32_t Baddr = ss + (g*16 + (lane & 7) + ((lane >> 4) << 3))*AP2
                               + t*32 + ((lane >> 3) & 1)*16;
                ldsm_x4(Kh4[g], Baddr);
            }
            #pragma unroll
            for (int j = 0; j < 8; j++) mma_f16(s[j], Qf[t], &Kh4[j>>1][(j&1)*2]);
        }

        // ---- online softmax ----
        const float* bp = bias_sm + stage*64;
        const bool diag = (kt >= 2*qt);
        float tmax_a = -1e30f, tmax_b = -1e30f;
        #pragma unroll
        for (int j = 0; j < 8; j++) {
            int kk = 8*j + klo;
            float b0 = bp[kk], b1 = bp[kk+1];
            s[j][0] = s[j][0]*scale + b0;  s[j][1] = s[j][1]*scale + b1;
            s[j][2] = s[j][2]*scale + b0;  s[j][3] = s[j][3]*scale + b1;
            if (diag) {
                int kg = kt*64 + kk;
                if (kg   > q_a)   s[j][0] = -1e30f;
                if (kg+1 > q_a)   s[j][1] = -1e30f;
                if (kg   > q_a+8) s[j][2] = -1e30f;
                if (kg+1 > q_a+8) s[j][3] = -1e30f;
            }
            tmax_a = fmaxf(tmax_a, fmaxf(s[j][0], s[j][1]));
            tmax_b = fmaxf(tmax_b, fmaxf(s[j][2], s[j][3]));
        }
        tmax_a = fmaxf(tmax_a, __shfl_xor_sync(0xffffffffu, tmax_a, 1));
        tmax_a = fmaxf(tmax_a, __shfl_xor_sync(0xffffffffu, tmax_a, 2));
        tmax_b = fmaxf(tmax_b, __shfl_xor_sync(0xffffffffu, tmax_b, 1));
        tmax_b = fmaxf(tmax_b, __shfl_xor_sync(0xffffffffu, tmax_b, 2));
        float mn_a = fmaxf(m_a, tmax_a), mn_b = fmaxf(m_b, tmax_b);
        float ca = __expf(m_a - mn_a), cb = __expf(m_b - mn_b);
        m_a = mn_a; m_b = mn_b;
        float sum_a = 0.f, sum_b = 0.f;
        #pragma unroll
        for (int j = 0; j < 8; j++) {
            s[j][0] = __expf(s[j][0] - mn_a);  s[j][1] = __expf(s[j][1] - mn_a);
            s[j][2] = __expf(s[j][2] - mn_b);  s[j][3] = __expf(s[j][3] - mn_b);
            sum_a += s[j][0] + s[j][1];
            sum_b += s[j][2] + s[j][3];
        }
        sum_a += __shfl_xor_sync(0xffffffffu, sum_a, 1);
        sum_a += __shfl_xor_sync(0xffffffffu, sum_a, 2);
        sum_b += __shfl_xor_sync(0xffffffffu, sum_b, 1);
        sum_b += __shfl_xor_sync(0xffffffffu, sum_b, 2);
        l_a = l_a*ca + sum_a;
        l_b = l_b*cb + sum_b;
        #pragma unroll
        for (int j = 0; j < 16; j++) {
            O[j][0] *= ca; O[j][1] *= ca; O[j][2] *= cb; O[j][3] *= cb;
        }

        // ---- PV: Ph·Vh (single product) ----
        #pragma unroll
        for (int t = 0; t < 4; t++) {
            uint32_t aH[4];
            aH[0] = pack_h(s[2*t][0],   s[2*t][1]);
            aH[1] = pack_h(s[2*t][2],   s[2*t][3]);
            aH[2] = pack_h(s[2*t+1][0], s[2*t+1][1]);
            aH[3] = pack_h(s[2*t+1][2], s[2*t+1][3]);
            #pragma unroll
            for (int g = 0; g < 8; g++) {
                uint32_t Baddr = ss + ATILE
                               + (t*16 + (lane & 7) + ((lane >> 3) & 1)*8)*AP2
                               + g*32 + (lane >> 4)*16;
                uint32_t Vh4[4];
                ldsm_x4_t(Vh4, Baddr);
                mma_f16(O[2*g],   aH, Vh4);
                mma_f16(O[2*g+1], aH, Vh4+2);
            }
        }
        __syncthreads();
    }

    // ---- epilogue: write fp16 hi ctx ----
    const float ia = 1.0f / l_a, ib = 1.0f / l_b;
    const size_t ra = (size_t)(b*SEQ + q0 + wid*16 + (lane >> 2));
    const size_t oa = ra*EMBED + h*DHEAD + klo;
    const size_t ob = oa + 8*(size_t)EMBED;
    #pragma unroll
    for (int j = 0; j < 16; j++) {
        *(uint32_t*)(g_ch + oa + 8*j) = pack_h(O[j][0]*ia, O[j][1]*ia);
        *(uint32_t*)(g_ch + ob + 8*j) = pack_h(O[j][2]*ib, O[j][3]*ib);
    }
}

// ---------------- launch ----------------
extern "C" void kernel_launch(void* const* d_in, const int* in_sizes, int n_in,
                              void* d_out, int out_size)
{
    (void)in_sizes; (void)n_in; (void)out_size;
    const float* x    = (const float*)d_in[0];
    const float* mask = (const float*)d_in[1];
    const float* Wq   = (const float*)d_in[2];
    const float* Wk   = (const float*)d_in[3];
    const float* Wv   = (const float*)d_in[4];
    const float* Wo   = (const float*)d_in[5];
    float* out        = (float*)d_out;

    cudaFuncSetAttribute(gemm_mma, cudaFuncAttributeMaxDynamicSharedMemorySize, GEMM_SMEM);
    cudaFuncSetAttribute(attn_mma, cudaFuncAttributeMaxDynamicSharedMemorySize, ATTN_SMEM);

    const int n4x = MTOT*EMBED/4;
    const int n4w = EMBED*EMBED/4;

    split_x<<<(n4x+255)/256, 256>>>(x, n4x);
    split_w<<<dim3((n4w+255)/256, 4), 256>>>(Wq, Wk, Wv, Wo, n4w);
    rope_table<<<(SEQ*64)/256, 256>>>();

    // fused Q/K/V projection: one launch, mode = blockIdx.z
    gemm_mma<<<dim3(EMBED/128, MTOT/128, 3), 128, GEMM_SMEM>>>(nullptr, 0);

    attn_mma<<<dim3(SEQ/128, NHEAD, BATCH), 256, ATTN_SMEM>>>(mask);

    gemm_mma<<<dim3(EMBED/128, MTOT/128, 1), 128, GEMM_SMEM>>>(out, 3);
}